// round 4
// baseline (speedup 1.0000x reference)
#include <cuda_runtime.h>
#include <math.h>

typedef unsigned long long ull;

#define Bz 64
#define Hh 1024
#define NNv 65536
#define Mv 64
#define Rv 4
#define SIMBLK (NNv/64)   /* 1024 sim blocks */
#define CSPBLK 64         /* write-head csp blocks per b (1024 n each) */
#define ECHUNK 256        /* fused read chunks */
#define EK (NNv/ECHUNK)   /* 256 n per chunk */
#define ESUB (EK/64)      /* 4 sub-tiles of 64 n */

// ---------------- scratch (device globals: no allocation allowed) ----------
__device__ float g_E[(size_t)Bz*NNv];            // exp(beta*sim) [B,N]
__device__ float g_wpow_w[(size_t)Bz*NNv];       // write-head w_pow
__device__ float g_m1[(size_t)NNv*Mv];           // updated memory
__device__ float g_kn[Bz*Mv];
__device__ float g_ev[Bz*Mv];
__device__ float g_av[Bz*Mv];
__device__ float g_beta[Bz];
__device__ float g_gate[Bz];
__device__ float g_gamma[Bz];
__device__ float g_shift[Bz*3];
__device__ float g_psum[(size_t)Bz*SIMBLK];
__device__ float g_sumexp[Bz];
__device__ float g_tpart[Bz*CSPBLK];             // write-head pow partials
__device__ float g_tpartR[Rv*ECHUNK];            // read-head pow partials
__device__ float g_totals[1+Rv];                 // [0]=write, [1..4]=read totals
__device__ float g_epart[(size_t)Rv*ECHUNK*Bz*Mv]; // fused split-K partials

__device__ __forceinline__ float clip01(float x){ return fminf(fmaxf(x, 0.f), 1.f); }
// fast x^g for x > 0 (x==0 -> -inf -> 0, also fine)
__device__ __forceinline__ float fpow(float x, float g){ return __expf(g * __logf(x)); }

__device__ __forceinline__ ull ffma2(ull a, ull b, ull c){
    ull d;
    asm("fma.rn.f32x2 %0, %1, %2, %3;" : "=l"(d) : "l"(a), "l"(b), "l"(c));
    return d;
}
__device__ __forceinline__ ull dup2(float x){
    ull d;
    asm("mov.b64 %0, {%1, %1};" : "=l"(d) : "f"(x));
    return d;
}
__device__ __forceinline__ void unpack2(ull v, float& lo, float& hi){
    asm("mov.b64 {%0, %1}, %2;" : "=f"(lo), "=f"(hi) : "l"(v));
}

// ---------------- kernel 1: head projections (once per step) ---------------
__global__ void heads_kernel(const float* __restrict__ h,
    const float* __restrict__ key_w,   const float* __restrict__ key_b,
    const float* __restrict__ beta_w,  const float* __restrict__ beta_b,
    const float* __restrict__ gate_w,  const float* __restrict__ gate_b,
    const float* __restrict__ shift_w, const float* __restrict__ shift_b,
    const float* __restrict__ gamma_w, const float* __restrict__ gamma_b,
    const float* __restrict__ erase_w, const float* __restrict__ erase_b,
    const float* __restrict__ add_w,   const float* __restrict__ add_b)
{
    __shared__ float hs[Hh];
    __shared__ float ksh[Mv];
    __shared__ float sdot[6];
    __shared__ float sinv;
    const int b = blockIdx.x, t = threadIdx.x;
    for (int i = t; i < Hh; i += 256) hs[i] = h[(size_t)b*Hh + i];
    __syncthreads();

    if (t < 64) {
        float a0=0,a1=0,a2=0,a3=0;
        for (int j = 0; j < Hh; j += 4) {
            a0 = fmaf(hs[j  ], key_w[(j  )*Mv + t], a0);
            a1 = fmaf(hs[j+1], key_w[(j+1)*Mv + t], a1);
            a2 = fmaf(hs[j+2], key_w[(j+2)*Mv + t], a2);
            a3 = fmaf(hs[j+3], key_w[(j+3)*Mv + t], a3);
        }
        ksh[t] = clip01(a0+a1+a2+a3 + key_b[t]);
    } else if (t < 128) {
        const int m = t - 64;
        float a0=0,a1=0,a2=0,a3=0;
        for (int j = 0; j < Hh; j += 4) {
            a0 = fmaf(hs[j  ], erase_w[(j  )*Mv + m], a0);
            a1 = fmaf(hs[j+1], erase_w[(j+1)*Mv + m], a1);
            a2 = fmaf(hs[j+2], erase_w[(j+2)*Mv + m], a2);
            a3 = fmaf(hs[j+3], erase_w[(j+3)*Mv + m], a3);
        }
        g_ev[b*Mv + m] = clip01(a0+a1+a2+a3 + erase_b[m]);
    } else if (t < 192) {
        const int m = t - 128;
        float a0=0,a1=0,a2=0,a3=0;
        for (int j = 0; j < Hh; j += 4) {
            a0 = fmaf(hs[j  ], add_w[(j  )*Mv + m], a0);
            a1 = fmaf(hs[j+1], add_w[(j+1)*Mv + m], a1);
            a2 = fmaf(hs[j+2], add_w[(j+2)*Mv + m], a2);
            a3 = fmaf(hs[j+3], add_w[(j+3)*Mv + m], a3);
        }
        g_av[b*Mv + m] = clip01(a0+a1+a2+a3 + add_b[m]);
    } else if (t < 198) {
        const int d = t - 192;
        const float* w; int str, col;
        if      (d == 0) { w = beta_w;  str = 1; col = 0; }
        else if (d == 1) { w = gate_w;  str = 1; col = 0; }
        else if (d == 2) { w = gamma_w; str = 1; col = 0; }
        else             { w = shift_w; str = 3; col = d - 3; }
        float a0=0,a1=0;
        for (int j = 0; j < Hh; j += 2) {
            a0 = fmaf(hs[j  ], w[(j  )*str + col], a0);
            a1 = fmaf(hs[j+1], w[(j+1)*str + col], a1);
        }
        sdot[d] = a0 + a1;
    }
    __syncthreads();

    if (t < 32) {
        float v = ksh[t]*ksh[t] + ksh[t+32]*ksh[t+32];
        #pragma unroll
        for (int off = 16; off; off >>= 1) v += __shfl_xor_sync(0xffffffffu, v, off);
        if (t == 0) sinv = 1.f / (sqrtf(v) + 1e-8f);
    }
    __syncthreads();
    if (t < 64) g_kn[b*Mv + t] = ksh[t] * sinv;
    if (t == 0) {
        g_beta[b]  = fmaxf(sdot[0] + beta_b[0], 0.f);
        g_gate[b]  = clip01(sdot[1] + gate_b[0]);
        g_gamma[b] = 1.f + fmaxf(sdot[2] + gamma_b[0], 0.f);
        float x0 = sdot[3] + shift_b[0];
        float x1 = sdot[4] + shift_b[1];
        float x2 = sdot[5] + shift_b[2];
        float mx = fmaxf(x0, fmaxf(x1, x2));
        float e0 = expf(x0-mx), e1 = expf(x1-mx), e2 = expf(x2-mx);
        float is = 1.f / (e0+e1+e2);
        g_shift[b*3+0] = e0*is; g_shift[b*3+1] = e1*is; g_shift[b*3+2] = e2*is;
    }
}

// ------- kernel 2: E[b,n] = exp(beta[b] * (kn[b]·m[n]) / (||m[n]||+eps)) ---
__global__ void sim_kernel(const float* __restrict__ mem,
                           const int* __restrict__ bank, int use_m1)
{
    const float* __restrict__ src = use_m1 ? g_m1
                                           : (mem + (size_t)bank[0]*NNv*Mv);
    __shared__ float knT[64*68];   // [k][b], padded; b contiguous -> natural pairs
    __shared__ float mt [64*68];   // [k][n], padded
    __shared__ float invn[64];
    __shared__ float sbeta[64];
    const int t = threadIdx.x;
    const int n0 = blockIdx.x * 64;

    for (int i = t; i < 64*64; i += 256) {
        int bb = i >> 6, mm = i & 63;
        knT[mm*68 + bb] = g_kn[i];
    }
    for (int i = t; i < 64*64; i += 256) {
        int rr = i >> 6, cc = i & 63;
        mt[cc*68 + rr] = src[(size_t)(n0 + rr)*Mv + cc];
    }
    if (t < 64) sbeta[t] = g_beta[t];
    __syncthreads();
    if (t < 64) {
        float s = 0.f;
        #pragma unroll 16
        for (int k = 0; k < 64; k++) { float v = mt[k*68 + t]; s = fmaf(v, v, s); }
        invn[t] = 1.f / (sqrtf(s) + 1e-8f);
    }
    __syncthreads();

    const int by = t >> 5, nx = t & 31;   // 8 b's (4 pairs), 2 n's per thread
    ull acc[4][2];
    #pragma unroll
    for (int p = 0; p < 4; p++) { acc[p][0] = 0ull; acc[p][1] = 0ull; }

    #pragma unroll 8
    for (int k = 0; k < 64; k++) {
        const ulonglong2 A0 = *(const ulonglong2*)&knT[k*68 + 8*by];
        const ulonglong2 A1 = *(const ulonglong2*)&knT[k*68 + 8*by + 4];
        const float2 Bv = *(const float2*)&mt [k*68 + 2*nx];
        const ull d0 = dup2(Bv.x), d1 = dup2(Bv.y);
        acc[0][0] = ffma2(A0.x, d0, acc[0][0]); acc[0][1] = ffma2(A0.x, d1, acc[0][1]);
        acc[1][0] = ffma2(A0.y, d0, acc[1][0]); acc[1][1] = ffma2(A0.y, d1, acc[1][1]);
        acc[2][0] = ffma2(A1.x, d0, acc[2][0]); acc[2][1] = ffma2(A1.x, d1, acc[2][1]);
        acc[3][0] = ffma2(A1.y, d0, acc[3][0]); acc[3][1] = ffma2(A1.y, d1, acc[3][1]);
    }

    const float2 iv = *(const float2*)&invn[2*nx];
    float ps[8];
    #pragma unroll
    for (int p = 0; p < 4; p++) {
        float c0l, c0h, c1l, c1h;
        unpack2(acc[p][0], c0l, c0h);
        unpack2(acc[p][1], c1l, c1h);
        const int bbl = 8*by + 2*p, bbh = bbl + 1;
        const float btl = sbeta[bbl], bth = sbeta[bbh];
        float e0l = __expf(btl * c0l * iv.x);
        float e1l = __expf(btl * c1l * iv.y);
        float e0h = __expf(bth * c0h * iv.x);
        float e1h = __expf(bth * c1h * iv.y);
        *(float2*)&g_E[(size_t)bbl*NNv + n0 + 2*nx] = make_float2(e0l, e1l);
        *(float2*)&g_E[(size_t)bbh*NNv + n0 + 2*nx] = make_float2(e0h, e1h);
        ps[2*p]   = e0l + e1l;
        ps[2*p+1] = e0h + e1h;
    }
    #pragma unroll
    for (int bi = 0; bi < 8; bi++)
        #pragma unroll
        for (int off = 16; off; off >>= 1)
            ps[bi] += __shfl_xor_sync(0xffffffffu, ps[bi], off);
    if (nx == 0) {
        #pragma unroll
        for (int bi = 0; bi < 8; bi++)
            g_psum[(size_t)(8*by + bi)*SIMBLK + blockIdx.x] = ps[bi];
    }
}

// ---------------- deterministic reductions ---------------------------------
__global__ void reduce_sumexp_kernel()
{
    const int b = blockIdx.x, t = threadIdx.x;
    float s = 0.f;
    for (int i = t; i < SIMBLK; i += 256) s += g_psum[(size_t)b*SIMBLK + i];
    __shared__ float red[256];
    red[t] = s; __syncthreads();
    for (int off = 128; off; off >>= 1) { if (t < off) red[t] += red[t+off]; __syncthreads(); }
    if (t == 0) g_sumexp[b] = red[0];
}

__global__ void reduce_totalW_kernel()
{
    const int t = threadIdx.x;
    float s = 0.f;
    for (int i = t; i < Bz*CSPBLK; i += 256) s += g_tpart[i];
    __shared__ float red[256];
    red[t] = s; __syncthreads();
    for (int off = 128; off; off >>= 1) { if (t < off) red[t] += red[t+off]; __syncthreads(); }
    if (t == 0) g_totals[0] = red[0];
}

__global__ void reduce_totalR_kernel()
{
    const int r = blockIdx.x, t = threadIdx.x;  // ECHUNK==256 threads
    __shared__ float red[256];
    red[t] = g_tpartR[r*ECHUNK + t]; __syncthreads();
    for (int off = 128; off; off >>= 1) { if (t < off) red[t] += red[t+off]; __syncthreads(); }
    if (t == 0) g_totals[1 + r] = red[0];
}

// ----- kernel 3: WRITE head: gate + 3-tap shift + fast pow + partial sum ---
__global__ void csp_write_kernel(const float* __restrict__ ww)
{
    const int b  = blockIdx.y;
    const int c0 = blockIdx.x * 1024;
    const float* __restrict__ wp = ww + (size_t)b*NNv;
    float* __restrict__ wo = g_wpow_w + (size_t)b*NNv;
    const float* __restrict__ Eb = g_E + (size_t)b*NNv;

    __shared__ float wg[1026];
    __shared__ float red[256];
    const float gg   = g_gate[b];
    const float invS = 1.f / g_sumexp[b];
    const float s0 = g_shift[b*3+0], s1 = g_shift[b*3+1], s2 = g_shift[b*3+2];
    const float gm = g_gamma[b];
    const int t = threadIdx.x;

    for (int i = t; i < 1026; i += 256) {
        const int n = c0 + i - 1;
        float v = 0.f;
        if (n >= 0 && n < NNv)
            v = gg * Eb[n] * invS + (1.f - gg) * wp[n];
        wg[i] = v;
    }
    __syncthreads();

    float ls = 0.f;
    #pragma unroll
    for (int j = 0; j < 4; j++) {
        const int i = t + j*256;
        const float wt = fmaf(s0, wg[i], fmaf(s1, wg[i+1], s2*wg[i+2]));
        const float pw = fpow(wt, gm);
        wo[c0 + i] = pw;
        ls += pw;
    }
    red[t] = ls; __syncthreads();
    for (int off = 128; off; off >>= 1) { if (t < off) red[t] += red[t+off]; __syncthreads(); }
    if (t == 0) g_tpart[b*CSPBLK + blockIdx.x] = red[0];
}

// --- kernel 4: m1 = m0*(1 - W^T e) + W^T a   (W = wpow_w * inv_total) ------
// dynamic smem: wsh[64*64] | esD[64*128] | asD[64*128]  (dup'd for FFMA2)
__global__ void memupdate_kernel(const float* __restrict__ mem,
                                 const int* __restrict__ bank)
{
    extern __shared__ float sm[];
    float* wsh = sm;            // [k=b][n], n contiguous -> natural pairs
    float* esD = sm + 4096;     // [b][2m] duplicated
    float* asD = sm + 4096 + 8192;
    const int t = threadIdx.x;
    const int n0 = blockIdx.x * 64;
    const float inv = 1.f / (g_totals[0] + 1e-5f);
    const float* __restrict__ m0 = mem + (size_t)bank[0]*NNv*Mv;

    for (int i = t; i < 64*64; i += 256) {
        int bb = i >> 6, nl = i & 63;
        wsh[i] = g_wpow_w[(size_t)bb*NNv + n0 + nl];
        float ev = g_ev[i]*inv, av = g_av[i]*inv;
        *(float2*)&esD[bb*128 + 2*nl] = make_float2(ev, ev);
        *(float2*)&asD[bb*128 + 2*nl] = make_float2(av, av);
    }
    __syncthreads();

    const int tn = t >> 4, tm = t & 15;   // 4 n (2 pairs) x 4 m per thread
    ull ce[2][4], ca[2][4];
    #pragma unroll
    for (int p = 0; p < 2; p++)
        #pragma unroll
        for (int j = 0; j < 4; j++) { ce[p][j] = 0ull; ca[p][j] = 0ull; }

    #pragma unroll 8
    for (int k = 0; k < 64; k++) {
        const ulonglong2 A  = *(const ulonglong2*)&wsh[k*64  + 4*tn];
        const ulonglong2 E0 = *(const ulonglong2*)&esD[k*128 + 8*tm];
        const ulonglong2 E1 = *(const ulonglong2*)&esD[k*128 + 8*tm + 4];
        const ulonglong2 D0 = *(const ulonglong2*)&asD[k*128 + 8*tm];
        const ulonglong2 D1 = *(const ulonglong2*)&asD[k*128 + 8*tm + 4];
        ce[0][0]=ffma2(A.x,E0.x,ce[0][0]); ce[0][1]=ffma2(A.x,E0.y,ce[0][1]);
        ce[0][2]=ffma2(A.x,E1.x,ce[0][2]); ce[0][3]=ffma2(A.x,E1.y,ce[0][3]);
        ce[1][0]=ffma2(A.y,E0.x,ce[1][0]); ce[1][1]=ffma2(A.y,E0.y,ce[1][1]);
        ce[1][2]=ffma2(A.y,E1.x,ce[1][2]); ce[1][3]=ffma2(A.y,E1.y,ce[1][3]);
        ca[0][0]=ffma2(A.x,D0.x,ca[0][0]); ca[0][1]=ffma2(A.x,D0.y,ca[0][1]);
        ca[0][2]=ffma2(A.x,D1.x,ca[0][2]); ca[0][3]=ffma2(A.x,D1.y,ca[0][3]);
        ca[1][0]=ffma2(A.y,D0.x,ca[1][0]); ca[1][1]=ffma2(A.y,D0.y,ca[1][1]);
        ca[1][2]=ffma2(A.y,D1.x,ca[1][2]); ca[1][3]=ffma2(A.y,D1.y,ca[1][3]);
    }

    #pragma unroll
    for (int p = 0; p < 2; p++) {
        float cel[4], ceh[4], cal[4], cah[4];
        #pragma unroll
        for (int j = 0; j < 4; j++) {
            unpack2(ce[p][j], cel[j], ceh[j]);
            unpack2(ca[p][j], cal[j], cah[j]);
        }
        // even n of the pair
        {
            const size_t n = (size_t)(n0 + 4*tn + 2*p);
            const float4 o = *(const float4*)&m0[n*Mv + 4*tm];
            float4 v;
            v.x = o.x*(1.f - cel[0]) + cal[0];
            v.y = o.y*(1.f - cel[1]) + cal[1];
            v.z = o.z*(1.f - cel[2]) + cal[2];
            v.w = o.w*(1.f - cel[3]) + cal[3];
            *(float4*)&g_m1[n*Mv + 4*tm] = v;
        }
        // odd n of the pair
        {
            const size_t n = (size_t)(n0 + 4*tn + 2*p + 1);
            const float4 o = *(const float4*)&m0[n*Mv + 4*tm];
            float4 v;
            v.x = o.x*(1.f - ceh[0]) + cah[0];
            v.y = o.y*(1.f - ceh[1]) + cah[1];
            v.z = o.z*(1.f - ceh[2]) + cah[2];
            v.w = o.w*(1.f - ceh[3]) + cah[3];
            *(float4*)&g_m1[n*Mv + 4*tm] = v;
        }
    }
}

// ----- kernel 5 (FUSED): read-head gate+shift+pow computed per tile, ------
// fed straight into the split-K einsum. No wpow_r round-trip to HBM.
// dynamic smem: bshD[64*128] | wpT[64*68] | wgs[64*67] | prm[384] | red[256]
__global__ void fused_read_kernel(const float* __restrict__ wr)
{
    extern __shared__ float sm[];
    float* bshD = sm;                       // [k=n][2m] m1 tile duplicated
    float* wpT  = sm + 8192;                // [nl][b] pow tile (b contiguous)
    float* wgs  = sm + 8192 + 4352;         // [b][66] stride 67 (conflict-free)
    float* prm  = sm + 8192 + 4352 + 4288;  // g | invS | gm | s0 | s1 | s2
    float* red  = prm + 384;

    const int chunk = blockIdx.x, r = blockIdx.y;
    const int n0 = chunk * EK;
    const int t = threadIdx.x;

    if (t < 64) {
        prm[t]       = g_gate[t];
        prm[64 + t]  = 1.f / g_sumexp[t];
        prm[128 + t] = g_gamma[t];
        prm[192 + t] = g_shift[t*3+0];
        prm[256 + t] = g_shift[t*3+1];
        prm[320 + t] = g_shift[t*3+2];
    }
    const int tb = t >> 4, tm = t & 15;   // 4 b (2 pairs) x 4 m per thread
    ull acc[2][4];
    #pragma unroll
    for (int p = 0; p < 2; p++)
        #pragma unroll
        for (int j = 0; j < 4; j++) acc[p][j] = 0ull;
    float psum = 0.f;
    __syncthreads();

    for (int sub = 0; sub < ESUB; sub++) {
        const int nb = n0 + sub*64;
        // stage wg with 1-element halo each side
        for (int i = t; i < 64*66; i += 256) {
            const int bb = i / 66, x = i - bb*66;
            const int n = nb - 1 + x;
            float v = 0.f;
            if (n >= 0 && n < NNv) {
                const float gg = prm[bb];
                v = gg * g_E[(size_t)bb*NNv + n] * prm[64 + bb]
                  + (1.f - gg) * wr[((size_t)r*Bz + bb)*NNv + n];
            }
            wgs[bb*67 + x] = v;
        }
        // stage duplicated m1 tile
        for (int i = t; i < 64*64; i += 256) {
            const int kk = i >> 6, mm = i & 63;
            const float v = g_m1[(size_t)(nb + kk)*Mv + mm];
            *(float2*)&bshD[kk*128 + 2*mm] = make_float2(v, v);
        }
        __syncthreads();
        // shift + fast pow -> transposed tile, accumulate pow sum
        for (int i = t; i < 64*64; i += 256) {
            const int nl = i >> 6, bb = i & 63;
            const float* w = &wgs[bb*67 + nl];
            const float wt = fmaf(prm[192+bb], w[0],
                             fmaf(prm[256+bb], w[1], prm[320+bb]*w[2]));
            const float pw = fpow(wt, prm[128 + bb]);
            wpT[nl*68 + bb] = pw;
            psum += pw;
        }
        __syncthreads();
        // GEMM over this 64-n sub-tile
        #pragma unroll 8
        for (int k = 0; k < 64; k++) {
            const ulonglong2 A  = *(const ulonglong2*)&wpT [k*68  + 4*tb];
            const ulonglong2 B0 = *(const ulonglong2*)&bshD[k*128 + 8*tm];
            const ulonglong2 B1 = *(const ulonglong2*)&bshD[k*128 + 8*tm + 4];
            acc[0][0]=ffma2(A.x,B0.x,acc[0][0]); acc[0][1]=ffma2(A.x,B0.y,acc[0][1]);
            acc[0][2]=ffma2(A.x,B1.x,acc[0][2]); acc[0][3]=ffma2(A.x,B1.y,acc[0][3]);
            acc[1][0]=ffma2(A.y,B0.x,acc[1][0]); acc[1][1]=ffma2(A.y,B0.y,acc[1][1]);
            acc[1][2]=ffma2(A.y,B1.x,acc[1][2]); acc[1][3]=ffma2(A.y,B1.y,acc[1][3]);
        }
        __syncthreads();
    }

    // write split-K partials
    const size_t base = ((size_t)r*ECHUNK + chunk) * (Bz*Mv);
    #pragma unroll
    for (int p = 0; p < 2; p++) {
        float lo[4], hi[4];
        #pragma unroll
        for (int j = 0; j < 4; j++) unpack2(acc[p][j], lo[j], hi[j]);
        *(float4*)&g_epart[base + (size_t)(4*tb + 2*p    )*Mv + 4*tm]
            = make_float4(lo[0], lo[1], lo[2], lo[3]);
        *(float4*)&g_epart[base + (size_t)(4*tb + 2*p + 1)*Mv + 4*tm]
            = make_float4(hi[0], hi[1], hi[2], hi[3]);
    }
    // reduce pow partial sum for this (r, chunk)
    red[t] = psum; __syncthreads();
    for (int off = 128; off; off >>= 1) { if (t < off) red[t] += red[t+off]; __syncthreads(); }
    if (t == 0) g_tpartR[r*ECHUNK + chunk] = red[0];
}

// ----- kernel 6: reduce split-K + apply 1/(total_r+eps) + transpose --------
__global__ void reduce_out_kernel(float* __restrict__ out)
{
    const int gid = blockIdx.x*256 + threadIdx.x;   // 0..R*B*M-1
    const int r = gid >> 12;
    const int b = (gid >> 6) & 63;
    const int m = gid & 63;
    const float inv = 1.f / (g_totals[1 + r] + 1e-5f);
    float s = 0.f;
    for (int c = 0; c < ECHUNK; c++)
        s += g_epart[(((size_t)r*ECHUNK + c)*Bz + b)*Mv + m];
    out[(size_t)b*(Rv*Mv) + r*Mv + m] = s * inv;
}

// ---------------------------------------------------------------------------
extern "C" void kernel_launch(void* const* d_in, const int* in_sizes, int n_in,
                              void* d_out, int out_size)
{
    const float* h_t     = (const float*)d_in[0];
    const float* ww      = (const float*)d_in[1];
    const float* wr      = (const float*)d_in[2];
    const float* memory  = (const float*)d_in[3];
    const float* key_w   = (const float*)d_in[4];
    const float* key_b   = (const float*)d_in[5];
    const float* beta_w  = (const float*)d_in[6];
    const float* beta_b  = (const float*)d_in[7];
    const float* gate_w  = (const float*)d_in[8];
    const float* gate_b  = (const float*)d_in[9];
    const float* shift_w = (const float*)d_in[10];
    const float* shift_b = (const float*)d_in[11];
    const float* gamma_w = (const float*)d_in[12];
    const float* gamma_b = (const float*)d_in[13];
    const float* erase_w = (const float*)d_in[14];
    const float* erase_b = (const float*)d_in[15];
    const float* add_w   = (const float*)d_in[16];
    const float* add_b   = (const float*)d_in[17];
    const int*   bank    = (const int*)d_in[18];
    float* out = (float*)d_out;

    const int MEMUP_SMEM = (4096 + 8192 + 8192) * 4;               // 81920 B
    const int FUSED_SMEM = (8192 + 4352 + 4288 + 384 + 256) * 4;   // 69888 B
    cudaFuncSetAttribute(memupdate_kernel,
        cudaFuncAttributeMaxDynamicSharedMemorySize, MEMUP_SMEM);
    cudaFuncSetAttribute(fused_read_kernel,
        cudaFuncAttributeMaxDynamicSharedMemorySize, FUSED_SMEM);

    // head params (shared by all 5 weight updates)
    heads_kernel<<<Bz, 256>>>(h_t, key_w, key_b, beta_w, beta_b, gate_w, gate_b,
                              shift_w, shift_b, gamma_w, gamma_b,
                              erase_w, erase_b, add_w, add_b);

    // --- write head: content addressing on m0 ---
    sim_kernel<<<SIMBLK, 256>>>(memory, bank, 0);
    reduce_sumexp_kernel<<<Bz, 256>>>();
    csp_write_kernel<<<dim3(CSPBLK, Bz), 256>>>(ww);
    reduce_totalW_kernel<<<1, 256>>>();

    // --- memory erase/add ---
    memupdate_kernel<<<NNv/64, 256, MEMUP_SMEM>>>(memory, bank);

    // --- read heads: shared content addressing on m1, fused csp+einsum ---
    sim_kernel<<<SIMBLK, 256>>>(memory, bank, 1);
    reduce_sumexp_kernel<<<Bz, 256>>>();
    fused_read_kernel<<<dim3(ECHUNK, Rv), 256, FUSED_SMEM>>>(wr);
    reduce_totalR_kernel<<<Rv, 256>>>();

    // --- final: reduce split-K, normalize, transpose ---
    reduce_out_kernel<<<(Rv*Bz*Mv)/256, 256>>>(out);
}

// round 5
// speedup vs baseline: 1.0018x; 1.0018x over previous
#include <cuda_runtime.h>
#include <math.h>

typedef unsigned long long ull;

#define Bz 64
#define Hh 1024
#define NNv 65536
#define Mv 64
#define Rv 4
#define SIMBLK (NNv/64)   /* 1024 sim blocks */
#define CSPBLK 64         /* write-head csp blocks per b (1024 n each) */
#define ECHUNK 256        /* fused read chunks */
#define EK (NNv/ECHUNK)   /* 256 n per chunk */
#define ESUB (EK/64)      /* 4 sub-tiles of 64 n */

// ---------------- scratch (device globals: no allocation allowed) ----------
__device__ float g_E[(size_t)Bz*NNv];            // exp(beta*sim) [B,N]
__device__ float g_wpow_w[(size_t)Bz*NNv];       // write-head w_pow
__device__ float g_m1[(size_t)NNv*Mv];           // updated memory
__device__ float g_kn[Bz*Mv];
__device__ float g_ev[Bz*Mv];
__device__ float g_av[Bz*Mv];
__device__ float g_beta[Bz];
__device__ float g_gate[Bz];
__device__ float g_gamma[Bz];
__device__ float g_shift[Bz*3];
__device__ float g_psum[(size_t)Bz*SIMBLK];
__device__ float g_sumexp[Bz];
__device__ float g_tpart[Bz*CSPBLK];             // write-head pow partials
__device__ float g_tpartR[Rv*ECHUNK];            // read-head pow partials
__device__ float g_totals[1+Rv];                 // [0]=write, [1..4]=read totals
__device__ float g_epart[(size_t)Rv*ECHUNK*Bz*Mv]; // fused split-K partials

__device__ __forceinline__ float clip01(float x){ return fminf(fmaxf(x, 0.f), 1.f); }
// fast x^g for x > 0 (x==0 -> -inf -> 0, also fine)
__device__ __forceinline__ float fpow(float x, float g){ return __expf(g * __logf(x)); }

__device__ __forceinline__ ull ffma2(ull a, ull b, ull c){
    ull d;
    asm("fma.rn.f32x2 %0, %1, %2, %3;" : "=l"(d) : "l"(a), "l"(b), "l"(c));
    return d;
}
__device__ __forceinline__ ull dup2(float x){
    ull d;
    asm("mov.b64 %0, {%1, %1};" : "=l"(d) : "f"(x));
    return d;
}
__device__ __forceinline__ void unpack2(ull v, float& lo, float& hi){
    asm("mov.b64 {%0, %1}, %2;" : "=f"(lo), "=f"(hi) : "l"(v));
}

// ---------------- kernel 1: head projections (once per step) ---------------
__global__ void heads_kernel(const float* __restrict__ h,
    const float* __restrict__ key_w,   const float* __restrict__ key_b,
    const float* __restrict__ beta_w,  const float* __restrict__ beta_b,
    const float* __restrict__ gate_w,  const float* __restrict__ gate_b,
    const float* __restrict__ shift_w, const float* __restrict__ shift_b,
    const float* __restrict__ gamma_w, const float* __restrict__ gamma_b,
    const float* __restrict__ erase_w, const float* __restrict__ erase_b,
    const float* __restrict__ add_w,   const float* __restrict__ add_b)
{
    __shared__ float hs[Hh];
    __shared__ float ksh[Mv];
    __shared__ float sdot[6];
    __shared__ float sinv;
    const int b = blockIdx.x, t = threadIdx.x;
    for (int i = t; i < Hh; i += 256) hs[i] = h[(size_t)b*Hh + i];
    __syncthreads();

    if (t < 64) {
        float a0=0,a1=0,a2=0,a3=0;
        for (int j = 0; j < Hh; j += 4) {
            a0 = fmaf(hs[j  ], key_w[(j  )*Mv + t], a0);
            a1 = fmaf(hs[j+1], key_w[(j+1)*Mv + t], a1);
            a2 = fmaf(hs[j+2], key_w[(j+2)*Mv + t], a2);
            a3 = fmaf(hs[j+3], key_w[(j+3)*Mv + t], a3);
        }
        ksh[t] = clip01(a0+a1+a2+a3 + key_b[t]);
    } else if (t < 128) {
        const int m = t - 64;
        float a0=0,a1=0,a2=0,a3=0;
        for (int j = 0; j < Hh; j += 4) {
            a0 = fmaf(hs[j  ], erase_w[(j  )*Mv + m], a0);
            a1 = fmaf(hs[j+1], erase_w[(j+1)*Mv + m], a1);
            a2 = fmaf(hs[j+2], erase_w[(j+2)*Mv + m], a2);
            a3 = fmaf(hs[j+3], erase_w[(j+3)*Mv + m], a3);
        }
        g_ev[b*Mv + m] = clip01(a0+a1+a2+a3 + erase_b[m]);
    } else if (t < 192) {
        const int m = t - 128;
        float a0=0,a1=0,a2=0,a3=0;
        for (int j = 0; j < Hh; j += 4) {
            a0 = fmaf(hs[j  ], add_w[(j  )*Mv + m], a0);
            a1 = fmaf(hs[j+1], add_w[(j+1)*Mv + m], a1);
            a2 = fmaf(hs[j+2], add_w[(j+2)*Mv + m], a2);
            a3 = fmaf(hs[j+3], add_w[(j+3)*Mv + m], a3);
        }
        g_av[b*Mv + m] = clip01(a0+a1+a2+a3 + add_b[m]);
    } else if (t < 198) {
        const int d = t - 192;
        const float* w; int str, col;
        if      (d == 0) { w = beta_w;  str = 1; col = 0; }
        else if (d == 1) { w = gate_w;  str = 1; col = 0; }
        else if (d == 2) { w = gamma_w; str = 1; col = 0; }
        else             { w = shift_w; str = 3; col = d - 3; }
        float a0=0,a1=0;
        for (int j = 0; j < Hh; j += 2) {
            a0 = fmaf(hs[j  ], w[(j  )*str + col], a0);
            a1 = fmaf(hs[j+1], w[(j+1)*str + col], a1);
        }
        sdot[d] = a0 + a1;
    }
    __syncthreads();

    if (t < 32) {
        float v = ksh[t]*ksh[t] + ksh[t+32]*ksh[t+32];
        #pragma unroll
        for (int off = 16; off; off >>= 1) v += __shfl_xor_sync(0xffffffffu, v, off);
        if (t == 0) sinv = 1.f / (sqrtf(v) + 1e-8f);
    }
    __syncthreads();
    if (t < 64) g_kn[b*Mv + t] = ksh[t] * sinv;
    if (t == 0) {
        g_beta[b]  = fmaxf(sdot[0] + beta_b[0], 0.f);
        g_gate[b]  = clip01(sdot[1] + gate_b[0]);
        g_gamma[b] = 1.f + fmaxf(sdot[2] + gamma_b[0], 0.f);
        float x0 = sdot[3] + shift_b[0];
        float x1 = sdot[4] + shift_b[1];
        float x2 = sdot[5] + shift_b[2];
        float mx = fmaxf(x0, fmaxf(x1, x2));
        float e0 = expf(x0-mx), e1 = expf(x1-mx), e2 = expf(x2-mx);
        float is = 1.f / (e0+e1+e2);
        g_shift[b*3+0] = e0*is; g_shift[b*3+1] = e1*is; g_shift[b*3+2] = e2*is;
    }
}

// ------- kernel 2: E[b,n] = exp(beta[b] * (kn[b]·m[n]) / (||m[n]||+eps)) ---
__global__ void sim_kernel(const float* __restrict__ mem,
                           const int* __restrict__ bank, int use_m1)
{
    const float* __restrict__ src = use_m1 ? g_m1
                                           : (mem + (size_t)bank[0]*NNv*Mv);
    __shared__ float knT[64*68];   // [k][b], padded; b contiguous -> natural pairs
    __shared__ float mt [64*68];   // [k][n], padded
    __shared__ float invn[64];
    __shared__ float sbeta[64];
    const int t = threadIdx.x;
    const int n0 = blockIdx.x * 64;

    for (int i = t; i < 64*64; i += 256) {
        int bb = i >> 6, mm = i & 63;
        knT[mm*68 + bb] = g_kn[i];
    }
    for (int i = t; i < 64*64; i += 256) {
        int rr = i >> 6, cc = i & 63;
        mt[cc*68 + rr] = src[(size_t)(n0 + rr)*Mv + cc];
    }
    if (t < 64) sbeta[t] = g_beta[t];
    __syncthreads();
    if (t < 64) {
        float s = 0.f;
        #pragma unroll 16
        for (int k = 0; k < 64; k++) { float v = mt[k*68 + t]; s = fmaf(v, v, s); }
        invn[t] = 1.f / (sqrtf(s) + 1e-8f);
    }
    __syncthreads();

    const int by = t >> 5, nx = t & 31;   // 8 b's (4 pairs), 2 n's per thread
    ull acc[4][2];
    #pragma unroll
    for (int p = 0; p < 4; p++) { acc[p][0] = 0ull; acc[p][1] = 0ull; }

    #pragma unroll 8
    for (int k = 0; k < 64; k++) {
        const ulonglong2 A0 = *(const ulonglong2*)&knT[k*68 + 8*by];
        const ulonglong2 A1 = *(const ulonglong2*)&knT[k*68 + 8*by + 4];
        const float2 Bv = *(const float2*)&mt [k*68 + 2*nx];
        const ull d0 = dup2(Bv.x), d1 = dup2(Bv.y);
        acc[0][0] = ffma2(A0.x, d0, acc[0][0]); acc[0][1] = ffma2(A0.x, d1, acc[0][1]);
        acc[1][0] = ffma2(A0.y, d0, acc[1][0]); acc[1][1] = ffma2(A0.y, d1, acc[1][1]);
        acc[2][0] = ffma2(A1.x, d0, acc[2][0]); acc[2][1] = ffma2(A1.x, d1, acc[2][1]);
        acc[3][0] = ffma2(A1.y, d0, acc[3][0]); acc[3][1] = ffma2(A1.y, d1, acc[3][1]);
    }

    const float2 iv = *(const float2*)&invn[2*nx];
    float ps[8];
    #pragma unroll
    for (int p = 0; p < 4; p++) {
        float c0l, c0h, c1l, c1h;
        unpack2(acc[p][0], c0l, c0h);
        unpack2(acc[p][1], c1l, c1h);
        const int bbl = 8*by + 2*p, bbh = bbl + 1;
        const float btl = sbeta[bbl], bth = sbeta[bbh];
        float e0l = __expf(btl * c0l * iv.x);
        float e1l = __expf(btl * c1l * iv.y);
        float e0h = __expf(bth * c0h * iv.x);
        float e1h = __expf(bth * c1h * iv.y);
        *(float2*)&g_E[(size_t)bbl*NNv + n0 + 2*nx] = make_float2(e0l, e1l);
        *(float2*)&g_E[(size_t)bbh*NNv + n0 + 2*nx] = make_float2(e0h, e1h);
        ps[2*p]   = e0l + e1l;
        ps[2*p+1] = e0h + e1h;
    }
    #pragma unroll
    for (int bi = 0; bi < 8; bi++)
        #pragma unroll
        for (int off = 16; off; off >>= 1)
            ps[bi] += __shfl_xor_sync(0xffffffffu, ps[bi], off);
    if (nx == 0) {
        #pragma unroll
        for (int bi = 0; bi < 8; bi++)
            g_psum[(size_t)(8*by + bi)*SIMBLK + blockIdx.x] = ps[bi];
    }
}

// ---------------- deterministic reductions ---------------------------------
__global__ void reduce_sumexp_kernel()
{
    const int b = blockIdx.x, t = threadIdx.x;
    float s = 0.f;
    for (int i = t; i < SIMBLK; i += 256) s += g_psum[(size_t)b*SIMBLK + i];
    __shared__ float red[256];
    red[t] = s; __syncthreads();
    for (int off = 128; off; off >>= 1) { if (t < off) red[t] += red[t+off]; __syncthreads(); }
    if (t == 0) g_sumexp[b] = red[0];
}

__global__ void reduce_totalW_kernel()
{
    const int t = threadIdx.x;
    float s = 0.f;
    for (int i = t; i < Bz*CSPBLK; i += 256) s += g_tpart[i];
    __shared__ float red[256];
    red[t] = s; __syncthreads();
    for (int off = 128; off; off >>= 1) { if (t < off) red[t] += red[t+off]; __syncthreads(); }
    if (t == 0) g_totals[0] = red[0];
}

__global__ void reduce_totalR_kernel()
{
    const int r = blockIdx.x, t = threadIdx.x;  // ECHUNK==256 threads
    __shared__ float red[256];
    red[t] = g_tpartR[r*ECHUNK + t]; __syncthreads();
    for (int off = 128; off; off >>= 1) { if (t < off) red[t] += red[t+off]; __syncthreads(); }
    if (t == 0) g_totals[1 + r] = red[0];
}

// ----- kernel 3: WRITE head: gate + 3-tap shift + fast pow + partial sum ---
__global__ void csp_write_kernel(const float* __restrict__ ww)
{
    const int b  = blockIdx.y;
    const int c0 = blockIdx.x * 1024;
    const float* __restrict__ wp = ww + (size_t)b*NNv;
    float* __restrict__ wo = g_wpow_w + (size_t)b*NNv;
    const float* __restrict__ Eb = g_E + (size_t)b*NNv;

    __shared__ float wg[1026];
    __shared__ float red[256];
    const float gg   = g_gate[b];
    const float invS = 1.f / g_sumexp[b];
    const float s0 = g_shift[b*3+0], s1 = g_shift[b*3+1], s2 = g_shift[b*3+2];
    const float gm = g_gamma[b];
    const int t = threadIdx.x;

    for (int i = t; i < 1026; i += 256) {
        const int n = c0 + i - 1;
        float v = 0.f;
        if (n >= 0 && n < NNv)
            v = gg * Eb[n] * invS + (1.f - gg) * wp[n];
        wg[i] = v;
    }
    __syncthreads();

    float ls = 0.f;
    #pragma unroll
    for (int j = 0; j < 4; j++) {
        const int i = t + j*256;
        const float wt = fmaf(s0, wg[i], fmaf(s1, wg[i+1], s2*wg[i+2]));
        const float pw = fpow(wt, gm);
        wo[c0 + i] = pw;
        ls += pw;
    }
    red[t] = ls; __syncthreads();
    for (int off = 128; off; off >>= 1) { if (t < off) red[t] += red[t+off]; __syncthreads(); }
    if (t == 0) g_tpart[b*CSPBLK + blockIdx.x] = red[0];
}

// --- kernel 4: m1 = m0*(1 - W^T e) + W^T a   (W = wpow_w * inv_total) ------
// dynamic smem: wsh[64*64] | esD[64*128] | asD[64*128]  (dup'd for FFMA2)
__global__ void memupdate_kernel(const float* __restrict__ mem,
                                 const int* __restrict__ bank)
{
    extern __shared__ float sm[];
    float* wsh = sm;            // [k=b][n], n contiguous -> natural pairs
    float* esD = sm + 4096;     // [b][2m] duplicated
    float* asD = sm + 4096 + 8192;
    const int t = threadIdx.x;
    const int n0 = blockIdx.x * 64;
    const float inv = 1.f / (g_totals[0] + 1e-5f);
    const float* __restrict__ m0 = mem + (size_t)bank[0]*NNv*Mv;

    for (int i = t; i < 64*64; i += 256) {
        int bb = i >> 6, nl = i & 63;
        wsh[i] = g_wpow_w[(size_t)bb*NNv + n0 + nl];
        float ev = g_ev[i]*inv, av = g_av[i]*inv;
        *(float2*)&esD[bb*128 + 2*nl] = make_float2(ev, ev);
        *(float2*)&asD[bb*128 + 2*nl] = make_float2(av, av);
    }
    __syncthreads();

    const int tn = t >> 4, tm = t & 15;   // 4 n (2 pairs) x 4 m per thread
    ull ce[2][4], ca[2][4];
    #pragma unroll
    for (int p = 0; p < 2; p++)
        #pragma unroll
        for (int j = 0; j < 4; j++) { ce[p][j] = 0ull; ca[p][j] = 0ull; }

    #pragma unroll 8
    for (int k = 0; k < 64; k++) {
        const ulonglong2 A  = *(const ulonglong2*)&wsh[k*64  + 4*tn];
        const ulonglong2 E0 = *(const ulonglong2*)&esD[k*128 + 8*tm];
        const ulonglong2 E1 = *(const ulonglong2*)&esD[k*128 + 8*tm + 4];
        const ulonglong2 D0 = *(const ulonglong2*)&asD[k*128 + 8*tm];
        const ulonglong2 D1 = *(const ulonglong2*)&asD[k*128 + 8*tm + 4];
        ce[0][0]=ffma2(A.x,E0.x,ce[0][0]); ce[0][1]=ffma2(A.x,E0.y,ce[0][1]);
        ce[0][2]=ffma2(A.x,E1.x,ce[0][2]); ce[0][3]=ffma2(A.x,E1.y,ce[0][3]);
        ce[1][0]=ffma2(A.y,E0.x,ce[1][0]); ce[1][1]=ffma2(A.y,E0.y,ce[1][1]);
        ce[1][2]=ffma2(A.y,E1.x,ce[1][2]); ce[1][3]=ffma2(A.y,E1.y,ce[1][3]);
        ca[0][0]=ffma2(A.x,D0.x,ca[0][0]); ca[0][1]=ffma2(A.x,D0.y,ca[0][1]);
        ca[0][2]=ffma2(A.x,D1.x,ca[0][2]); ca[0][3]=ffma2(A.x,D1.y,ca[0][3]);
        ca[1][0]=ffma2(A.y,D0.x,ca[1][0]); ca[1][1]=ffma2(A.y,D0.y,ca[1][1]);
        ca[1][2]=ffma2(A.y,D1.x,ca[1][2]); ca[1][3]=ffma2(A.y,D1.y,ca[1][3]);
    }

    #pragma unroll
    for (int p = 0; p < 2; p++) {
        float cel[4], ceh[4], cal[4], cah[4];
        #pragma unroll
        for (int j = 0; j < 4; j++) {
            unpack2(ce[p][j], cel[j], ceh[j]);
            unpack2(ca[p][j], cal[j], cah[j]);
        }
        // even n of the pair
        {
            const size_t n = (size_t)(n0 + 4*tn + 2*p);
            const float4 o = *(const float4*)&m0[n*Mv + 4*tm];
            float4 v;
            v.x = o.x*(1.f - cel[0]) + cal[0];
            v.y = o.y*(1.f - cel[1]) + cal[1];
            v.z = o.z*(1.f - cel[2]) + cal[2];
            v.w = o.w*(1.f - cel[3]) + cal[3];
            *(float4*)&g_m1[n*Mv + 4*tm] = v;
        }
        // odd n of the pair
        {
            const size_t n = (size_t)(n0 + 4*tn + 2*p + 1);
            const float4 o = *(const float4*)&m0[n*Mv + 4*tm];
            float4 v;
            v.x = o.x*(1.f - ceh[0]) + cah[0];
            v.y = o.y*(1.f - ceh[1]) + cah[1];
            v.z = o.z*(1.f - ceh[2]) + cah[2];
            v.w = o.w*(1.f - ceh[3]) + cah[3];
            *(float4*)&g_m1[n*Mv + 4*tm] = v;
        }
    }
}

// ----- kernel 5 (FUSED): read-head gate+shift+pow computed per tile, ------
// fed straight into the split-K einsum. No wpow_r round-trip to HBM.
// dynamic smem: bshD[64*128] | wpT[64*68] | wgs[64*67] | prm[384] | red[256]
__global__ void fused_read_kernel(const float* __restrict__ wr)
{
    extern __shared__ float sm[];
    float* bshD = sm;                       // [k=n][2m] m1 tile duplicated
    float* wpT  = sm + 8192;                // [nl][b] pow tile (b contiguous)
    float* wgs  = sm + 8192 + 4352;         // [b][66] stride 67 (conflict-free)
    float* prm  = sm + 8192 + 4352 + 4288;  // g | invS | gm | s0 | s1 | s2
    float* red  = prm + 384;

    const int chunk = blockIdx.x, r = blockIdx.y;
    const int n0 = chunk * EK;
    const int t = threadIdx.x;

    if (t < 64) {
        prm[t]       = g_gate[t];
        prm[64 + t]  = 1.f / g_sumexp[t];
        prm[128 + t] = g_gamma[t];
        prm[192 + t] = g_shift[t*3+0];
        prm[256 + t] = g_shift[t*3+1];
        prm[320 + t] = g_shift[t*3+2];
    }
    const int tb = t >> 4, tm = t & 15;   // 4 b (2 pairs) x 4 m per thread
    ull acc[2][4];
    #pragma unroll
    for (int p = 0; p < 2; p++)
        #pragma unroll
        for (int j = 0; j < 4; j++) acc[p][j] = 0ull;
    float psum = 0.f;
    __syncthreads();

    for (int sub = 0; sub < ESUB; sub++) {
        const int nb = n0 + sub*64;
        // stage wg with 1-element halo each side
        for (int i = t; i < 64*66; i += 256) {
            const int bb = i / 66, x = i - bb*66;
            const int n = nb - 1 + x;
            float v = 0.f;
            if (n >= 0 && n < NNv) {
                const float gg = prm[bb];
                v = gg * g_E[(size_t)bb*NNv + n] * prm[64 + bb]
                  + (1.f - gg) * wr[((size_t)r*Bz + bb)*NNv + n];
            }
            wgs[bb*67 + x] = v;
        }
        // stage duplicated m1 tile
        for (int i = t; i < 64*64; i += 256) {
            const int kk = i >> 6, mm = i & 63;
            const float v = g_m1[(size_t)(nb + kk)*Mv + mm];
            *(float2*)&bshD[kk*128 + 2*mm] = make_float2(v, v);
        }
        __syncthreads();
        // shift + fast pow -> transposed tile, accumulate pow sum
        for (int i = t; i < 64*64; i += 256) {
            const int nl = i >> 6, bb = i & 63;
            const float* w = &wgs[bb*67 + nl];
            const float wt = fmaf(prm[192+bb], w[0],
                             fmaf(prm[256+bb], w[1], prm[320+bb]*w[2]));
            const float pw = fpow(wt, prm[128 + bb]);
            wpT[nl*68 + bb] = pw;
            psum += pw;
        }
        __syncthreads();
        // GEMM over this 64-n sub-tile
        #pragma unroll 8
        for (int k = 0; k < 64; k++) {
            const ulonglong2 A  = *(const ulonglong2*)&wpT [k*68  + 4*tb];
            const ulonglong2 B0 = *(const ulonglong2*)&bshD[k*128 + 8*tm];
            const ulonglong2 B1 = *(const ulonglong2*)&bshD[k*128 + 8*tm + 4];
            acc[0][0]=ffma2(A.x,B0.x,acc[0][0]); acc[0][1]=ffma2(A.x,B0.y,acc[0][1]);
            acc[0][2]=ffma2(A.x,B1.x,acc[0][2]); acc[0][3]=ffma2(A.x,B1.y,acc[0][3]);
            acc[1][0]=ffma2(A.y,B0.x,acc[1][0]); acc[1][1]=ffma2(A.y,B0.y,acc[1][1]);
            acc[1][2]=ffma2(A.y,B1.x,acc[1][2]); acc[1][3]=ffma2(A.y,B1.y,acc[1][3]);
        }
        __syncthreads();
    }

    // write split-K partials
    const size_t base = ((size_t)r*ECHUNK + chunk) * (Bz*Mv);
    #pragma unroll
    for (int p = 0; p < 2; p++) {
        float lo[4], hi[4];
        #pragma unroll
        for (int j = 0; j < 4; j++) unpack2(acc[p][j], lo[j], hi[j]);
        *(float4*)&g_epart[base + (size_t)(4*tb + 2*p    )*Mv + 4*tm]
            = make_float4(lo[0], lo[1], lo[2], lo[3]);
        *(float4*)&g_epart[base + (size_t)(4*tb + 2*p + 1)*Mv + 4*tm]
            = make_float4(hi[0], hi[1], hi[2], hi[3]);
    }
    // reduce pow partial sum for this (r, chunk)
    red[t] = psum; __syncthreads();
    for (int off = 128; off; off >>= 1) { if (t < off) red[t] += red[t+off]; __syncthreads(); }
    if (t == 0) g_tpartR[r*ECHUNK + chunk] = red[0];
}

// ----- kernel 6: reduce split-K + apply 1/(total_r+eps) + transpose --------
__global__ void reduce_out_kernel(float* __restrict__ out)
{
    const int gid = blockIdx.x*256 + threadIdx.x;   // 0..R*B*M-1
    const int r = gid >> 12;
    const int b = (gid >> 6) & 63;
    const int m = gid & 63;
    const float inv = 1.f / (g_totals[1 + r] + 1e-5f);
    float s = 0.f;
    for (int c = 0; c < ECHUNK; c++)
        s += g_epart[(((size_t)r*ECHUNK + c)*Bz + b)*Mv + m];
    out[(size_t)b*(Rv*Mv) + r*Mv + m] = s * inv;
}

// ---------------------------------------------------------------------------
extern "C" void kernel_launch(void* const* d_in, const int* in_sizes, int n_in,
                              void* d_out, int out_size)
{
    const float* h_t     = (const float*)d_in[0];
    const float* ww      = (const float*)d_in[1];
    const float* wr      = (const float*)d_in[2];
    const float* memory  = (const float*)d_in[3];
    const float* key_w   = (const float*)d_in[4];
    const float* key_b   = (const float*)d_in[5];
    const float* beta_w  = (const float*)d_in[6];
    const float* beta_b  = (const float*)d_in[7];
    const float* gate_w  = (const float*)d_in[8];
    const float* gate_b  = (const float*)d_in[9];
    const float* shift_w = (const float*)d_in[10];
    const float* shift_b = (const float*)d_in[11];
    const float* gamma_w = (const float*)d_in[12];
    const float* gamma_b = (const float*)d_in[13];
    const float* erase_w = (const float*)d_in[14];
    const float* erase_b = (const float*)d_in[15];
    const float* add_w   = (const float*)d_in[16];
    const float* add_b   = (const float*)d_in[17];
    const int*   bank    = (const int*)d_in[18];
    float* out = (float*)d_out;

    const int MEMUP_SMEM = (4096 + 8192 + 8192) * 4;               // 81920 B
    const int FUSED_SMEM = (8192 + 4352 + 4288 + 384 + 256) * 4;   // 69888 B
    cudaFuncSetAttribute(memupdate_kernel,
        cudaFuncAttributeMaxDynamicSharedMemorySize, MEMUP_SMEM);
    cudaFuncSetAttribute(fused_read_kernel,
        cudaFuncAttributeMaxDynamicSharedMemorySize, FUSED_SMEM);

    // head params (shared by all 5 weight updates)
    heads_kernel<<<Bz, 256>>>(h_t, key_w, key_b, beta_w, beta_b, gate_w, gate_b,
                              shift_w, shift_b, gamma_w, gamma_b,
                              erase_w, erase_b, add_w, add_b);

    // --- write head: content addressing on m0 ---
    sim_kernel<<<SIMBLK, 256>>>(memory, bank, 0);
    reduce_sumexp_kernel<<<Bz, 256>>>();
    csp_write_kernel<<<dim3(CSPBLK, Bz), 256>>>(ww);
    reduce_totalW_kernel<<<1, 256>>>();

    // --- memory erase/add ---
    memupdate_kernel<<<NNv/64, 256, MEMUP_SMEM>>>(memory, bank);

    // --- read heads: shared content addressing on m1, fused csp+einsum ---
    sim_kernel<<<SIMBLK, 256>>>(memory, bank, 1);
    reduce_sumexp_kernel<<<Bz, 256>>>();
    fused_read_kernel<<<dim3(ECHUNK, Rv), 256, FUSED_SMEM>>>(wr);
    reduce_totalR_kernel<<<Rv, 256>>>();

    // --- final: reduce split-K, normalize, transpose ---
    reduce_out_kernel<<<(Rv*Bz*Mv)/256, 256>>>(out);
}

// round 6
// speedup vs baseline: 1.0940x; 1.0919x over previous
#include <cuda_runtime.h>
#include <math.h>

typedef unsigned long long ull;

#define Bz 64
#define Hh 1024
#define NNv 65536
#define Mv 64
#define Rv 4
#define SIMBLK (NNv/64)   /* 1024 sim blocks */
#define CSPBLK 64         /* N/1024 csp blocks per b */
#define ECHUNK 128        /* einsum split-K chunks */
#define EK (NNv/ECHUNK)   /* 512 n per chunk */

// ---------------- scratch (device globals: no allocation allowed) ----------
__device__ float g_E[(size_t)Bz*NNv];            // exp(beta*sim) buffer [B,N]
__device__ float g_wpow_w[(size_t)Bz*NNv];       // write-head w_pow
__device__ float g_wpow_r[(size_t)Rv*Bz*NNv];    // read-head w_pow [R,B,N]
__device__ float g_m1[(size_t)NNv*Mv];           // updated memory
__device__ float g_kn[Bz*Mv];
__device__ float g_ev[Bz*Mv];
__device__ float g_av[Bz*Mv];
__device__ float g_beta[Bz];
__device__ float g_gate[Bz];
__device__ float g_gamma[Bz];
__device__ float g_shift[Bz*3];
__device__ float g_psum[(size_t)Bz*SIMBLK];      // per-block exp partial sums
__device__ float g_sumexp[Bz];
__device__ float g_tpart[Rv*Bz*CSPBLK];          // per-block pow partial sums
__device__ float g_totals[1+Rv];                 // [0]=write total, [1..4]=read totals
__device__ float g_epart[(size_t)Rv*ECHUNK*Bz*Mv]; // einsum split-K partials

__device__ __forceinline__ float clip01(float x){ return fminf(fmaxf(x, 0.f), 1.f); }
// fast x^g for x > 0 (w_tilde is strictly positive: softmax inputs, s_j > 0)
__device__ __forceinline__ float fpow(float x, float g){ return __expf(g * __logf(x)); }

__device__ __forceinline__ ull ffma2(ull a, ull b, ull c){
    ull d;
    asm("fma.rn.f32x2 %0, %1, %2, %3;" : "=l"(d) : "l"(a), "l"(b), "l"(c));
    return d;
}
__device__ __forceinline__ void unpack2(ull v, float& lo, float& hi){
    asm("mov.b64 {%0, %1}, %2;" : "=f"(lo), "=f"(hi) : "l"(v));
}

// ---------------- kernel 1: head projections (once per step) ---------------
__global__ void heads_kernel(const float* __restrict__ h,
    const float* __restrict__ key_w,   const float* __restrict__ key_b,
    const float* __restrict__ beta_w,  const float* __restrict__ beta_b,
    const float* __restrict__ gate_w,  const float* __restrict__ gate_b,
    const float* __restrict__ shift_w, const float* __restrict__ shift_b,
    const float* __restrict__ gamma_w, const float* __restrict__ gamma_b,
    const float* __restrict__ erase_w, const float* __restrict__ erase_b,
    const float* __restrict__ add_w,   const float* __restrict__ add_b)
{
    __shared__ float hs[Hh];
    __shared__ float ksh[Mv];
    __shared__ float sdot[6];
    __shared__ float sinv;
    const int b = blockIdx.x, t = threadIdx.x;
    for (int i = t; i < Hh; i += 256) hs[i] = h[(size_t)b*Hh + i];
    __syncthreads();

    if (t < 64) {
        float a0=0,a1=0,a2=0,a3=0;
        for (int j = 0; j < Hh; j += 4) {
            a0 = fmaf(hs[j  ], key_w[(j  )*Mv + t], a0);
            a1 = fmaf(hs[j+1], key_w[(j+1)*Mv + t], a1);
            a2 = fmaf(hs[j+2], key_w[(j+2)*Mv + t], a2);
            a3 = fmaf(hs[j+3], key_w[(j+3)*Mv + t], a3);
        }
        ksh[t] = clip01(a0+a1+a2+a3 + key_b[t]);
    } else if (t < 128) {
        const int m = t - 64;
        float a0=0,a1=0,a2=0,a3=0;
        for (int j = 0; j < Hh; j += 4) {
            a0 = fmaf(hs[j  ], erase_w[(j  )*Mv + m], a0);
            a1 = fmaf(hs[j+1], erase_w[(j+1)*Mv + m], a1);
            a2 = fmaf(hs[j+2], erase_w[(j+2)*Mv + m], a2);
            a3 = fmaf(hs[j+3], erase_w[(j+3)*Mv + m], a3);
        }
        g_ev[b*Mv + m] = clip01(a0+a1+a2+a3 + erase_b[m]);
    } else if (t < 192) {
        const int m = t - 128;
        float a0=0,a1=0,a2=0,a3=0;
        for (int j = 0; j < Hh; j += 4) {
            a0 = fmaf(hs[j  ], add_w[(j  )*Mv + m], a0);
            a1 = fmaf(hs[j+1], add_w[(j+1)*Mv + m], a1);
            a2 = fmaf(hs[j+2], add_w[(j+2)*Mv + m], a2);
            a3 = fmaf(hs[j+3], add_w[(j+3)*Mv + m], a3);
        }
        // relu then clip01 == clip01
        g_av[b*Mv + m] = clip01(a0+a1+a2+a3 + add_b[m]);
    } else if (t < 198) {
        const int d = t - 192;
        const float* w; int str, col;
        if      (d == 0) { w = beta_w;  str = 1; col = 0; }
        else if (d == 1) { w = gate_w;  str = 1; col = 0; }
        else if (d == 2) { w = gamma_w; str = 1; col = 0; }
        else             { w = shift_w; str = 3; col = d - 3; }
        float a0=0,a1=0;
        for (int j = 0; j < Hh; j += 2) {
            a0 = fmaf(hs[j  ], w[(j  )*str + col], a0);
            a1 = fmaf(hs[j+1], w[(j+1)*str + col], a1);
        }
        sdot[d] = a0 + a1;
    }
    __syncthreads();

    if (t < 32) {
        float v = ksh[t]*ksh[t] + ksh[t+32]*ksh[t+32];
        #pragma unroll
        for (int off = 16; off; off >>= 1) v += __shfl_xor_sync(0xffffffffu, v, off);
        if (t == 0) sinv = 1.f / (sqrtf(v) + 1e-8f);
    }
    __syncthreads();
    if (t < 64) g_kn[b*Mv + t] = ksh[t] * sinv;
    if (t == 0) {
        g_beta[b]  = fmaxf(sdot[0] + beta_b[0], 0.f);
        g_gate[b]  = clip01(sdot[1] + gate_b[0]);
        g_gamma[b] = 1.f + fmaxf(sdot[2] + gamma_b[0], 0.f);
        float x0 = sdot[3] + shift_b[0];
        float x1 = sdot[4] + shift_b[1];
        float x2 = sdot[5] + shift_b[2];
        float mx = fmaxf(x0, fmaxf(x1, x2));
        float e0 = expf(x0-mx), e1 = expf(x1-mx), e2 = expf(x2-mx);
        float is = 1.f / (e0+e1+e2);
        g_shift[b*3+0] = e0*is; g_shift[b*3+1] = e1*is; g_shift[b*3+2] = e2*is;
    }
}

// ------- kernel 2: E[b,n] = exp(beta[b] * (kn[b]·m[n]) / (||m[n]||+eps)) ---
// sim in [-1,1] (cosine) so exp without max-subtraction is numerically safe
// and mathematically identical to the reference softmax.
__global__ void sim_kernel(const float* __restrict__ mem,
                           const int* __restrict__ bank, int use_m1)
{
    const float* __restrict__ src = use_m1 ? g_m1
                                           : (mem + (size_t)bank[0]*NNv*Mv);
    __shared__ float knT[64*68];   // [k][b], padded
    __shared__ float mt [64*68];   // [k][n], n-tile=64, padded
    __shared__ float invn[64];
    __shared__ float sbeta[64];
    const int t = threadIdx.x;
    const int n0 = blockIdx.x * 64;

    for (int i = t; i < 64*64; i += 256) {
        int bb = i >> 6, mm = i & 63;
        knT[mm*68 + bb] = g_kn[i];
    }
    for (int i = t; i < 64*64; i += 256) {
        int rr = i >> 6, cc = i & 63;
        mt[cc*68 + rr] = src[(size_t)(n0 + rr)*Mv + cc];
    }
    if (t < 64) sbeta[t] = g_beta[t];
    __syncthreads();
    if (t < 64) {
        float s = 0.f;
        #pragma unroll 16
        for (int k = 0; k < 64; k++) { float v = mt[k*68 + t]; s = fmaf(v, v, s); }
        invn[t] = 1.f / (sqrtf(s) + 1e-8f);
    }
    __syncthreads();

    const int by = t >> 5, nx = t & 31;   // 8 b's per thread, 2 n's per thread
    float c[8][2];
    #pragma unroll
    for (int i = 0; i < 8; i++) { c[i][0] = 0.f; c[i][1] = 0.f; }

    #pragma unroll 16
    for (int k = 0; k < 64; k++) {
        const float4 A0 = *(const float4*)&knT[k*68 + 8*by];
        const float4 A1 = *(const float4*)&knT[k*68 + 8*by + 4];
        const float2 Bv = *(const float2*)&mt [k*68 + 2*nx];
        float a[8] = {A0.x, A0.y, A0.z, A0.w, A1.x, A1.y, A1.z, A1.w};
        #pragma unroll
        for (int bi = 0; bi < 8; bi++) {
            c[bi][0] = fmaf(a[bi], Bv.x, c[bi][0]);
            c[bi][1] = fmaf(a[bi], Bv.y, c[bi][1]);
        }
    }

    const float2 iv = *(const float2*)&invn[2*nx];
    float psum[8];
    #pragma unroll
    for (int bi = 0; bi < 8; bi++) {
        const int bb = 8*by + bi;
        const float bt = sbeta[bb];
        float e0 = __expf(bt * c[bi][0] * iv.x);
        float e1 = __expf(bt * c[bi][1] * iv.y);
        *(float2*)&g_E[(size_t)bb*NNv + n0 + 2*nx] = make_float2(e0, e1);
        psum[bi] = e0 + e1;
    }
    #pragma unroll
    for (int bi = 0; bi < 8; bi++)
        #pragma unroll
        for (int off = 16; off; off >>= 1)
            psum[bi] += __shfl_xor_sync(0xffffffffu, psum[bi], off);
    if (nx == 0) {
        #pragma unroll
        for (int bi = 0; bi < 8; bi++)
            g_psum[(size_t)(8*by + bi)*SIMBLK + blockIdx.x] = psum[bi];
    }
}

// ---------------- deterministic reductions ---------------------------------
__global__ void reduce_sumexp_kernel()
{
    const int b = blockIdx.x, t = threadIdx.x;
    float s = 0.f;
    for (int i = t; i < SIMBLK; i += 256) s += g_psum[(size_t)b*SIMBLK + i];
    __shared__ float red[256];
    red[t] = s; __syncthreads();
    for (int off = 128; off; off >>= 1) { if (t < off) red[t] += red[t+off]; __syncthreads(); }
    if (t == 0) g_sumexp[b] = red[0];
}

__global__ void reduce_total_kernel(int out_off)
{
    const int seg = blockIdx.x, t = threadIdx.x;
    float s = 0.f;
    for (int i = t; i < Bz*CSPBLK; i += 256) s += g_tpart[seg*(Bz*CSPBLK) + i];
    __shared__ float red[256];
    red[t] = s; __syncthreads();
    for (int off = 128; off; off >>= 1) { if (t < off) red[t] += red[t+off]; __syncthreads(); }
    if (t == 0) g_totals[out_off + seg] = red[0];
}

// ----- kernel 3: w_c normalize + gate + 3-tap shift + fast pow + psum ------
__global__ void csp_kernel(const float* __restrict__ wprev_base, int is_read)
{
    const int r  = blockIdx.z;
    const int b  = blockIdx.y;
    const int c0 = blockIdx.x * 1024;
    const size_t head_off = ((size_t)(is_read ? r*Bz : 0) + b) * NNv;
    const float* __restrict__ wp = wprev_base + head_off;
    float* __restrict__ wo = (is_read ? g_wpow_r : g_wpow_w) + head_off;
    const float* __restrict__ Eb = g_E + (size_t)b*NNv;

    __shared__ float wg[1026];
    __shared__ float red[256];
    const float gg   = g_gate[b];
    const float invS = 1.f / g_sumexp[b];
    const float s0 = g_shift[b*3+0], s1 = g_shift[b*3+1], s2 = g_shift[b*3+2];
    const float gm = g_gamma[b];
    const int t = threadIdx.x;

    for (int i = t; i < 1026; i += 256) {
        const int n = c0 + i - 1;
        float v = 0.f;
        if (n >= 0 && n < NNv)
            v = gg * Eb[n] * invS + (1.f - gg) * wp[n];
        wg[i] = v;
    }
    __syncthreads();

    float ls = 0.f;
    #pragma unroll
    for (int j = 0; j < 4; j++) {
        const int i = t + j*256;
        const float wt = fmaf(s0, wg[i], fmaf(s1, wg[i+1], s2*wg[i+2]));
        const float pw = fpow(wt, gm);
        wo[c0 + i] = pw;
        ls += pw;
    }
    red[t] = ls; __syncthreads();
    for (int off = 128; off; off >>= 1) { if (t < off) red[t] += red[t+off]; __syncthreads(); }
    if (t == 0)
        g_tpart[(is_read ? r : 0)*(Bz*CSPBLK) + b*CSPBLK + blockIdx.x] = red[0];
}

// --- kernel 4: m1 = m0*(1 - W^T e) + W^T a   (W = wpow_w * inv_total) ------
__global__ void memupdate_kernel(const float* __restrict__ mem,
                                 const int* __restrict__ bank)
{
    const float* __restrict__ m0 = mem + (size_t)bank[0]*NNv*Mv;
    __shared__ float wsh[64*64];   // [k=b][n-local]
    __shared__ float es [64*64];   // [b][m] pre-scaled by inv_total
    __shared__ float as_[64*64];
    const int t = threadIdx.x;
    const int n0 = blockIdx.x * 64;
    const float inv = 1.f / (g_totals[0] + 1e-5f);

    for (int i = t; i < 64*64; i += 256) {
        int bb = i >> 6, nl = i & 63;
        wsh[i] = g_wpow_w[(size_t)bb*NNv + n0 + nl];
    }
    for (int i = t; i < 64*64; i += 256) { es[i] = g_ev[i]*inv; as_[i] = g_av[i]*inv; }
    __syncthreads();

    const int tn = t >> 4, tm = t & 15;   // 4 n x 4 m per thread
    float ce[4][4], ca[4][4];
    #pragma unroll
    for (int i = 0; i < 4; i++)
        #pragma unroll
        for (int j = 0; j < 4; j++) { ce[i][j] = 0.f; ca[i][j] = 0.f; }

    #pragma unroll 16
    for (int k = 0; k < 64; k++) {
        const float4 A  = *(const float4*)&wsh[k*64 + 4*tn];
        const float4 E4 = *(const float4*)&es [k*64 + 4*tm];
        const float4 A4 = *(const float4*)&as_[k*64 + 4*tm];
        float av[4] = {A.x, A.y, A.z, A.w};
        float ev[4] = {E4.x, E4.y, E4.z, E4.w};
        float aa[4] = {A4.x, A4.y, A4.z, A4.w};
        #pragma unroll
        for (int i = 0; i < 4; i++)
            #pragma unroll
            for (int j = 0; j < 4; j++) {
                ce[i][j] = fmaf(av[i], ev[j], ce[i][j]);
                ca[i][j] = fmaf(av[i], aa[j], ca[i][j]);
            }
    }

    #pragma unroll
    for (int i = 0; i < 4; i++) {
        const size_t n = (size_t)(n0 + 4*tn + i);
        const float4 o = *(const float4*)&m0[n*Mv + 4*tm];
        float4 v;
        v.x = o.x*(1.f - ce[i][0]) + ca[i][0];
        v.y = o.y*(1.f - ce[i][1]) + ca[i][1];
        v.z = o.z*(1.f - ce[i][2]) + ca[i][2];
        v.w = o.w*(1.f - ce[i][3]) + ca[i][3];
        *(float4*)&g_m1[n*Mv + 4*tm] = v;
    }
}

// ----- kernel 5: split-K read einsum partials (FFMA2 inner loop) -----------
// dynamic smem: ashT[64*68] (w_pow transposed [k][b]) | bshD[64*128] (m1 dup'd)
__global__ void einsum_kernel()
{
    extern __shared__ float sm[];
    float* ashT = sm;            // [k][b], padded, b contiguous -> natural pairs
    float* bshD = sm + 64*68;    // [k][2m] duplicated for FFMA2 broadcast
    const int chunk = blockIdx.x, r = blockIdx.y;
    const int n0 = chunk * EK;
    const int t = threadIdx.x;
    const int tb = t >> 4, tm = t & 15;  // 4 b (2 pairs) x 4 m per thread
    ull acc[2][4];
    #pragma unroll
    for (int p = 0; p < 2; p++)
        #pragma unroll
        for (int j = 0; j < 4; j++) acc[p][j] = 0ull;

    for (int sub = 0; sub < EK/64; sub++) {
        const int nb = n0 + sub*64;
        for (int i = t; i < 64*64; i += 256) {
            int bb = i >> 6, kk = i & 63;
            ashT[kk*68 + bb] = g_wpow_r[((size_t)r*Bz + bb)*NNv + nb + kk];
        }
        for (int i = t; i < 64*64; i += 256) {
            int kk = i >> 6, mm = i & 63;
            const float v = g_m1[(size_t)(nb + kk)*Mv + mm];
            *(float2*)&bshD[kk*128 + 2*mm] = make_float2(v, v);
        }
        __syncthreads();
        #pragma unroll 8
        for (int k = 0; k < 64; k++) {
            const ulonglong2 A  = *(const ulonglong2*)&ashT[k*68  + 4*tb];
            const ulonglong2 B0 = *(const ulonglong2*)&bshD[k*128 + 8*tm];
            const ulonglong2 B1 = *(const ulonglong2*)&bshD[k*128 + 8*tm + 4];
            acc[0][0]=ffma2(A.x,B0.x,acc[0][0]); acc[0][1]=ffma2(A.x,B0.y,acc[0][1]);
            acc[0][2]=ffma2(A.x,B1.x,acc[0][2]); acc[0][3]=ffma2(A.x,B1.y,acc[0][3]);
            acc[1][0]=ffma2(A.y,B0.x,acc[1][0]); acc[1][1]=ffma2(A.y,B0.y,acc[1][1]);
            acc[1][2]=ffma2(A.y,B1.x,acc[1][2]); acc[1][3]=ffma2(A.y,B1.y,acc[1][3]);
        }
        __syncthreads();
    }

    const size_t base = ((size_t)r*ECHUNK + chunk) * (Bz*Mv);
    #pragma unroll
    for (int p = 0; p < 2; p++) {
        float lo[4], hi[4];
        #pragma unroll
        for (int j = 0; j < 4; j++) unpack2(acc[p][j], lo[j], hi[j]);
        *(float4*)&g_epart[base + (size_t)(4*tb + 2*p    )*Mv + 4*tm]
            = make_float4(lo[0], lo[1], lo[2], lo[3]);
        *(float4*)&g_epart[base + (size_t)(4*tb + 2*p + 1)*Mv + 4*tm]
            = make_float4(hi[0], hi[1], hi[2], hi[3]);
    }
}

// ----- kernel 6: reduce split-K + apply 1/(total_r+eps) + transpose --------
__global__ void reduce_out_kernel(float* __restrict__ out)
{
    const int gid = blockIdx.x*256 + threadIdx.x;   // 0..R*B*M-1
    const int r = gid >> 12;
    const int b = (gid >> 6) & 63;
    const int m = gid & 63;
    const float inv = 1.f / (g_totals[1 + r] + 1e-5f);
    float s = 0.f;
    for (int c = 0; c < ECHUNK; c++)
        s += g_epart[(((size_t)r*ECHUNK + c)*Bz + b)*Mv + m];
    out[(size_t)b*(Rv*Mv) + r*Mv + m] = s * inv;
}

// ---------------------------------------------------------------------------
extern "C" void kernel_launch(void* const* d_in, const int* in_sizes, int n_in,
                              void* d_out, int out_size)
{
    const float* h_t     = (const float*)d_in[0];
    const float* ww      = (const float*)d_in[1];
    const float* wr      = (const float*)d_in[2];
    const float* memory  = (const float*)d_in[3];
    const float* key_w   = (const float*)d_in[4];
    const float* key_b   = (const float*)d_in[5];
    const float* beta_w  = (const float*)d_in[6];
    const float* beta_b  = (const float*)d_in[7];
    const float* gate_w  = (const float*)d_in[8];
    const float* gate_b  = (const float*)d_in[9];
    const float* shift_w = (const float*)d_in[10];
    const float* shift_b = (const float*)d_in[11];
    const float* gamma_w = (const float*)d_in[12];
    const float* gamma_b = (const float*)d_in[13];
    const float* erase_w = (const float*)d_in[14];
    const float* erase_b = (const float*)d_in[15];
    const float* add_w   = (const float*)d_in[16];
    const float* add_b   = (const float*)d_in[17];
    const int*   bank    = (const int*)d_in[18];
    float* out = (float*)d_out;

    const int EINSUM_SMEM = (64*68 + 64*128) * 4;   // 50176 B
    cudaFuncSetAttribute(einsum_kernel,
        cudaFuncAttributeMaxDynamicSharedMemorySize, EINSUM_SMEM);

    // head params (shared by all 5 weight updates)
    heads_kernel<<<Bz, 256>>>(h_t, key_w, key_b, beta_w, beta_b, gate_w, gate_b,
                              shift_w, shift_b, gamma_w, gamma_b,
                              erase_w, erase_b, add_w, add_b);

    // --- write head: content addressing on m0 ---
    sim_kernel<<<SIMBLK, 256>>>(memory, bank, 0);
    reduce_sumexp_kernel<<<Bz, 256>>>();
    csp_kernel<<<dim3(CSPBLK, Bz, 1), 256>>>(ww, 0);
    reduce_total_kernel<<<1, 256>>>(0);

    // --- memory erase/add ---
    memupdate_kernel<<<NNv/64, 256>>>(memory, bank);

    // --- read heads: shared content addressing on m1 ---
    sim_kernel<<<SIMBLK, 256>>>(memory, bank, 1);
    reduce_sumexp_kernel<<<Bz, 256>>>();
    csp_kernel<<<dim3(CSPBLK, Bz, Rv), 256>>>(wr, 1);
    reduce_total_kernel<<<Rv, 256>>>(1);

    // --- read: r[r,b,:] = (wpow_r[r,b,:]/total_r) @ m1 ---
    einsum_kernel<<<dim3(ECHUNK, Rv), 256, EINSUM_SMEM>>>();
    reduce_out_kernel<<<(Rv*Bz*Mv)/256, 256>>>(out);
}

// round 7
// speedup vs baseline: 1.1044x; 1.0095x over previous
#include <cuda_runtime.h>
#include <math.h>

typedef unsigned long long ull;

#define Bz 64
#define Hh 1024
#define NNv 65536
#define Mv 64
#define Rv 4
#define SIMBLK (NNv/64)   /* 1024 sim blocks */
#define CSPBLK 64         /* N/1024 csp blocks per b */
#define ECHUNK 128        /* einsum split-K chunks */
#define EK (NNv/ECHUNK)   /* 512 n per chunk */

// ---------------- scratch (device globals: no allocation allowed) ----------
__device__ float g_E[(size_t)Bz*NNv];            // exp(beta*sim) buffer [B,N]
__device__ float g_wpow_w[(size_t)Bz*NNv];       // write-head w_pow
__device__ float g_wpow_r[(size_t)Rv*Bz*NNv];    // read-head w_pow [R,B,N]
__device__ float g_m1[(size_t)NNv*Mv];           // updated memory
__device__ float g_kn[Bz*Mv];
__device__ float g_ev[Bz*Mv];
__device__ float g_av[Bz*Mv];
__device__ float g_beta[Bz];
__device__ float g_gate[Bz];
__device__ float g_gamma[Bz];
__device__ float g_shift[Bz*3];
__device__ float g_psum[(size_t)Bz*SIMBLK];      // per-block exp partial sums
__device__ float g_sumexp[Bz];
__device__ float g_tpart[Rv*Bz*CSPBLK];          // per-block pow partial sums
__device__ float g_totals[1+Rv];                 // [0]=write total, [1..4]=read totals
__device__ float g_epart[(size_t)Rv*ECHUNK*Bz*Mv]; // einsum split-K partials

__device__ __forceinline__ float clip01(float x){ return fminf(fmaxf(x, 0.f), 1.f); }
// fast x^g for x > 0 (w_tilde is strictly positive: softmax inputs, s_j > 0)
__device__ __forceinline__ float fpow(float x, float g){ return __expf(g * __logf(x)); }

__device__ __forceinline__ ull ffma2(ull a, ull b, ull c){
    ull d;
    asm("fma.rn.f32x2 %0, %1, %2, %3;" : "=l"(d) : "l"(a), "l"(b), "l"(c));
    return d;
}
__device__ __forceinline__ void unpack2(ull v, float& lo, float& hi){
    asm("mov.b64 {%0, %1}, %2;" : "=f"(lo), "=f"(hi) : "l"(v));
}

// ---------------- kernel 1: head projections (once per step) ---------------
__global__ void heads_kernel(const float* __restrict__ h,
    const float* __restrict__ key_w,   const float* __restrict__ key_b,
    const float* __restrict__ beta_w,  const float* __restrict__ beta_b,
    const float* __restrict__ gate_w,  const float* __restrict__ gate_b,
    const float* __restrict__ shift_w, const float* __restrict__ shift_b,
    const float* __restrict__ gamma_w, const float* __restrict__ gamma_b,
    const float* __restrict__ erase_w, const float* __restrict__ erase_b,
    const float* __restrict__ add_w,   const float* __restrict__ add_b)
{
    __shared__ float hs[Hh];
    __shared__ float ksh[Mv];
    __shared__ float sdot[6];
    __shared__ float sinv;
    const int b = blockIdx.x, t = threadIdx.x;
    for (int i = t; i < Hh; i += 256) hs[i] = h[(size_t)b*Hh + i];
    __syncthreads();

    if (t < 64) {
        float a0=0,a1=0,a2=0,a3=0;
        for (int j = 0; j < Hh; j += 4) {
            a0 = fmaf(hs[j  ], key_w[(j  )*Mv + t], a0);
            a1 = fmaf(hs[j+1], key_w[(j+1)*Mv + t], a1);
            a2 = fmaf(hs[j+2], key_w[(j+2)*Mv + t], a2);
            a3 = fmaf(hs[j+3], key_w[(j+3)*Mv + t], a3);
        }
        ksh[t] = clip01(a0+a1+a2+a3 + key_b[t]);
    } else if (t < 128) {
        const int m = t - 64;
        float a0=0,a1=0,a2=0,a3=0;
        for (int j = 0; j < Hh; j += 4) {
            a0 = fmaf(hs[j  ], erase_w[(j  )*Mv + m], a0);
            a1 = fmaf(hs[j+1], erase_w[(j+1)*Mv + m], a1);
            a2 = fmaf(hs[j+2], erase_w[(j+2)*Mv + m], a2);
            a3 = fmaf(hs[j+3], erase_w[(j+3)*Mv + m], a3);
        }
        g_ev[b*Mv + m] = clip01(a0+a1+a2+a3 + erase_b[m]);
    } else if (t < 192) {
        const int m = t - 128;
        float a0=0,a1=0,a2=0,a3=0;
        for (int j = 0; j < Hh; j += 4) {
            a0 = fmaf(hs[j  ], add_w[(j  )*Mv + m], a0);
            a1 = fmaf(hs[j+1], add_w[(j+1)*Mv + m], a1);
            a2 = fmaf(hs[j+2], add_w[(j+2)*Mv + m], a2);
            a3 = fmaf(hs[j+3], add_w[(j+3)*Mv + m], a3);
        }
        // relu then clip01 == clip01
        g_av[b*Mv + m] = clip01(a0+a1+a2+a3 + add_b[m]);
    } else if (t < 198) {
        const int d = t - 192;
        const float* w; int str, col;
        if      (d == 0) { w = beta_w;  str = 1; col = 0; }
        else if (d == 1) { w = gate_w;  str = 1; col = 0; }
        else if (d == 2) { w = gamma_w; str = 1; col = 0; }
        else             { w = shift_w; str = 3; col = d - 3; }
        float a0=0,a1=0;
        for (int j = 0; j < Hh; j += 2) {
            a0 = fmaf(hs[j  ], w[(j  )*str + col], a0);
            a1 = fmaf(hs[j+1], w[(j+1)*str + col], a1);
        }
        sdot[d] = a0 + a1;
    }
    __syncthreads();

    if (t < 32) {
        float v = ksh[t]*ksh[t] + ksh[t+32]*ksh[t+32];
        #pragma unroll
        for (int off = 16; off; off >>= 1) v += __shfl_xor_sync(0xffffffffu, v, off);
        if (t == 0) sinv = 1.f / (sqrtf(v) + 1e-8f);
    }
    __syncthreads();
    if (t < 64) g_kn[b*Mv + t] = ksh[t] * sinv;
    if (t == 0) {
        g_beta[b]  = fmaxf(sdot[0] + beta_b[0], 0.f);
        g_gate[b]  = clip01(sdot[1] + gate_b[0]);
        g_gamma[b] = 1.f + fmaxf(sdot[2] + gamma_b[0], 0.f);
        float x0 = sdot[3] + shift_b[0];
        float x1 = sdot[4] + shift_b[1];
        float x2 = sdot[5] + shift_b[2];
        float mx = fmaxf(x0, fmaxf(x1, x2));
        float e0 = expf(x0-mx), e1 = expf(x1-mx), e2 = expf(x2-mx);
        float is = 1.f / (e0+e1+e2);
        g_shift[b*3+0] = e0*is; g_shift[b*3+1] = e1*is; g_shift[b*3+2] = e2*is;
    }
}

// ------- kernel 2: E[b,n] = exp(beta[b] * (kn[b]·m[n]) / (||m[n]||+eps)) ---
// sim in [-1,1] (cosine) so exp without max-subtraction is numerically safe
// and mathematically identical to the reference softmax.
__global__ void sim_kernel(const float* __restrict__ mem,
                           const int* __restrict__ bank, int use_m1)
{
    const float* __restrict__ src = use_m1 ? g_m1
                                           : (mem + (size_t)bank[0]*NNv*Mv);
    __shared__ float knT[64*68];   // [k][b], padded
    __shared__ float mt [64*68];   // [k][n], n-tile=64, padded
    __shared__ float invn[64];
    __shared__ float sbeta[64];
    const int t = threadIdx.x;
    const int n0 = blockIdx.x * 64;

    for (int i = t; i < 64*64; i += 256) {
        int bb = i >> 6, mm = i & 63;
        knT[mm*68 + bb] = g_kn[i];
    }
    for (int i = t; i < 64*64; i += 256) {
        int rr = i >> 6, cc = i & 63;
        mt[cc*68 + rr] = src[(size_t)(n0 + rr)*Mv + cc];
    }
    if (t < 64) sbeta[t] = g_beta[t];
    __syncthreads();
    if (t < 64) {
        float s = 0.f;
        #pragma unroll 16
        for (int k = 0; k < 64; k++) { float v = mt[k*68 + t]; s = fmaf(v, v, s); }
        invn[t] = 1.f / (sqrtf(s) + 1e-8f);
    }
    __syncthreads();

    const int by = t >> 5, nx = t & 31;   // 8 b's per thread, 2 n's per thread
    float c[8][2];
    #pragma unroll
    for (int i = 0; i < 8; i++) { c[i][0] = 0.f; c[i][1] = 0.f; }

    #pragma unroll 16
    for (int k = 0; k < 64; k++) {
        const float4 A0 = *(const float4*)&knT[k*68 + 8*by];
        const float4 A1 = *(const float4*)&knT[k*68 + 8*by + 4];
        const float2 Bv = *(const float2*)&mt [k*68 + 2*nx];
        float a[8] = {A0.x, A0.y, A0.z, A0.w, A1.x, A1.y, A1.z, A1.w};
        #pragma unroll
        for (int bi = 0; bi < 8; bi++) {
            c[bi][0] = fmaf(a[bi], Bv.x, c[bi][0]);
            c[bi][1] = fmaf(a[bi], Bv.y, c[bi][1]);
        }
    }

    const float2 iv = *(const float2*)&invn[2*nx];
    float psum[8];
    #pragma unroll
    for (int bi = 0; bi < 8; bi++) {
        const int bb = 8*by + bi;
        const float bt = sbeta[bb];
        float e0 = __expf(bt * c[bi][0] * iv.x);
        float e1 = __expf(bt * c[bi][1] * iv.y);
        *(float2*)&g_E[(size_t)bb*NNv + n0 + 2*nx] = make_float2(e0, e1);
        psum[bi] = e0 + e1;
    }
    #pragma unroll
    for (int bi = 0; bi < 8; bi++)
        #pragma unroll
        for (int off = 16; off; off >>= 1)
            psum[bi] += __shfl_xor_sync(0xffffffffu, psum[bi], off);
    if (nx == 0) {
        #pragma unroll
        for (int bi = 0; bi < 8; bi++)
            g_psum[(size_t)(8*by + bi)*SIMBLK + blockIdx.x] = psum[bi];
    }
}

// ---------------- deterministic reductions ---------------------------------
__global__ void reduce_sumexp_kernel()
{
    const int b = blockIdx.x, t = threadIdx.x;
    float s = 0.f;
    for (int i = t; i < SIMBLK; i += 256) s += g_psum[(size_t)b*SIMBLK + i];
    __shared__ float red[256];
    red[t] = s; __syncthreads();
    for (int off = 128; off; off >>= 1) { if (t < off) red[t] += red[t+off]; __syncthreads(); }
    if (t == 0) g_sumexp[b] = red[0];
}

__global__ void reduce_total_kernel(int out_off)
{
    const int seg = blockIdx.x, t = threadIdx.x;
    float s = 0.f;
    for (int i = t; i < Bz*CSPBLK; i += 256) s += g_tpart[seg*(Bz*CSPBLK) + i];
    __shared__ float red[256];
    red[t] = s; __syncthreads();
    for (int off = 128; off; off >>= 1) { if (t < off) red[t] += red[t+off]; __syncthreads(); }
    if (t == 0) g_totals[out_off + seg] = red[0];
}

// ----- kernel 3: w_c normalize + gate + 3-tap shift + fast pow + psum ------
__global__ void csp_kernel(const float* __restrict__ wprev_base, int is_read)
{
    const int r  = blockIdx.z;
    const int b  = blockIdx.y;
    const int c0 = blockIdx.x * 1024;
    const size_t head_off = ((size_t)(is_read ? r*Bz : 0) + b) * NNv;
    const float* __restrict__ wp = wprev_base + head_off;
    float* __restrict__ wo = (is_read ? g_wpow_r : g_wpow_w) + head_off;
    const float* __restrict__ Eb = g_E + (size_t)b*NNv;

    __shared__ float wg[1026];
    __shared__ float red[256];
    const float gg   = g_gate[b];
    const float invS = 1.f / g_sumexp[b];
    const float s0 = g_shift[b*3+0], s1 = g_shift[b*3+1], s2 = g_shift[b*3+2];
    const float gm = g_gamma[b];
    const int t = threadIdx.x;

    for (int i = t; i < 1026; i += 256) {
        const int n = c0 + i - 1;
        float v = 0.f;
        if (n >= 0 && n < NNv)
            v = gg * Eb[n] * invS + (1.f - gg) * wp[n];
        wg[i] = v;
    }
    __syncthreads();

    float ls = 0.f;
    #pragma unroll
    for (int j = 0; j < 4; j++) {
        const int i = t + j*256;
        const float wt = fmaf(s0, wg[i], fmaf(s1, wg[i+1], s2*wg[i+2]));
        const float pw = fpow(wt, gm);
        wo[c0 + i] = pw;
        ls += pw;
    }
    red[t] = ls; __syncthreads();
    for (int off = 128; off; off >>= 1) { if (t < off) red[t] += red[t+off]; __syncthreads(); }
    if (t == 0)
        g_tpart[(is_read ? r : 0)*(Bz*CSPBLK) + b*CSPBLK + blockIdx.x] = red[0];
}

// --- kernel 4: m1 = m0*(1 - W^T e) + W^T a   (W = wpow_w * inv_total) ------
__global__ void memupdate_kernel(const float* __restrict__ mem,
                                 const int* __restrict__ bank)
{
    const float* __restrict__ m0 = mem + (size_t)bank[0]*NNv*Mv;
    __shared__ float wsh[64*64];   // [k=b][n-local]
    __shared__ float es [64*64];   // [b][m] pre-scaled by inv_total
    __shared__ float as_[64*64];
    const int t = threadIdx.x;
    const int n0 = blockIdx.x * 64;
    const float inv = 1.f / (g_totals[0] + 1e-5f);

    for (int i = t; i < 64*64; i += 256) {
        int bb = i >> 6, nl = i & 63;
        wsh[i] = g_wpow_w[(size_t)bb*NNv + n0 + nl];
    }
    for (int i = t; i < 64*64; i += 256) { es[i] = g_ev[i]*inv; as_[i] = g_av[i]*inv; }
    __syncthreads();

    const int tn = t >> 4, tm = t & 15;   // 4 n x 4 m per thread
    float ce[4][4], ca[4][4];
    #pragma unroll
    for (int i = 0; i < 4; i++)
        #pragma unroll
        for (int j = 0; j < 4; j++) { ce[i][j] = 0.f; ca[i][j] = 0.f; }

    #pragma unroll 16
    for (int k = 0; k < 64; k++) {
        const float4 A  = *(const float4*)&wsh[k*64 + 4*tn];
        const float4 E4 = *(const float4*)&es [k*64 + 4*tm];
        const float4 A4 = *(const float4*)&as_[k*64 + 4*tm];
        float av[4] = {A.x, A.y, A.z, A.w};
        float ev[4] = {E4.x, E4.y, E4.z, E4.w};
        float aa[4] = {A4.x, A4.y, A4.z, A4.w};
        #pragma unroll
        for (int i = 0; i < 4; i++)
            #pragma unroll
            for (int j = 0; j < 4; j++) {
                ce[i][j] = fmaf(av[i], ev[j], ce[i][j]);
                ca[i][j] = fmaf(av[i], aa[j], ca[i][j]);
            }
    }

    #pragma unroll
    for (int i = 0; i < 4; i++) {
        const size_t n = (size_t)(n0 + 4*tn + i);
        const float4 o = *(const float4*)&m0[n*Mv + 4*tm];
        float4 v;
        v.x = o.x*(1.f - ce[i][0]) + ca[i][0];
        v.y = o.y*(1.f - ce[i][1]) + ca[i][1];
        v.z = o.z*(1.f - ce[i][2]) + ca[i][2];
        v.w = o.w*(1.f - ce[i][3]) + ca[i][3];
        *(float4*)&g_m1[n*Mv + 4*tm] = v;
    }
}

// ----- kernel 5: split-K read einsum partials (FFMA2 inner loop) -----------
// dynamic smem: ashT[64*68] (w_pow transposed [k][b]) | bshD[64*128] (m1 dup'd)
__global__ void einsum_kernel()
{
    extern __shared__ float sm[];
    float* ashT = sm;            // [k][b], padded, b contiguous -> natural pairs
    float* bshD = sm + 64*68;    // [k][2m] duplicated for FFMA2 broadcast
    const int chunk = blockIdx.x, r = blockIdx.y;
    const int n0 = chunk * EK;
    const int t = threadIdx.x;
    const int tb = t >> 4, tm = t & 15;  // 4 b (2 pairs) x 4 m per thread
    ull acc[2][4];
    #pragma unroll
    for (int p = 0; p < 2; p++)
        #pragma unroll
        for (int j = 0; j < 4; j++) acc[p][j] = 0ull;

    for (int sub = 0; sub < EK/64; sub++) {
        const int nb = n0 + sub*64;
        for (int i = t; i < 64*64; i += 256) {
            int bb = i >> 6, kk = i & 63;
            ashT[kk*68 + bb] = g_wpow_r[((size_t)r*Bz + bb)*NNv + nb + kk];
        }
        for (int i = t; i < 64*64; i += 256) {
            int kk = i >> 6, mm = i & 63;
            const float v = g_m1[(size_t)(nb + kk)*Mv + mm];
            *(float2*)&bshD[kk*128 + 2*mm] = make_float2(v, v);
        }
        __syncthreads();
        #pragma unroll 8
        for (int k = 0; k < 64; k++) {
            const ulonglong2 A  = *(const ulonglong2*)&ashT[k*68  + 4*tb];
            const ulonglong2 B0 = *(const ulonglong2*)&bshD[k*128 + 8*tm];
            const ulonglong2 B1 = *(const ulonglong2*)&bshD[k*128 + 8*tm + 4];
            acc[0][0]=ffma2(A.x,B0.x,acc[0][0]); acc[0][1]=ffma2(A.x,B0.y,acc[0][1]);
            acc[0][2]=ffma2(A.x,B1.x,acc[0][2]); acc[0][3]=ffma2(A.x,B1.y,acc[0][3]);
            acc[1][0]=ffma2(A.y,B0.x,acc[1][0]); acc[1][1]=ffma2(A.y,B0.y,acc[1][1]);
            acc[1][2]=ffma2(A.y,B1.x,acc[1][2]); acc[1][3]=ffma2(A.y,B1.y,acc[1][3]);
        }
        __syncthreads();
    }

    const size_t base = ((size_t)r*ECHUNK + chunk) * (Bz*Mv);
    #pragma unroll
    for (int p = 0; p < 2; p++) {
        float lo[4], hi[4];
        #pragma unroll
        for (int j = 0; j < 4; j++) unpack2(acc[p][j], lo[j], hi[j]);
        *(float4*)&g_epart[base + (size_t)(4*tb + 2*p    )*Mv + 4*tm]
            = make_float4(lo[0], lo[1], lo[2], lo[3]);
        *(float4*)&g_epart[base + (size_t)(4*tb + 2*p + 1)*Mv + 4*tm]
            = make_float4(hi[0], hi[1], hi[2], hi[3]);
    }
}

// ----- kernel 6: reduce split-K + apply 1/(total_r+eps) + transpose --------
__global__ void reduce_out_kernel(float* __restrict__ out)
{
    const int gid = blockIdx.x*256 + threadIdx.x;   // 0..R*B*M-1
    const int r = gid >> 12;
    const int b = (gid >> 6) & 63;
    const int m = gid & 63;
    const float inv = 1.f / (g_totals[1 + r] + 1e-5f);
    float s = 0.f;
    for (int c = 0; c < ECHUNK; c++)
        s += g_epart[(((size_t)r*ECHUNK + c)*Bz + b)*Mv + m];
    out[(size_t)b*(Rv*Mv) + r*Mv + m] = s * inv;
}

// ---------------------------------------------------------------------------
extern "C" void kernel_launch(void* const* d_in, const int* in_sizes, int n_in,
                              void* d_out, int out_size)
{
    const float* h_t     = (const float*)d_in[0];
    const float* ww      = (const float*)d_in[1];
    const float* wr      = (const float*)d_in[2];
    const float* memory  = (const float*)d_in[3];
    const float* key_w   = (const float*)d_in[4];
    const float* key_b   = (const float*)d_in[5];
    const float* beta_w  = (const float*)d_in[6];
    const float* beta_b  = (const float*)d_in[7];
    const float* gate_w  = (const float*)d_in[8];
    const float* gate_b  = (const float*)d_in[9];
    const float* shift_w = (const float*)d_in[10];
    const float* shift_b = (const float*)d_in[11];
    const float* gamma_w = (const float*)d_in[12];
    const float* gamma_b = (const float*)d_in[13];
    const float* erase_w = (const float*)d_in[14];
    const float* erase_b = (const float*)d_in[15];
    const float* add_w   = (const float*)d_in[16];
    const float* add_b   = (const float*)d_in[17];
    const int*   bank    = (const int*)d_in[18];
    float* out = (float*)d_out;

    const int EINSUM_SMEM = (64*68 + 64*128) * 4;   // 50176 B
    cudaFuncSetAttribute(einsum_kernel,
        cudaFuncAttributeMaxDynamicSharedMemorySize, EINSUM_SMEM);

    // head params (shared by all 5 weight updates)
    heads_kernel<<<Bz, 256>>>(h_t, key_w, key_b, beta_w, beta_b, gate_w, gate_b,
                              shift_w, shift_b, gamma_w, gamma_b,
                              erase_w, erase_b, add_w, add_b);

    // --- write head: content addressing on m0 ---
    sim_kernel<<<SIMBLK, 256>>>(memory, bank, 0);
    reduce_sumexp_kernel<<<Bz, 256>>>();
    csp_kernel<<<dim3(CSPBLK, Bz, 1), 256>>>(ww, 0);
    reduce_total_kernel<<<1, 256>>>(0);

    // --- memory erase/add ---
    memupdate_kernel<<<NNv/64, 256>>>(memory, bank);

    // --- read heads: shared content addressing on m1 ---
    sim_kernel<<<SIMBLK, 256>>>(memory, bank, 1);
    reduce_sumexp_kernel<<<Bz, 256>>>();
    csp_kernel<<<dim3(CSPBLK, Bz, Rv), 256>>>(wr, 1);
    reduce_total_kernel<<<Rv, 256>>>(1);

    // --- read: r[r,b,:] = (wpow_r[r,b,:]/total_r) @ m1 ---
    einsum_kernel<<<dim3(ECHUNK, Rv), 256, EINSUM_SMEM>>>();
    reduce_out_kernel<<<(Rv*Bz*Mv)/256, 256>>>(out);
}

// round 8
// speedup vs baseline: 1.3815x; 1.2509x over previous
#include <cuda_runtime.h>
#include <math.h>

#define Bz 64
#define Hh 1024
#define NNv 65536
#define Mv 64
#define Rv 4
#define SIMBLK (NNv/64)   /* 1024 sim blocks */
#define CSPBLK 64         /* N/1024 csp blocks per b */
#define ECHUNK 128        /* einsum split-K chunks */
#define EK (NNv/ECHUNK)   /* 512 n per chunk */

// ---------------- scratch (device globals: no allocation allowed) ----------
__device__ float g_E[(size_t)Bz*NNv];            // exp(beta*sim) buffer [B,N]
__device__ float g_wpow_w[(size_t)Bz*NNv];       // write-head w_pow
__device__ float g_wpow_r[(size_t)Rv*Bz*NNv];    // read-head w_pow [R,B,N]
__device__ float g_m1[(size_t)NNv*Mv];           // updated memory
__device__ float g_kn[Bz*Mv];
__device__ float g_ev[Bz*Mv];
__device__ float g_av[Bz*Mv];
__device__ float g_beta[Bz];
__device__ float g_gate[Bz];
__device__ float g_gamma[Bz];
__device__ float g_shift[Bz*3];
__device__ float g_psum[(size_t)Bz*SIMBLK];      // per-block exp partial sums
__device__ float g_sumexp[Bz];
__device__ float g_tpart[Rv*Bz*CSPBLK];          // per-block pow partial sums
__device__ float g_totals[1+Rv];                 // [0]=write total, [1..4]=read totals
__device__ float g_epart[(size_t)Rv*ECHUNK*Bz*Mv]; // einsum split-K partials

__device__ __forceinline__ float clip01(float x){ return fminf(fmaxf(x, 0.f), 1.f); }
// fast x^g for x > 0 (w_tilde strictly positive: gated softmax mix, s_j > 0)
__device__ __forceinline__ float fpow(float x, float g){ return __expf(g * __logf(x)); }

// ---------------- kernel 1: head projections (once per step) ---------------
__global__ void heads_kernel(const float* __restrict__ h,
    const float* __restrict__ key_w,   const float* __restrict__ key_b,
    const float* __restrict__ beta_w,  const float* __restrict__ beta_b,
    const float* __restrict__ gate_w,  const float* __restrict__ gate_b,
    const float* __restrict__ shift_w, const float* __restrict__ shift_b,
    const float* __restrict__ gamma_w, const float* __restrict__ gamma_b,
    const float* __restrict__ erase_w, const float* __restrict__ erase_b,
    const float* __restrict__ add_w,   const float* __restrict__ add_b)
{
    __shared__ float hs[Hh];
    __shared__ float ksh[Mv];
    __shared__ float sdot[6];
    __shared__ float sinv;
    const int b = blockIdx.x, t = threadIdx.x;
    for (int i = t; i < Hh; i += 256) hs[i] = h[(size_t)b*Hh + i];
    __syncthreads();

    if (t < 64) {
        float a0=0,a1=0,a2=0,a3=0;
        for (int j = 0; j < Hh; j += 4) {
            a0 = fmaf(hs[j  ], key_w[(j  )*Mv + t], a0);
            a1 = fmaf(hs[j+1], key_w[(j+1)*Mv + t], a1);
            a2 = fmaf(hs[j+2], key_w[(j+2)*Mv + t], a2);
            a3 = fmaf(hs[j+3], key_w[(j+3)*Mv + t], a3);
        }
        ksh[t] = clip01(a0+a1+a2+a3 + key_b[t]);
    } else if (t < 128) {
        const int m = t - 64;
        float a0=0,a1=0,a2=0,a3=0;
        for (int j = 0; j < Hh; j += 4) {
            a0 = fmaf(hs[j  ], erase_w[(j  )*Mv + m], a0);
            a1 = fmaf(hs[j+1], erase_w[(j+1)*Mv + m], a1);
            a2 = fmaf(hs[j+2], erase_w[(j+2)*Mv + m], a2);
            a3 = fmaf(hs[j+3], erase_w[(j+3)*Mv + m], a3);
        }
        g_ev[b*Mv + m] = clip01(a0+a1+a2+a3 + erase_b[m]);
    } else if (t < 192) {
        const int m = t - 128;
        float a0=0,a1=0,a2=0,a3=0;
        for (int j = 0; j < Hh; j += 4) {
            a0 = fmaf(hs[j  ], add_w[(j  )*Mv + m], a0);
            a1 = fmaf(hs[j+1], add_w[(j+1)*Mv + m], a1);
            a2 = fmaf(hs[j+2], add_w[(j+2)*Mv + m], a2);
            a3 = fmaf(hs[j+3], add_w[(j+3)*Mv + m], a3);
        }
        // relu then clip01 == clip01
        g_av[b*Mv + m] = clip01(a0+a1+a2+a3 + add_b[m]);
    } else if (t < 198) {
        const int d = t - 192;
        const float* w; int str, col;
        if      (d == 0) { w = beta_w;  str = 1; col = 0; }
        else if (d == 1) { w = gate_w;  str = 1; col = 0; }
        else if (d == 2) { w = gamma_w; str = 1; col = 0; }
        else             { w = shift_w; str = 3; col = d - 3; }
        float a0=0,a1=0;
        for (int j = 0; j < Hh; j += 2) {
            a0 = fmaf(hs[j  ], w[(j  )*str + col], a0);
            a1 = fmaf(hs[j+1], w[(j+1)*str + col], a1);
        }
        sdot[d] = a0 + a1;
    }
    __syncthreads();

    if (t < 32) {
        float v = ksh[t]*ksh[t] + ksh[t+32]*ksh[t+32];
        #pragma unroll
        for (int off = 16; off; off >>= 1) v += __shfl_xor_sync(0xffffffffu, v, off);
        if (t == 0) sinv = 1.f / (sqrtf(v) + 1e-8f);
    }
    __syncthreads();
    if (t < 64) g_kn[b*Mv + t] = ksh[t] * sinv;
    if (t == 0) {
        g_beta[b]  = fmaxf(sdot[0] + beta_b[0], 0.f);
        g_gate[b]  = clip01(sdot[1] + gate_b[0]);
        g_gamma[b] = 1.f + fmaxf(sdot[2] + gamma_b[0], 0.f);
        float x0 = sdot[3] + shift_b[0];
        float x1 = sdot[4] + shift_b[1];
        float x2 = sdot[5] + shift_b[2];
        float mx = fmaxf(x0, fmaxf(x1, x2));
        float e0 = expf(x0-mx), e1 = expf(x1-mx), e2 = expf(x2-mx);
        float is = 1.f / (e0+e1+e2);
        g_shift[b*3+0] = e0*is; g_shift[b*3+1] = e1*is; g_shift[b*3+2] = e2*is;
    }
}

// ------- kernel 2: E[b,n] = exp(beta[b] * (kn[b]·m[n]) / (||m[n]||+eps)) ---
// sim in [-1,1] (cosine) so exp without max-subtraction is numerically safe
// and mathematically identical to the reference softmax.
__global__ void sim_kernel(const float* __restrict__ mem,
                           const int* __restrict__ bank, int use_m1)
{
    const float* __restrict__ src = use_m1 ? g_m1
                                           : (mem + (size_t)bank[0]*NNv*Mv);
    __shared__ float knT[64*68];   // [k][b], padded
    __shared__ float mt [64*68];   // [k][n], n-tile=64, padded
    __shared__ float invn[64];
    __shared__ float sbeta[64];
    const int t = threadIdx.x;
    const int n0 = blockIdx.x * 64;

    for (int i = t; i < 64*64; i += 256) {
        int bb = i >> 6, mm = i & 63;
        knT[mm*68 + bb] = g_kn[i];
    }
    for (int i = t; i < 64*64; i += 256) {
        int rr = i >> 6, cc = i & 63;
        mt[cc*68 + rr] = src[(size_t)(n0 + rr)*Mv + cc];
    }
    if (t < 64) sbeta[t] = g_beta[t];
    __syncthreads();
    if (t < 64) {
        float s = 0.f;
        #pragma unroll 16
        for (int k = 0; k < 64; k++) { float v = mt[k*68 + t]; s = fmaf(v, v, s); }
        invn[t] = 1.f / (sqrtf(s) + 1e-8f);
    }
    __syncthreads();

    const int by = t >> 5, nx = t & 31;   // 8 b's per thread, 2 n's per thread
    float c[8][2];
    #pragma unroll
    for (int i = 0; i < 8; i++) { c[i][0] = 0.f; c[i][1] = 0.f; }

    #pragma unroll 16
    for (int k = 0; k < 64; k++) {
        const float4 A0 = *(const float4*)&knT[k*68 + 8*by];
        const float4 A1 = *(const float4*)&knT[k*68 + 8*by + 4];
        const float2 Bv = *(const float2*)&mt [k*68 + 2*nx];
        float a[8] = {A0.x, A0.y, A0.z, A0.w, A1.x, A1.y, A1.z, A1.w};
        #pragma unroll
        for (int bi = 0; bi < 8; bi++) {
            c[bi][0] = fmaf(a[bi], Bv.x, c[bi][0]);
            c[bi][1] = fmaf(a[bi], Bv.y, c[bi][1]);
        }
    }

    const float2 iv = *(const float2*)&invn[2*nx];
    float psum[8];
    #pragma unroll
    for (int bi = 0; bi < 8; bi++) {
        const int bb = 8*by + bi;
        const float bt = sbeta[bb];
        float e0 = __expf(bt * c[bi][0] * iv.x);
        float e1 = __expf(bt * c[bi][1] * iv.y);
        *(float2*)&g_E[(size_t)bb*NNv + n0 + 2*nx] = make_float2(e0, e1);
        psum[bi] = e0 + e1;
    }
    #pragma unroll
    for (int bi = 0; bi < 8; bi++)
        #pragma unroll
        for (int off = 16; off; off >>= 1)
            psum[bi] += __shfl_xor_sync(0xffffffffu, psum[bi], off);
    if (nx == 0) {
        #pragma unroll
        for (int bi = 0; bi < 8; bi++)
            g_psum[(size_t)(8*by + bi)*SIMBLK + blockIdx.x] = psum[bi];
    }
}

// ---------------- deterministic reductions ---------------------------------
__global__ void reduce_sumexp_kernel()
{
    const int b = blockIdx.x, t = threadIdx.x;
    float s = 0.f;
    for (int i = t; i < SIMBLK; i += 256) s += g_psum[(size_t)b*SIMBLK + i];
    __shared__ float red[256];
    red[t] = s; __syncthreads();
    for (int off = 128; off; off >>= 1) { if (t < off) red[t] += red[t+off]; __syncthreads(); }
    if (t == 0) g_sumexp[b] = red[0];
}

__global__ void reduce_total_kernel(int out_off)
{
    const int seg = blockIdx.x, t = threadIdx.x;
    float s = 0.f;
    for (int i = t; i < Bz*CSPBLK; i += 256) s += g_tpart[seg*(Bz*CSPBLK) + i];
    __shared__ float red[256];
    red[t] = s; __syncthreads();
    for (int off = 128; off; off >>= 1) { if (t < off) red[t] += red[t+off]; __syncthreads(); }
    if (t == 0) g_totals[out_off + seg] = red[0];
}

// ----- kernel 3a: WRITE head csp: gate + 3-tap shift + fast pow + psum -----
__global__ void csp_write_kernel(const float* __restrict__ ww)
{
    const int b  = blockIdx.y;
    const int c0 = blockIdx.x * 1024;
    const float* __restrict__ wp = ww + (size_t)b*NNv;
    float* __restrict__ wo = g_wpow_w + (size_t)b*NNv;
    const float* __restrict__ Eb = g_E + (size_t)b*NNv;

    __shared__ float wg[1026];
    __shared__ float red[256];
    const float gg   = g_gate[b];
    const float invS = 1.f / g_sumexp[b];
    const float s0 = g_shift[b*3+0], s1 = g_shift[b*3+1], s2 = g_shift[b*3+2];
    const float gm = g_gamma[b];
    const int t = threadIdx.x;

    for (int i = t; i < 1026; i += 256) {
        const int n = c0 + i - 1;
        float v = 0.f;
        if (n >= 0 && n < NNv)
            v = gg * Eb[n] * invS + (1.f - gg) * wp[n];
        wg[i] = v;
    }
    __syncthreads();

    float ls = 0.f;
    #pragma unroll
    for (int j = 0; j < 4; j++) {
        const int i = t + j*256;
        const float wt = fmaf(s0, wg[i], fmaf(s1, wg[i+1], s2*wg[i+2]));
        const float pw = fpow(wt, gm);
        wo[c0 + i] = pw;
        ls += pw;
    }
    red[t] = ls; __syncthreads();
    for (int off = 128; off; off >>= 1) { if (t < off) red[t] += red[t+off]; __syncthreads(); }
    if (t == 0) g_tpart[b*CSPBLK + blockIdx.x] = red[0];
}

// ----- kernel 3b: READ heads csp, all R heads per block --------------------
// The gated content term g*E[n]/sumexp is identical across the R heads:
// compute it once into smem (ec), then per head only wr differs.
__global__ void csp_read_kernel(const float* __restrict__ wr)
{
    const int b  = blockIdx.y;
    const int c0 = blockIdx.x * 1024;
    const float* __restrict__ Eb = g_E + (size_t)b*NNv;

    __shared__ float ec[1026];     // gated content part (with halo)
    __shared__ float wg[1026];
    __shared__ float red[256];
    const float gg   = g_gate[b];
    const float onemg = 1.f - gg;
    const float invS = gg / g_sumexp[b];   // fold gate into scale
    const float s0 = g_shift[b*3+0], s1 = g_shift[b*3+1], s2 = g_shift[b*3+2];
    const float gm = g_gamma[b];
    const int t = threadIdx.x;

    for (int i = t; i < 1026; i += 256) {
        const int n = c0 + i - 1;
        ec[i] = (n >= 0 && n < NNv) ? Eb[n] * invS : 0.f;
    }

    #pragma unroll
    for (int r = 0; r < Rv; r++) {
        const size_t head_off = ((size_t)r*Bz + b) * NNv;
        const float* __restrict__ wp = wr + head_off;
        float* __restrict__ wo = g_wpow_r + head_off;

        __syncthreads();   // ec ready (r==0) / prior wg consumers done
        for (int i = t; i < 1026; i += 256) {
            const int n = c0 + i - 1;
            float v = ec[i];
            if (n >= 0 && n < NNv) v = fmaf(onemg, wp[n], v);
            wg[i] = v;
        }
        __syncthreads();

        float ls = 0.f;
        #pragma unroll
        for (int j = 0; j < 4; j++) {
            const int i = t + j*256;
            const float wt = fmaf(s0, wg[i], fmaf(s1, wg[i+1], s2*wg[i+2]));
            const float pw = fpow(wt, gm);
            wo[c0 + i] = pw;
            ls += pw;
        }
        red[t] = ls; __syncthreads();
        for (int off = 128; off; off >>= 1) { if (t < off) red[t] += red[t+off]; __syncthreads(); }
        if (t == 0)
            g_tpart[r*(Bz*CSPBLK) + b*CSPBLK + blockIdx.x] = red[0];
    }
}

// --- kernel 4: m1 = m0*(1 - W^T e) + W^T a   (W = wpow_w * inv_total) ------
__global__ void memupdate_kernel(const float* __restrict__ mem,
                                 const int* __restrict__ bank)
{
    const float* __restrict__ m0 = mem + (size_t)bank[0]*NNv*Mv;
    __shared__ float wsh[64*64];   // [k=b][n-local]
    __shared__ float es [64*64];   // [b][m] pre-scaled by inv_total
    __shared__ float as_[64*64];
    const int t = threadIdx.x;
    const int n0 = blockIdx.x * 64;
    const float inv = 1.f / (g_totals[0] + 1e-5f);

    for (int i = t; i < 64*64; i += 256) {
        int bb = i >> 6, nl = i & 63;
        wsh[i] = g_wpow_w[(size_t)bb*NNv + n0 + nl];
    }
    for (int i = t; i < 64*64; i += 256) { es[i] = g_ev[i]*inv; as_[i] = g_av[i]*inv; }
    __syncthreads();

    const int tn = t >> 4, tm = t & 15;   // 4 n x 4 m per thread
    float ce[4][4], ca[4][4];
    #pragma unroll
    for (int i = 0; i < 4; i++)
        #pragma unroll
        for (int j = 0; j < 4; j++) { ce[i][j] = 0.f; ca[i][j] = 0.f; }

    #pragma unroll 16
    for (int k = 0; k < 64; k++) {
        const float4 A  = *(const float4*)&wsh[k*64 + 4*tn];
        const float4 E4 = *(const float4*)&es [k*64 + 4*tm];
        const float4 A4 = *(const float4*)&as_[k*64 + 4*tm];
        float av[4] = {A.x, A.y, A.z, A.w};
        float ev[4] = {E4.x, E4.y, E4.z, E4.w};
        float aa[4] = {A4.x, A4.y, A4.z, A4.w};
        #pragma unroll
        for (int i = 0; i < 4; i++)
            #pragma unroll
            for (int j = 0; j < 4; j++) {
                ce[i][j] = fmaf(av[i], ev[j], ce[i][j]);
                ca[i][j] = fmaf(av[i], aa[j], ca[i][j]);
            }
    }

    #pragma unroll
    for (int i = 0; i < 4; i++) {
        const size_t n = (size_t)(n0 + 4*tn + i);
        const float4 o = *(const float4*)&m0[n*Mv + 4*tm];
        float4 v;
        v.x = o.x*(1.f - ce[i][0]) + ca[i][0];
        v.y = o.y*(1.f - ce[i][1]) + ca[i][1];
        v.z = o.z*(1.f - ce[i][2]) + ca[i][2];
        v.w = o.w*(1.f - ce[i][3]) + ca[i][3];
        *(float4*)&g_m1[n*Mv + 4*tm] = v;
    }
}

// ----- kernel 5: split-K read einsum partials: part[r,c,b,m] (R1 version) --
__global__ void einsum_kernel()
{
    const int chunk = blockIdx.x, r = blockIdx.y;
    const int n0 = chunk * EK;
    __shared__ float ashT[64*68];  // [k][b], padded
    __shared__ float bsh [64*64];  // [k][m]
    const int t = threadIdx.x;
    const int tb = t >> 4, tm = t & 15;  // 4 b x 4 m per thread
    float acc[4][4];
    #pragma unroll
    for (int i = 0; i < 4; i++)
        #pragma unroll
        for (int j = 0; j < 4; j++) acc[i][j] = 0.f;

    for (int sub = 0; sub < EK/64; sub++) {
        const int nb = n0 + sub*64;
        for (int i = t; i < 64*64; i += 256) {
            int bb = i >> 6, kk = i & 63;
            ashT[kk*68 + bb] = g_wpow_r[((size_t)r*Bz + bb)*NNv + nb + kk];
        }
        for (int i = t; i < 64*64; i += 256) {
            int kk = i >> 6, mm = i & 63;
            bsh[i] = g_m1[(size_t)(nb + kk)*Mv + mm];
        }
        __syncthreads();
        #pragma unroll 16
        for (int k = 0; k < 64; k++) {
            const float4 A = *(const float4*)&ashT[k*68 + 4*tb];
            const float4 Bv = *(const float4*)&bsh[k*64 + 4*tm];
            float av[4] = {A.x, A.y, A.z, A.w};
            float bv[4] = {Bv.x, Bv.y, Bv.z, Bv.w};
            #pragma unroll
            for (int i = 0; i < 4; i++)
                #pragma unroll
                for (int j = 0; j < 4; j++)
                    acc[i][j] = fmaf(av[i], bv[j], acc[i][j]);
        }
        __syncthreads();
    }

    const size_t base = ((size_t)r*ECHUNK + chunk) * (Bz*Mv);
    #pragma unroll
    for (int i = 0; i < 4; i++) {
        float4 v = make_float4(acc[i][0], acc[i][1], acc[i][2], acc[i][3]);
        *(float4*)&g_epart[base + (size_t)(4*tb + i)*Mv + 4*tm] = v;
    }
}

// ----- kernel 6: reduce split-K + apply 1/(total_r+eps) + transpose --------
__global__ void reduce_out_kernel(float* __restrict__ out)
{
    const int gid = blockIdx.x*256 + threadIdx.x;   // 0..R*B*M-1
    const int r = gid >> 12;
    const int b = (gid >> 6) & 63;
    const int m = gid & 63;
    const float inv = 1.f / (g_totals[1 + r] + 1e-5f);
    float s = 0.f;
    for (int c = 0; c < ECHUNK; c++)
        s += g_epart[(((size_t)r*ECHUNK + c)*Bz + b)*Mv + m];
    out[(size_t)b*(Rv*Mv) + r*Mv + m] = s * inv;
}

// ---------------------------------------------------------------------------
extern "C" void kernel_launch(void* const* d_in, const int* in_sizes, int n_in,
                              void* d_out, int out_size)
{
    const float* h_t     = (const float*)d_in[0];
    const float* ww      = (const float*)d_in[1];
    const float* wr      = (const float*)d_in[2];
    const float* memory  = (const float*)d_in[3];
    const float* key_w   = (const float*)d_in[4];
    const float* key_b   = (const float*)d_in[5];
    const float* beta_w  = (const float*)d_in[6];
    const float* beta_b  = (const float*)d_in[7];
    const float* gate_w  = (const float*)d_in[8];
    const float* gate_b  = (const float*)d_in[9];
    const float* shift_w = (const float*)d_in[10];
    const float* shift_b = (const float*)d_in[11];
    const float* gamma_w = (const float*)d_in[12];
    const float* gamma_b = (const float*)d_in[13];
    const float* erase_w = (const float*)d_in[14];
    const float* erase_b = (const float*)d_in[15];
    const float* add_w   = (const float*)d_in[16];
    const float* add_b   = (const float*)d_in[17];
    const int*   bank    = (const int*)d_in[18];
    float* out = (float*)d_out;

    // head params (shared by all 5 weight updates)
    heads_kernel<<<Bz, 256>>>(h_t, key_w, key_b, beta_w, beta_b, gate_w, gate_b,
                              shift_w, shift_b, gamma_w, gamma_b,
                              erase_w, erase_b, add_w, add_b);

    // --- write head: content addressing on m0 ---
    sim_kernel<<<SIMBLK, 256>>>(memory, bank, 0);
    reduce_sumexp_kernel<<<Bz, 256>>>();
    csp_write_kernel<<<dim3(CSPBLK, Bz), 256>>>(ww);
    reduce_total_kernel<<<1, 256>>>(0);

    // --- memory erase/add ---
    memupdate_kernel<<<NNv/64, 256>>>(memory, bank);

    // --- read heads: shared content addressing on m1, all R heads/block ---
    sim_kernel<<<SIMBLK, 256>>>(memory, bank, 1);
    reduce_sumexp_kernel<<<Bz, 256>>>();
    csp_read_kernel<<<dim3(CSPBLK, Bz), 256>>>(wr);
    reduce_total_kernel<<<Rv, 256>>>(1);

    // --- read: r[r,b,:] = (wpow_r[r,b,:]/total_r) @ m1 ---
    einsum_kernel<<<dim3(ECHUNK, Rv), 256>>>();
    reduce_out_kernel<<<(Rv*Bz*Mv)/256, 256>>>(out);
}

// round 10
// speedup vs baseline: 1.5497x; 1.1218x over previous
#include <cuda_runtime.h>
#include <math.h>

#define Bz 64
#define Hh 1024
#define NNv 65536
#define Mv 64
#define Rv 4
#define SIMBLK (NNv/64)   /* 1024 sim blocks */
#define CSPBLK 64         /* N/1024 csp blocks per b */
#define ECHUNK 128        /* einsum split-K chunks */
#define EK (NNv/ECHUNK)   /* 512 n per chunk */

// ---------------- scratch (device globals: no allocation allowed) ----------
__device__ float g_E[(size_t)Bz*NNv];            // exp(beta*sim) buffer [B,N]
__device__ float g_wpow_w[(size_t)Bz*NNv];       // write-head w_pow
__device__ float g_wpow_r[(size_t)Rv*Bz*NNv];    // read-head w_pow [R,B,N]
__device__ float g_m1[(size_t)NNv*Mv];           // updated memory
__device__ float g_kn[Bz*Mv];
__device__ float g_ev[Bz*Mv];
__device__ float g_av[Bz*Mv];
__device__ float g_beta[Bz];
__device__ float g_gate[Bz];
__device__ float g_gamma[Bz];
__device__ float g_shift[Bz*3];
__device__ float g_psum[(size_t)Bz*SIMBLK];      // per-block exp partial sums
__device__ float g_sumexp[Bz];
__device__ float g_tpart[Rv*Bz*CSPBLK];          // per-block pow partial sums
__device__ float g_totals[1+Rv];                 // [0]=write total, [1..4]=read totals
__device__ float g_epart[(size_t)Rv*ECHUNK*Bz*Mv]; // einsum split-K partials

__device__ __forceinline__ float clip01(float x){ return fminf(fmaxf(x, 0.f), 1.f); }
// fast x^g for x > 0 (w_tilde strictly positive: gated softmax mix, s_j > 0)
__device__ __forceinline__ float fpow(float x, float g){ return __expf(g * __logf(x)); }

// ---------------- kernel 1: head projections (once per step) ---------------
__global__ void heads_kernel(const float* __restrict__ h,
    const float* __restrict__ key_w,   const float* __restrict__ key_b,
    const float* __restrict__ beta_w,  const float* __restrict__ beta_b,
    const float* __restrict__ gate_w,  const float* __restrict__ gate_b,
    const float* __restrict__ shift_w, const float* __restrict__ shift_b,
    const float* __restrict__ gamma_w, const float* __restrict__ gamma_b,
    const float* __restrict__ erase_w, const float* __restrict__ erase_b,
    const float* __restrict__ add_w,   const float* __restrict__ add_b)
{
    __shared__ float hs[Hh];
    __shared__ float ksh[Mv];
    __shared__ float sdot[6];
    __shared__ float sinv;
    const int b = blockIdx.x, t = threadIdx.x;
    for (int i = t; i < Hh; i += 256) hs[i] = h[(size_t)b*Hh + i];
    __syncthreads();

    if (t < 64) {
        float a0=0,a1=0,a2=0,a3=0;
        for (int j = 0; j < Hh; j += 4) {
            a0 = fmaf(hs[j  ], key_w[(j  )*Mv + t], a0);
            a1 = fmaf(hs[j+1], key_w[(j+1)*Mv + t], a1);
            a2 = fmaf(hs[j+2], key_w[(j+2)*Mv + t], a2);
            a3 = fmaf(hs[j+3], key_w[(j+3)*Mv + t], a3);
        }
        ksh[t] = clip01(a0+a1+a2+a3 + key_b[t]);
    } else if (t < 128) {
        const int m = t - 64;
        float a0=0,a1=0,a2=0,a3=0;
        for (int j = 0; j < Hh; j += 4) {
            a0 = fmaf(hs[j  ], erase_w[(j  )*Mv + m], a0);
            a1 = fmaf(hs[j+1], erase_w[(j+1)*Mv + m], a1);
            a2 = fmaf(hs[j+2], erase_w[(j+2)*Mv + m], a2);
            a3 = fmaf(hs[j+3], erase_w[(j+3)*Mv + m], a3);
        }
        g_ev[b*Mv + m] = clip01(a0+a1+a2+a3 + erase_b[m]);
    } else if (t < 192) {
        const int m = t - 128;
        float a0=0,a1=0,a2=0,a3=0;
        for (int j = 0; j < Hh; j += 4) {
            a0 = fmaf(hs[j  ], add_w[(j  )*Mv + m], a0);
            a1 = fmaf(hs[j+1], add_w[(j+1)*Mv + m], a1);
            a2 = fmaf(hs[j+2], add_w[(j+2)*Mv + m], a2);
            a3 = fmaf(hs[j+3], add_w[(j+3)*Mv + m], a3);
        }
        // relu then clip01 == clip01
        g_av[b*Mv + m] = clip01(a0+a1+a2+a3 + add_b[m]);
    } else if (t < 198) {
        const int d = t - 192;
        const float* w; int str, col;
        if      (d == 0) { w = beta_w;  str = 1; col = 0; }
        else if (d == 1) { w = gate_w;  str = 1; col = 0; }
        else if (d == 2) { w = gamma_w; str = 1; col = 0; }
        else             { w = shift_w; str = 3; col = d - 3; }
        float a0=0,a1=0;
        for (int j = 0; j < Hh; j += 2) {
            a0 = fmaf(hs[j  ], w[(j  )*str + col], a0);
            a1 = fmaf(hs[j+1], w[(j+1)*str + col], a1);
        }
        sdot[d] = a0 + a1;
    }
    __syncthreads();

    if (t < 32) {
        float v = ksh[t]*ksh[t] + ksh[t+32]*ksh[t+32];
        #pragma unroll
        for (int off = 16; off; off >>= 1) v += __shfl_xor_sync(0xffffffffu, v, off);
        if (t == 0) sinv = 1.f / (sqrtf(v) + 1e-8f);
    }
    __syncthreads();
    if (t < 64) g_kn[b*Mv + t] = ksh[t] * sinv;
    if (t == 0) {
        g_beta[b]  = fmaxf(sdot[0] + beta_b[0], 0.f);
        g_gate[b]  = clip01(sdot[1] + gate_b[0]);
        g_gamma[b] = 1.f + fmaxf(sdot[2] + gamma_b[0], 0.f);
        float x0 = sdot[3] + shift_b[0];
        float x1 = sdot[4] + shift_b[1];
        float x2 = sdot[5] + shift_b[2];
        float mx = fmaxf(x0, fmaxf(x1, x2));
        float e0 = expf(x0-mx), e1 = expf(x1-mx), e2 = expf(x2-mx);
        float is = 1.f / (e0+e1+e2);
        g_shift[b*3+0] = e0*is; g_shift[b*3+1] = e1*is; g_shift[b*3+2] = e2*is;
    }
}

// ------- kernel 2: E[b,n] = exp(beta[b] * (kn[b]·m[n]) / (||m[n]||+eps)) ---
// sim in [-1,1] (cosine) so exp without max-subtraction is numerically safe
// and mathematically identical to the reference softmax.
__global__ void sim_kernel(const float* __restrict__ mem,
                           const int* __restrict__ bank, int use_m1)
{
    const float* __restrict__ src = use_m1 ? g_m1
                                           : (mem + (size_t)bank[0]*NNv*Mv);
    __shared__ __align__(16) float knT[64*68];   // [k][b], padded
    __shared__ __align__(16) float mt [64*68];   // [k][n], n-tile=64, padded
    __shared__ float invn[64];
    __shared__ float sbeta[64];
    const int t = threadIdx.x;
    const int n0 = blockIdx.x * 64;

    for (int i = t; i < 64*64; i += 256) {
        int bb = i >> 6, mm = i & 63;
        knT[mm*68 + bb] = g_kn[i];
    }
    for (int i = t; i < 64*64; i += 256) {
        int rr = i >> 6, cc = i & 63;
        mt[cc*68 + rr] = src[(size_t)(n0 + rr)*Mv + cc];
    }
    if (t < 64) sbeta[t] = g_beta[t];
    __syncthreads();
    if (t < 64) {
        float s = 0.f;
        #pragma unroll 16
        for (int k = 0; k < 64; k++) { float v = mt[k*68 + t]; s = fmaf(v, v, s); }
        invn[t] = 1.f / (sqrtf(s) + 1e-8f);
    }
    __syncthreads();

    const int by = t >> 5, nx = t & 31;   // 8 b's per thread, 2 n's per thread
    float c[8][2];
    #pragma unroll
    for (int i = 0; i < 8; i++) { c[i][0] = 0.f; c[i][1] = 0.f; }

    #pragma unroll 16
    for (int k = 0; k < 64; k++) {
        const float4 A0 = *(const float4*)&knT[k*68 + 8*by];
        const float4 A1 = *(const float4*)&knT[k*68 + 8*by + 4];
        const float2 Bv = *(const float2*)&mt [k*68 + 2*nx];
        float a[8] = {A0.x, A0.y, A0.z, A0.w, A1.x, A1.y, A1.z, A1.w};
        #pragma unroll
        for (int bi = 0; bi < 8; bi++) {
            c[bi][0] = fmaf(a[bi], Bv.x, c[bi][0]);
            c[bi][1] = fmaf(a[bi], Bv.y, c[bi][1]);
        }
    }

    const float2 iv = *(const float2*)&invn[2*nx];
    float psum[8];
    #pragma unroll
    for (int bi = 0; bi < 8; bi++) {
        const int bb = 8*by + bi;
        const float bt = sbeta[bb];
        float e0 = __expf(bt * c[bi][0] * iv.x);
        float e1 = __expf(bt * c[bi][1] * iv.y);
        *(float2*)&g_E[(size_t)bb*NNv + n0 + 2*nx] = make_float2(e0, e1);
        psum[bi] = e0 + e1;
    }
    #pragma unroll
    for (int bi = 0; bi < 8; bi++)
        #pragma unroll
        for (int off = 16; off; off >>= 1)
            psum[bi] += __shfl_xor_sync(0xffffffffu, psum[bi], off);
    if (nx == 0) {
        #pragma unroll
        for (int bi = 0; bi < 8; bi++)
            g_psum[(size_t)(8*by + bi)*SIMBLK + blockIdx.x] = psum[bi];
    }
}

// ---------------- deterministic reductions ---------------------------------
__global__ void reduce_sumexp_kernel()
{
    const int b = blockIdx.x, t = threadIdx.x;
    float s = 0.f;
    for (int i = t; i < SIMBLK; i += 256) s += g_psum[(size_t)b*SIMBLK + i];
    __shared__ float red[256];
    red[t] = s; __syncthreads();
    for (int off = 128; off; off >>= 1) { if (t < off) red[t] += red[t+off]; __syncthreads(); }
    if (t == 0) g_sumexp[b] = red[0];
}

__global__ void reduce_total_kernel(int out_off)
{
    const int seg = blockIdx.x, t = threadIdx.x;
    float s = 0.f;
    for (int i = t; i < Bz*CSPBLK; i += 256) s += g_tpart[seg*(Bz*CSPBLK) + i];
    __shared__ float red[256];
    red[t] = s; __syncthreads();
    for (int off = 128; off; off >>= 1) { if (t < off) red[t] += red[t+off]; __syncthreads(); }
    if (t == 0) g_totals[out_off + seg] = red[0];
}

// ----- kernel 3a: WRITE head csp (vectorized) -------------------------------
// wg2[0..1023]: gated value at n = c0+i (float4-aligned). wg2[1024] = right
// halo (n = c0+1024), wg2[1025] = left halo (n = c0-1). Array padded to 1032
// floats so the NEXT smem array stays 16B-aligned.
__global__ void csp_write_kernel(const float* __restrict__ ww)
{
    const int b  = blockIdx.y;
    const int c0 = blockIdx.x * 1024;
    const float* __restrict__ wp = ww + (size_t)b*NNv;
    float* __restrict__ wo = g_wpow_w + (size_t)b*NNv;
    const float* __restrict__ Eb = g_E + (size_t)b*NNv;

    __shared__ __align__(16) float wg2[1032];
    __shared__ __align__(16) float red[256];
    const float gg   = g_gate[b];
    const float invS = gg / g_sumexp[b];   // gate folded into content scale
    const float omg  = 1.f - gg;
    const float s0 = g_shift[b*3+0], s1 = g_shift[b*3+1], s2 = g_shift[b*3+2];
    const float gm = g_gamma[b];
    const int t = threadIdx.x;

    {
        const int n = c0 + 4*t;
        const float4 e = *(const float4*)&Eb[n];
        const float4 w = *(const float4*)&wp[n];
        float4 v;
        v.x = fmaf(omg, w.x, e.x*invS);
        v.y = fmaf(omg, w.y, e.y*invS);
        v.z = fmaf(omg, w.z, e.z*invS);
        v.w = fmaf(omg, w.w, e.w*invS);
        *(float4*)&wg2[4*t] = v;
    }
    if (t == 0) {
        const int nl = c0 - 1;
        wg2[1025] = (nl >= 0)  ? fmaf(omg, wp[nl], Eb[nl]*invS) : 0.f;
        const int nr = c0 + 1024;
        wg2[1024] = (nr < NNv) ? fmaf(omg, wp[nr], Eb[nr]*invS) : 0.f;
    }
    __syncthreads();

    const float4 f   = *(const float4*)&wg2[4*t];
    const float left  = wg2[(t == 0) ? 1025 : 4*t - 1];
    const float right = wg2[4*t + 4];   // t==255 lands on wg2[1024] = halo
    float4 o;
    o.x = fpow(fmaf(s0, left, fmaf(s1, f.x, s2*f.y)),  gm);
    o.y = fpow(fmaf(s0, f.x,  fmaf(s1, f.y, s2*f.z)),  gm);
    o.z = fpow(fmaf(s0, f.y,  fmaf(s1, f.z, s2*f.w)),  gm);
    o.w = fpow(fmaf(s0, f.z,  fmaf(s1, f.w, s2*right)), gm);
    *(float4*)&wo[c0 + 4*t] = o;

    red[t] = (o.x + o.y) + (o.z + o.w);
    __syncthreads();
    for (int off = 128; off; off >>= 1) { if (t < off) red[t] += red[t+off]; __syncthreads(); }
    if (t == 0) g_tpart[b*CSPBLK + blockIdx.x] = red[0];
}

// ----- kernel 3b: READ heads csp (vectorized, all R heads per block) --------
// Gated content term g*E/sumexp is r-independent: staged once into ec.
__global__ void csp_read_kernel(const float* __restrict__ wr)
{
    const int b  = blockIdx.y;
    const int c0 = blockIdx.x * 1024;
    const float* __restrict__ Eb = g_E + (size_t)b*NNv;

    __shared__ __align__(16) float ec [1032];   // same halo layout as wg2
    __shared__ __align__(16) float wg2[1032];
    __shared__ __align__(16) float red[256];
    const float gg   = g_gate[b];
    const float omg  = 1.f - gg;
    const float invS = gg / g_sumexp[b];
    const float s0 = g_shift[b*3+0], s1 = g_shift[b*3+1], s2 = g_shift[b*3+2];
    const float gm = g_gamma[b];
    const int t = threadIdx.x;

    {
        const int n = c0 + 4*t;
        const float4 e = *(const float4*)&Eb[n];
        float4 v;
        v.x = e.x*invS; v.y = e.y*invS; v.z = e.z*invS; v.w = e.w*invS;
        *(float4*)&ec[4*t] = v;
    }
    if (t == 0) {
        const int nl = c0 - 1;
        ec[1025] = (nl >= 0)  ? Eb[nl]*invS : 0.f;
        const int nr = c0 + 1024;
        ec[1024] = (nr < NNv) ? Eb[nr]*invS : 0.f;
    }

    #pragma unroll
    for (int r = 0; r < Rv; r++) {
        const size_t head_off = ((size_t)r*Bz + b) * NNv;
        const float* __restrict__ wp = wr + head_off;
        float* __restrict__ wo = g_wpow_r + head_off;

        __syncthreads();   // ec ready (r==0) / prior-r wg2 consumers done
        {
            const int n = c0 + 4*t;
            const float4 w = *(const float4*)&wp[n];
            const float4 e = *(const float4*)&ec[4*t];
            float4 v;
            v.x = fmaf(omg, w.x, e.x);
            v.y = fmaf(omg, w.y, e.y);
            v.z = fmaf(omg, w.z, e.z);
            v.w = fmaf(omg, w.w, e.w);
            *(float4*)&wg2[4*t] = v;
        }
        if (t == 0) {
            const int nl = c0 - 1;
            wg2[1025] = (nl >= 0)  ? fmaf(omg, wp[nl], ec[1025]) : 0.f;
            const int nr = c0 + 1024;
            wg2[1024] = (nr < NNv) ? fmaf(omg, wp[nr], ec[1024]) : 0.f;
        }
        __syncthreads();

        const float4 f   = *(const float4*)&wg2[4*t];
        const float left  = wg2[(t == 0) ? 1025 : 4*t - 1];
        const float right = wg2[4*t + 4];
        float4 o;
        o.x = fpow(fmaf(s0, left, fmaf(s1, f.x, s2*f.y)),  gm);
        o.y = fpow(fmaf(s0, f.x,  fmaf(s1, f.y, s2*f.z)),  gm);
        o.z = fpow(fmaf(s0, f.y,  fmaf(s1, f.z, s2*f.w)),  gm);
        o.w = fpow(fmaf(s0, f.z,  fmaf(s1, f.w, s2*right)), gm);
        *(float4*)&wo[c0 + 4*t] = o;

        red[t] = (o.x + o.y) + (o.z + o.w);
        __syncthreads();
        for (int off = 128; off; off >>= 1) { if (t < off) red[t] += red[t+off]; __syncthreads(); }
        if (t == 0)
            g_tpart[r*(Bz*CSPBLK) + b*CSPBLK + blockIdx.x] = red[0];
    }
}

// --- kernel 4: m1 = m0*(1 - W^T e) + W^T a   (W = wpow_w * inv_total) ------
__global__ void memupdate_kernel(const float* __restrict__ mem,
                                 const int* __restrict__ bank)
{
    const float* __restrict__ m0 = mem + (size_t)bank[0]*NNv*Mv;
    __shared__ __align__(16) float wsh[64*64];   // [k=b][n-local]
    __shared__ __align__(16) float es [64*64];   // [b][m] pre-scaled by inv_total
    __shared__ __align__(16) float as_[64*64];
    const int t = threadIdx.x;
    const int n0 = blockIdx.x * 64;
    const float inv = 1.f / (g_totals[0] + 1e-5f);

    for (int i = t; i < 64*64; i += 256) {
        int bb = i >> 6, nl = i & 63;
        wsh[i] = g_wpow_w[(size_t)bb*NNv + n0 + nl];
    }
    for (int i = t; i < 64*64; i += 256) { es[i] = g_ev[i]*inv; as_[i] = g_av[i]*inv; }
    __syncthreads();

    const int tn = t >> 4, tm = t & 15;   // 4 n x 4 m per thread
    float ce[4][4], ca[4][4];
    #pragma unroll
    for (int i = 0; i < 4; i++)
        #pragma unroll
        for (int j = 0; j < 4; j++) { ce[i][j] = 0.f; ca[i][j] = 0.f; }

    #pragma unroll 16
    for (int k = 0; k < 64; k++) {
        const float4 A  = *(const float4*)&wsh[k*64 + 4*tn];
        const float4 E4 = *(const float4*)&es [k*64 + 4*tm];
        const float4 A4 = *(const float4*)&as_[k*64 + 4*tm];
        float av[4] = {A.x, A.y, A.z, A.w};
        float ev[4] = {E4.x, E4.y, E4.z, E4.w};
        float aa[4] = {A4.x, A4.y, A4.z, A4.w};
        #pragma unroll
        for (int i = 0; i < 4; i++)
            #pragma unroll
            for (int j = 0; j < 4; j++) {
                ce[i][j] = fmaf(av[i], ev[j], ce[i][j]);
                ca[i][j] = fmaf(av[i], aa[j], ca[i][j]);
            }
    }

    #pragma unroll
    for (int i = 0; i < 4; i++) {
        const size_t n = (size_t)(n0 + 4*tn + i);
        const float4 o = *(const float4*)&m0[n*Mv + 4*tm];
        float4 v;
        v.x = o.x*(1.f - ce[i][0]) + ca[i][0];
        v.y = o.y*(1.f - ce[i][1]) + ca[i][1];
        v.z = o.z*(1.f - ce[i][2]) + ca[i][2];
        v.w = o.w*(1.f - ce[i][3]) + ca[i][3];
        *(float4*)&g_m1[n*Mv + 4*tm] = v;
    }
}

// ----- kernel 5: split-K read einsum partials: part[r,c,b,m] ----------------
__global__ void einsum_kernel()
{
    const int chunk = blockIdx.x, r = blockIdx.y;
    const int n0 = chunk * EK;
    __shared__ __align__(16) float ashT[64*68];  // [k][b], padded
    __shared__ __align__(16) float bsh [64*64];  // [k][m]
    const int t = threadIdx.x;
    const int tb = t >> 4, tm = t & 15;  // 4 b x 4 m per thread
    float acc[4][4];
    #pragma unroll
    for (int i = 0; i < 4; i++)
        #pragma unroll
        for (int j = 0; j < 4; j++) acc[i][j] = 0.f;

    for (int sub = 0; sub < EK/64; sub++) {
        const int nb = n0 + sub*64;
        for (int i = t; i < 64*64; i += 256) {
            int bb = i >> 6, kk = i & 63;
            ashT[kk*68 + bb] = g_wpow_r[((size_t)r*Bz + bb)*NNv + nb + kk];
        }
        for (int i = t; i < 64*64; i += 256) {
            int kk = i >> 6, mm = i & 63;
            bsh[i] = g_m1[(size_t)(nb + kk)*Mv + mm];
        }
        __syncthreads();
        #pragma unroll 16
        for (int k = 0; k < 64; k++) {
            const float4 A = *(const float4*)&ashT[k*68 + 4*tb];
            const float4 Bv = *(const float4*)&bsh[k*64 + 4*tm];
            float av[4] = {A.x, A.y, A.z, A.w};
            float bv[4] = {Bv.x, Bv.y, Bv.z, Bv.w};
            #pragma unroll
            for (int i = 0; i < 4; i++)
                #pragma unroll
                for (int j = 0; j < 4; j++)
                    acc[i][j] = fmaf(av[i], bv[j], acc[i][j]);
        }
        __syncthreads();
    }

    const size_t base = ((size_t)r*ECHUNK + chunk) * (Bz*Mv);
    #pragma unroll
    for (int i = 0; i < 4; i++) {
        float4 v = make_float4(acc[i][0], acc[i][1], acc[i][2], acc[i][3]);
        *(float4*)&g_epart[base + (size_t)(4*tb + i)*Mv + 4*tm] = v;
    }
}

// ----- kernel 6: reduce split-K + apply 1/(total_r+eps) + transpose --------
__global__ void reduce_out_kernel(float* __restrict__ out)
{
    const int gid = blockIdx.x*256 + threadIdx.x;   // 0..R*B*M-1
    const int r = gid >> 12;
    const int b = (gid >> 6) & 63;
    const int m = gid & 63;
    const float inv = 1.f / (g_totals[1 + r] + 1e-5f);
    float s = 0.f;
    for (int c = 0; c < ECHUNK; c++)
        s += g_epart[(((size_t)r*ECHUNK + c)*Bz + b)*Mv + m];
    out[(size_t)b*(Rv*Mv) + r*Mv + m] = s * inv;
}

// ---------------------------------------------------------------------------
extern "C" void kernel_launch(void* const* d_in, const int* in_sizes, int n_in,
                              void* d_out, int out_size)
{
    const float* h_t     = (const float*)d_in[0];
    const float* ww      = (const float*)d_in[1];
    const float* wr      = (const float*)d_in[2];
    const float* memory  = (const float*)d_in[3];
    const float* key_w   = (const float*)d_in[4];
    const float* key_b   = (const float*)d_in[5];
    const float* beta_w  = (const float*)d_in[6];
    const float* beta_b  = (const float*)d_in[7];
    const float* gate_w  = (const float*)d_in[8];
    const float* gate_b  = (const float*)d_in[9];
    const float* shift_w = (const float*)d_in[10];
    const float* shift_b = (const float*)d_in[11];
    const float* gamma_w = (const float*)d_in[12];
    const float* gamma_b = (const float*)d_in[13];
    const float* erase_w = (const float*)d_in[14];
    const float* erase_b = (const float*)d_in[15];
    const float* add_w   = (const float*)d_in[16];
    const float* add_b   = (const float*)d_in[17];
    const int*   bank    = (const int*)d_in[18];
    float* out = (float*)d_out;

    // head params (shared by all 5 weight updates)
    heads_kernel<<<Bz, 256>>>(h_t, key_w, key_b, beta_w, beta_b, gate_w, gate_b,
                              shift_w, shift_b, gamma_w, gamma_b,
                              erase_w, erase_b, add_w, add_b);

    // --- write head: content addressing on m0 ---
    sim_kernel<<<SIMBLK, 256>>>(memory, bank, 0);
    reduce_sumexp_kernel<<<Bz, 256>>>();
    csp_write_kernel<<<dim3(CSPBLK, Bz), 256>>>(ww);
    reduce_total_kernel<<<1, 256>>>(0);

    // --- memory erase/add ---
    memupdate_kernel<<<NNv/64, 256>>>(memory, bank);

    // --- read heads: shared content addressing on m1, all R heads/block ---
    sim_kernel<<<SIMBLK, 256>>>(memory, bank, 1);
    reduce_sumexp_kernel<<<Bz, 256>>>();
    csp_read_kernel<<<dim3(CSPBLK, Bz), 256>>>(wr);
    reduce_total_kernel<<<Rv, 256>>>(1);

    // --- read: r[r,b,:] = (wpow_r[r,b,:]/total_r) @ m1 ---
    einsum_kernel<<<dim3(ECHUNK, Rv), 256>>>();
    reduce_out_kernel<<<(Rv*Bz*Mv)/256, 256>>>(out);
}

// round 11
// speedup vs baseline: 1.7314x; 1.1173x over previous
#include <cuda_runtime.h>
#include <cuda_bf16.h>
#include <mma.h>
#include <math.h>

using namespace nvcuda;

#define Bz 64
#define Hh 1024
#define NNv 65536
#define Mv 64
#define Rv 4
#define SIMBLK (NNv/64)   /* 1024 sim blocks */
#define CSPBLK 64         /* N/1024 csp blocks per b */
#define ECHUNK 128        /* einsum split-K chunks */
#define EK (NNv/ECHUNK)   /* 512 n per chunk */

// ---------------- scratch (device globals: no allocation allowed) ----------
__device__ float g_E[(size_t)Bz*NNv];            // exp(beta*sim) buffer [B,N]
__device__ float g_wpow_w[(size_t)Bz*NNv];       // write-head w_pow
__device__ float g_wpow_r[(size_t)Rv*Bz*NNv];    // read-head w_pow [R,B,N]
__device__ float g_m1[(size_t)NNv*Mv];           // updated memory
__device__ float g_kn[Bz*Mv];
__device__ float g_ev[Bz*Mv];
__device__ float g_av[Bz*Mv];
__device__ float g_beta[Bz];
__device__ float g_gate[Bz];
__device__ float g_gamma[Bz];
__device__ float g_shift[Bz*3];
__device__ float g_psum[(size_t)Bz*SIMBLK];      // per-block exp partial sums
__device__ float g_sumexp[Bz];
__device__ float g_tpart[Rv*Bz*CSPBLK];          // per-block pow partial sums
__device__ float g_totals[1+Rv];                 // [0]=write total, [1..4]=read totals
__device__ float g_epart[(size_t)Rv*ECHUNK*Bz*Mv]; // einsum split-K partials

__device__ __forceinline__ float clip01(float x){ return fminf(fmaxf(x, 0.f), 1.f); }
// fast x^g for x > 0 (w_tilde strictly positive: gated softmax mix, s_j > 0)
__device__ __forceinline__ float fpow(float x, float g){ return __expf(g * __logf(x)); }

// ---------------- kernel 1: head projections (once per step) ---------------
__global__ void heads_kernel(const float* __restrict__ h,
    const float* __restrict__ key_w,   const float* __restrict__ key_b,
    const float* __restrict__ beta_w,  const float* __restrict__ beta_b,
    const float* __restrict__ gate_w,  const float* __restrict__ gate_b,
    const float* __restrict__ shift_w, const float* __restrict__ shift_b,
    const float* __restrict__ gamma_w, const float* __restrict__ gamma_b,
    const float* __restrict__ erase_w, const float* __restrict__ erase_b,
    const float* __restrict__ add_w,   const float* __restrict__ add_b)
{
    __shared__ float hs[Hh];
    __shared__ float ksh[Mv];
    __shared__ float sdot[6];
    __shared__ float sinv;
    const int b = blockIdx.x, t = threadIdx.x;
    for (int i = t; i < Hh; i += 256) hs[i] = h[(size_t)b*Hh + i];
    __syncthreads();

    if (t < 64) {
        float a0=0,a1=0,a2=0,a3=0;
        for (int j = 0; j < Hh; j += 4) {
            a0 = fmaf(hs[j  ], key_w[(j  )*Mv + t], a0);
            a1 = fmaf(hs[j+1], key_w[(j+1)*Mv + t], a1);
            a2 = fmaf(hs[j+2], key_w[(j+2)*Mv + t], a2);
            a3 = fmaf(hs[j+3], key_w[(j+3)*Mv + t], a3);
        }
        ksh[t] = clip01(a0+a1+a2+a3 + key_b[t]);
    } else if (t < 128) {
        const int m = t - 64;
        float a0=0,a1=0,a2=0,a3=0;
        for (int j = 0; j < Hh; j += 4) {
            a0 = fmaf(hs[j  ], erase_w[(j  )*Mv + m], a0);
            a1 = fmaf(hs[j+1], erase_w[(j+1)*Mv + m], a1);
            a2 = fmaf(hs[j+2], erase_w[(j+2)*Mv + m], a2);
            a3 = fmaf(hs[j+3], erase_w[(j+3)*Mv + m], a3);
        }
        g_ev[b*Mv + m] = clip01(a0+a1+a2+a3 + erase_b[m]);
    } else if (t < 192) {
        const int m = t - 128;
        float a0=0,a1=0,a2=0,a3=0;
        for (int j = 0; j < Hh; j += 4) {
            a0 = fmaf(hs[j  ], add_w[(j  )*Mv + m], a0);
            a1 = fmaf(hs[j+1], add_w[(j+1)*Mv + m], a1);
            a2 = fmaf(hs[j+2], add_w[(j+2)*Mv + m], a2);
            a3 = fmaf(hs[j+3], add_w[(j+3)*Mv + m], a3);
        }
        // relu then clip01 == clip01
        g_av[b*Mv + m] = clip01(a0+a1+a2+a3 + add_b[m]);
    } else if (t < 198) {
        const int d = t - 192;
        const float* w; int str, col;
        if      (d == 0) { w = beta_w;  str = 1; col = 0; }
        else if (d == 1) { w = gate_w;  str = 1; col = 0; }
        else if (d == 2) { w = gamma_w; str = 1; col = 0; }
        else             { w = shift_w; str = 3; col = d - 3; }
        float a0=0,a1=0;
        for (int j = 0; j < Hh; j += 2) {
            a0 = fmaf(hs[j  ], w[(j  )*str + col], a0);
            a1 = fmaf(hs[j+1], w[(j+1)*str + col], a1);
        }
        sdot[d] = a0 + a1;
    }
    __syncthreads();

    if (t < 32) {
        float v = ksh[t]*ksh[t] + ksh[t+32]*ksh[t+32];
        #pragma unroll
        for (int off = 16; off; off >>= 1) v += __shfl_xor_sync(0xffffffffu, v, off);
        if (t == 0) sinv = 1.f / (sqrtf(v) + 1e-8f);
    }
    __syncthreads();
    if (t < 64) g_kn[b*Mv + t] = ksh[t] * sinv;
    if (t == 0) {
        g_beta[b]  = fmaxf(sdot[0] + beta_b[0], 0.f);
        g_gate[b]  = clip01(sdot[1] + gate_b[0]);
        g_gamma[b] = 1.f + fmaxf(sdot[2] + gamma_b[0], 0.f);
        float x0 = sdot[3] + shift_b[0];
        float x1 = sdot[4] + shift_b[1];
        float x2 = sdot[5] + shift_b[2];
        float mx = fmaxf(x0, fmaxf(x1, x2));
        float e0 = expf(x0-mx), e1 = expf(x1-mx), e2 = expf(x2-mx);
        float is = 1.f / (e0+e1+e2);
        g_shift[b*3+0] = e0*is; g_shift[b*3+1] = e1*is; g_shift[b*3+2] = e2*is;
    }
}

// ------- kernel 2: E[b,n] = exp(beta[b] * (kn[b]·m[n]) / (||m[n]||+eps)) ---
// sim in [-1,1] (cosine) so exp without max-subtraction is numerically safe
// and mathematically identical to the reference softmax.
__global__ void sim_kernel(const float* __restrict__ mem,
                           const int* __restrict__ bank, int use_m1)
{
    const float* __restrict__ src = use_m1 ? g_m1
                                           : (mem + (size_t)bank[0]*NNv*Mv);
    __shared__ __align__(16) float knT[64*68];   // [k][b], padded
    __shared__ __align__(16) float mt [64*68];   // [k][n], n-tile=64, padded
    __shared__ float invn[64];
    __shared__ float sbeta[64];
    const int t = threadIdx.x;
    const int n0 = blockIdx.x * 64;

    for (int i = t; i < 64*64; i += 256) {
        int bb = i >> 6, mm = i & 63;
        knT[mm*68 + bb] = g_kn[i];
    }
    for (int i = t; i < 64*64; i += 256) {
        int rr = i >> 6, cc = i & 63;
        mt[cc*68 + rr] = src[(size_t)(n0 + rr)*Mv + cc];
    }
    if (t < 64) sbeta[t] = g_beta[t];
    __syncthreads();
    if (t < 64) {
        float s = 0.f;
        #pragma unroll 16
        for (int k = 0; k < 64; k++) { float v = mt[k*68 + t]; s = fmaf(v, v, s); }
        invn[t] = 1.f / (sqrtf(s) + 1e-8f);
    }
    __syncthreads();

    const int by = t >> 5, nx = t & 31;   // 8 b's per thread, 2 n's per thread
    float c[8][2];
    #pragma unroll
    for (int i = 0; i < 8; i++) { c[i][0] = 0.f; c[i][1] = 0.f; }

    #pragma unroll 16
    for (int k = 0; k < 64; k++) {
        const float4 A0 = *(const float4*)&knT[k*68 + 8*by];
        const float4 A1 = *(const float4*)&knT[k*68 + 8*by + 4];
        const float2 Bv = *(const float2*)&mt [k*68 + 2*nx];
        float a[8] = {A0.x, A0.y, A0.z, A0.w, A1.x, A1.y, A1.z, A1.w};
        #pragma unroll
        for (int bi = 0; bi < 8; bi++) {
            c[bi][0] = fmaf(a[bi], Bv.x, c[bi][0]);
            c[bi][1] = fmaf(a[bi], Bv.y, c[bi][1]);
        }
    }

    const float2 iv = *(const float2*)&invn[2*nx];
    float psum[8];
    #pragma unroll
    for (int bi = 0; bi < 8; bi++) {
        const int bb = 8*by + bi;
        const float bt = sbeta[bb];
        float e0 = __expf(bt * c[bi][0] * iv.x);
        float e1 = __expf(bt * c[bi][1] * iv.y);
        *(float2*)&g_E[(size_t)bb*NNv + n0 + 2*nx] = make_float2(e0, e1);
        psum[bi] = e0 + e1;
    }
    #pragma unroll
    for (int bi = 0; bi < 8; bi++)
        #pragma unroll
        for (int off = 16; off; off >>= 1)
            psum[bi] += __shfl_xor_sync(0xffffffffu, psum[bi], off);
    if (nx == 0) {
        #pragma unroll
        for (int bi = 0; bi < 8; bi++)
            g_psum[(size_t)(8*by + bi)*SIMBLK + blockIdx.x] = psum[bi];
    }
}

// ---------------- deterministic reductions ---------------------------------
__global__ void reduce_sumexp_kernel()
{
    const int b = blockIdx.x, t = threadIdx.x;
    float s = 0.f;
    for (int i = t; i < SIMBLK; i += 256) s += g_psum[(size_t)b*SIMBLK + i];
    __shared__ float red[256];
    red[t] = s; __syncthreads();
    for (int off = 128; off; off >>= 1) { if (t < off) red[t] += red[t+off]; __syncthreads(); }
    if (t == 0) g_sumexp[b] = red[0];
}

__global__ void reduce_total_kernel(int out_off)
{
    const int seg = blockIdx.x, t = threadIdx.x;
    float s = 0.f;
    for (int i = t; i < Bz*CSPBLK; i += 256) s += g_tpart[seg*(Bz*CSPBLK) + i];
    __shared__ float red[256];
    red[t] = s; __syncthreads();
    for (int off = 128; off; off >>= 1) { if (t < off) red[t] += red[t+off]; __syncthreads(); }
    if (t == 0) g_totals[out_off + seg] = red[0];
}

// ----- kernel 3a: WRITE head csp (vectorized) -------------------------------
// wg2[0..1023]: gated value at n = c0+i (float4-aligned). wg2[1024] = right
// halo (n = c0+1024), wg2[1025] = left halo (n = c0-1). Array padded to 1032
// floats so the NEXT smem array stays 16B-aligned.
__global__ void csp_write_kernel(const float* __restrict__ ww)
{
    const int b  = blockIdx.y;
    const int c0 = blockIdx.x * 1024;
    const float* __restrict__ wp = ww + (size_t)b*NNv;
    float* __restrict__ wo = g_wpow_w + (size_t)b*NNv;
    const float* __restrict__ Eb = g_E + (size_t)b*NNv;

    __shared__ __align__(16) float wg2[1032];
    __shared__ __align__(16) float red[256];
    const float gg   = g_gate[b];
    const float invS = gg / g_sumexp[b];   // gate folded into content scale
    const float omg  = 1.f - gg;
    const float s0 = g_shift[b*3+0], s1 = g_shift[b*3+1], s2 = g_shift[b*3+2];
    const float gm = g_gamma[b];
    const int t = threadIdx.x;

    {
        const int n = c0 + 4*t;
        const float4 e = *(const float4*)&Eb[n];
        const float4 w = *(const float4*)&wp[n];
        float4 v;
        v.x = fmaf(omg, w.x, e.x*invS);
        v.y = fmaf(omg, w.y, e.y*invS);
        v.z = fmaf(omg, w.z, e.z*invS);
        v.w = fmaf(omg, w.w, e.w*invS);
        *(float4*)&wg2[4*t] = v;
    }
    if (t == 0) {
        const int nl = c0 - 1;
        wg2[1025] = (nl >= 0)  ? fmaf(omg, wp[nl], Eb[nl]*invS) : 0.f;
        const int nr = c0 + 1024;
        wg2[1024] = (nr < NNv) ? fmaf(omg, wp[nr], Eb[nr]*invS) : 0.f;
    }
    __syncthreads();

    const float4 f   = *(const float4*)&wg2[4*t];
    const float left  = wg2[(t == 0) ? 1025 : 4*t - 1];
    const float right = wg2[4*t + 4];   // t==255 lands on wg2[1024] = halo
    float4 o;
    o.x = fpow(fmaf(s0, left, fmaf(s1, f.x, s2*f.y)),  gm);
    o.y = fpow(fmaf(s0, f.x,  fmaf(s1, f.y, s2*f.z)),  gm);
    o.z = fpow(fmaf(s0, f.y,  fmaf(s1, f.z, s2*f.w)),  gm);
    o.w = fpow(fmaf(s0, f.z,  fmaf(s1, f.w, s2*right)), gm);
    *(float4*)&wo[c0 + 4*t] = o;

    red[t] = (o.x + o.y) + (o.z + o.w);
    __syncthreads();
    for (int off = 128; off; off >>= 1) { if (t < off) red[t] += red[t+off]; __syncthreads(); }
    if (t == 0) g_tpart[b*CSPBLK + blockIdx.x] = red[0];
}

// ----- kernel 3b: READ heads csp (vectorized, all R heads per block) --------
// Gated content term g*E/sumexp is r-independent: staged once into ec.
__global__ void csp_read_kernel(const float* __restrict__ wr)
{
    const int b  = blockIdx.y;
    const int c0 = blockIdx.x * 1024;
    const float* __restrict__ Eb = g_E + (size_t)b*NNv;

    __shared__ __align__(16) float ec [1032];   // same halo layout as wg2
    __shared__ __align__(16) float wg2[1032];
    __shared__ __align__(16) float red[256];
    const float gg   = g_gate[b];
    const float omg  = 1.f - gg;
    const float invS = gg / g_sumexp[b];
    const float s0 = g_shift[b*3+0], s1 = g_shift[b*3+1], s2 = g_shift[b*3+2];
    const float gm = g_gamma[b];
    const int t = threadIdx.x;

    {
        const int n = c0 + 4*t;
        const float4 e = *(const float4*)&Eb[n];
        float4 v;
        v.x = e.x*invS; v.y = e.y*invS; v.z = e.z*invS; v.w = e.w*invS;
        *(float4*)&ec[4*t] = v;
    }
    if (t == 0) {
        const int nl = c0 - 1;
        ec[1025] = (nl >= 0)  ? Eb[nl]*invS : 0.f;
        const int nr = c0 + 1024;
        ec[1024] = (nr < NNv) ? Eb[nr]*invS : 0.f;
    }

    #pragma unroll
    for (int r = 0; r < Rv; r++) {
        const size_t head_off = ((size_t)r*Bz + b) * NNv;
        const float* __restrict__ wp = wr + head_off;
        float* __restrict__ wo = g_wpow_r + head_off;

        __syncthreads();   // ec ready (r==0) / prior-r wg2 consumers done
        {
            const int n = c0 + 4*t;
            const float4 w = *(const float4*)&wp[n];
            const float4 e = *(const float4*)&ec[4*t];
            float4 v;
            v.x = fmaf(omg, w.x, e.x);
            v.y = fmaf(omg, w.y, e.y);
            v.z = fmaf(omg, w.z, e.z);
            v.w = fmaf(omg, w.w, e.w);
            *(float4*)&wg2[4*t] = v;
        }
        if (t == 0) {
            const int nl = c0 - 1;
            wg2[1025] = (nl >= 0)  ? fmaf(omg, wp[nl], ec[1025]) : 0.f;
            const int nr = c0 + 1024;
            wg2[1024] = (nr < NNv) ? fmaf(omg, wp[nr], ec[1024]) : 0.f;
        }
        __syncthreads();

        const float4 f   = *(const float4*)&wg2[4*t];
        const float left  = wg2[(t == 0) ? 1025 : 4*t - 1];
        const float right = wg2[4*t + 4];
        float4 o;
        o.x = fpow(fmaf(s0, left, fmaf(s1, f.x, s2*f.y)),  gm);
        o.y = fpow(fmaf(s0, f.x,  fmaf(s1, f.y, s2*f.z)),  gm);
        o.z = fpow(fmaf(s0, f.y,  fmaf(s1, f.z, s2*f.w)),  gm);
        o.w = fpow(fmaf(s0, f.z,  fmaf(s1, f.w, s2*right)), gm);
        *(float4*)&wo[c0 + 4*t] = o;

        red[t] = (o.x + o.y) + (o.z + o.w);
        __syncthreads();
        for (int off = 128; off; off >>= 1) { if (t < off) red[t] += red[t+off]; __syncthreads(); }
        if (t == 0)
            g_tpart[r*(Bz*CSPBLK) + b*CSPBLK + blockIdx.x] = red[0];
    }
}

// --- kernel 4: m1 = m0*(1 - W^T e) + W^T a   (W = wpow_w * inv_total) ------
__global__ void memupdate_kernel(const float* __restrict__ mem,
                                 const int* __restrict__ bank)
{
    const float* __restrict__ m0 = mem + (size_t)bank[0]*NNv*Mv;
    __shared__ __align__(16) float wsh[64*64];   // [k=b][n-local]
    __shared__ __align__(16) float es [64*64];   // [b][m] pre-scaled by inv_total
    __shared__ __align__(16) float as_[64*64];
    const int t = threadIdx.x;
    const int n0 = blockIdx.x * 64;
    const float inv = 1.f / (g_totals[0] + 1e-5f);

    for (int i = t; i < 64*64; i += 256) {
        int bb = i >> 6, nl = i & 63;
        wsh[i] = g_wpow_w[(size_t)bb*NNv + n0 + nl];
    }
    for (int i = t; i < 64*64; i += 256) { es[i] = g_ev[i]*inv; as_[i] = g_av[i]*inv; }
    __syncthreads();

    const int tn = t >> 4, tm = t & 15;   // 4 n x 4 m per thread
    float ce[4][4], ca[4][4];
    #pragma unroll
    for (int i = 0; i < 4; i++)
        #pragma unroll
        for (int j = 0; j < 4; j++) { ce[i][j] = 0.f; ca[i][j] = 0.f; }

    #pragma unroll 16
    for (int k = 0; k < 64; k++) {
        const float4 A  = *(const float4*)&wsh[k*64 + 4*tn];
        const float4 E4 = *(const float4*)&es [k*64 + 4*tm];
        const float4 A4 = *(const float4*)&as_[k*64 + 4*tm];
        float av[4] = {A.x, A.y, A.z, A.w};
        float ev[4] = {E4.x, E4.y, E4.z, E4.w};
        float aa[4] = {A4.x, A4.y, A4.z, A4.w};
        #pragma unroll
        for (int i = 0; i < 4; i++)
            #pragma unroll
            for (int j = 0; j < 4; j++) {
                ce[i][j] = fmaf(av[i], ev[j], ce[i][j]);
                ca[i][j] = fmaf(av[i], aa[j], ca[i][j]);
            }
    }

    #pragma unroll
    for (int i = 0; i < 4; i++) {
        const size_t n = (size_t)(n0 + 4*tn + i);
        const float4 o = *(const float4*)&m0[n*Mv + 4*tm];
        float4 v;
        v.x = o.x*(1.f - ce[i][0]) + ca[i][0];
        v.y = o.y*(1.f - ce[i][1]) + ca[i][1];
        v.z = o.z*(1.f - ce[i][2]) + ca[i][2];
        v.w = o.w*(1.f - ce[i][3]) + ca[i][3];
        *(float4*)&g_m1[n*Mv + 4*tm] = v;
    }
}

// ----- kernel 5: split-K read einsum partials (bf16 WMMA tensor cores) -----
// C[64 b][64 m] += A[b][k=n] * B[k=n][m] over EK n's, fp32 accumulate.
// 8 warps: warp w owns C tiles (row w>>1, cols (w&1)*2 .. +1) of 16x16.
__global__ void einsum_kernel()
{
    __shared__ __align__(16) __nv_bfloat16 ash[64*72];  // [b][k], ld=72
    __shared__ __align__(16) __nv_bfloat16 bsh[64*72];  // [k][m], ld=72
    const int chunk = blockIdx.x, r = blockIdx.y;
    const int n0 = chunk * EK;
    const int t = threadIdx.x;
    const int warp  = t >> 5;
    const int trow  = warp >> 1;          // b-tile: 0..3  -> b0 = trow*16
    const int tcol0 = (warp & 1) * 2;     // m-tiles: {0,1} or {2,3}

    wmma::fragment<wmma::accumulator, 16, 16, 16, float> acc0, acc1;
    wmma::fill_fragment(acc0, 0.f);
    wmma::fill_fragment(acc1, 0.f);

    for (int sub = 0; sub < EK/64; sub++) {
        const int nb = n0 + sub*64;
        for (int i = t; i < 64*64; i += 256) {
            const int bb = i >> 6, kk = i & 63;
            ash[bb*72 + kk] =
                __float2bfloat16(g_wpow_r[((size_t)r*Bz + bb)*NNv + nb + kk]);
        }
        for (int i = t; i < 64*64; i += 256) {
            const int kk = i >> 6, mm = i & 63;
            bsh[kk*72 + mm] = __float2bfloat16(g_m1[(size_t)(nb + kk)*Mv + mm]);
        }
        __syncthreads();

        #pragma unroll
        for (int kt = 0; kt < 4; kt++) {
            wmma::fragment<wmma::matrix_a, 16, 16, 16, __nv_bfloat16,
                           wmma::row_major> fa;
            wmma::load_matrix_sync(fa, &ash[(trow*16)*72 + kt*16], 72);
            wmma::fragment<wmma::matrix_b, 16, 16, 16, __nv_bfloat16,
                           wmma::row_major> fb0, fb1;
            wmma::load_matrix_sync(fb0, &bsh[(kt*16)*72 + (tcol0    )*16], 72);
            wmma::load_matrix_sync(fb1, &bsh[(kt*16)*72 + (tcol0 + 1)*16], 72);
            wmma::mma_sync(acc0, fa, fb0, acc0);
            wmma::mma_sync(acc1, fa, fb1, acc1);
        }
        __syncthreads();
    }

    const size_t base = ((size_t)r*ECHUNK + chunk) * (Bz*Mv);
    wmma::store_matrix_sync(&g_epart[base + (size_t)(trow*16)*Mv + (tcol0    )*16],
                            acc0, Mv, wmma::mem_row_major);
    wmma::store_matrix_sync(&g_epart[base + (size_t)(trow*16)*Mv + (tcol0 + 1)*16],
                            acc1, Mv, wmma::mem_row_major);
}

// ----- kernel 6: reduce split-K + apply 1/(total_r+eps) + transpose --------
__global__ void reduce_out_kernel(float* __restrict__ out)
{
    const int gid = blockIdx.x*256 + threadIdx.x;   // 0..R*B*M-1
    const int r = gid >> 12;
    const int b = (gid >> 6) & 63;
    const int m = gid & 63;
    const float inv = 1.f / (g_totals[1 + r] + 1e-5f);
    float s = 0.f;
    for (int c = 0; c < ECHUNK; c++)
        s += g_epart[(((size_t)r*ECHUNK + c)*Bz + b)*Mv + m];
    out[(size_t)b*(Rv*Mv) + r*Mv + m] = s * inv;
}

// ---------------------------------------------------------------------------
extern "C" void kernel_launch(void* const* d_in, const int* in_sizes, int n_in,
                              void* d_out, int out_size)
{
    const float* h_t     = (const float*)d_in[0];
    const float* ww      = (const float*)d_in[1];
    const float* wr      = (const float*)d_in[2];
    const float* memory  = (const float*)d_in[3];
    const float* key_w   = (const float*)d_in[4];
    const float* key_b   = (const float*)d_in[5];
    const float* beta_w  = (const float*)d_in[6];
    const float* beta_b  = (const float*)d_in[7];
    const float* gate_w  = (const float*)d_in[8];
    const float* gate_b  = (const float*)d_in[9];
    const float* shift_w = (const float*)d_in[10];
    const float* shift_b = (const float*)d_in[11];
    const float* gamma_w = (const float*)d_in[12];
    const float* gamma_b = (const float*)d_in[13];
    const float* erase_w = (const float*)d_in[14];
    const float* erase_b = (const float*)d_in[15];
    const float* add_w   = (const float*)d_in[16];
    const float* add_b   = (const float*)d_in[17];
    const int*   bank    = (const int*)d_in[18];
    float* out = (float*)d_out;

    // head params (shared by all 5 weight updates)
    heads_kernel<<<Bz, 256>>>(h_t, key_w, key_b, beta_w, beta_b, gate_w, gate_b,
                              shift_w, shift_b, gamma_w, gamma_b,
                              erase_w, erase_b, add_w, add_b);

    // --- write head: content addressing on m0 ---
    sim_kernel<<<SIMBLK, 256>>>(memory, bank, 0);
    reduce_sumexp_kernel<<<Bz, 256>>>();
    csp_write_kernel<<<dim3(CSPBLK, Bz), 256>>>(ww);
    reduce_total_kernel<<<1, 256>>>(0);

    // --- memory erase/add ---
    memupdate_kernel<<<NNv/64, 256>>>(memory, bank);

    // --- read heads: shared content addressing on m1, all R heads/block ---
    sim_kernel<<<SIMBLK, 256>>>(memory, bank, 1);
    reduce_sumexp_kernel<<<Bz, 256>>>();
    csp_read_kernel<<<dim3(CSPBLK, Bz), 256>>>(wr);
    reduce_total_kernel<<<Rv, 256>>>(1);

    // --- read: r[r,b,:] = (wpow_r[r,b,:]/total_r) @ m1 ---
    einsum_kernel<<<dim3(ECHUNK, Rv), 256>>>();
    reduce_out_kernel<<<(Rv*Bz*Mv)/256, 256>>>(out);
}

// round 12
// speedup vs baseline: 1.7421x; 1.0062x over previous
#include <cuda_runtime.h>
#include <cuda_bf16.h>
#include <mma.h>
#include <math.h>

using namespace nvcuda;

#define Bz 64
#define Hh 1024
#define NNv 65536
#define Mv 64
#define Rv 4
#define SIMBLK (NNv/64)   /* 1024 sim blocks */
#define CSPBLK 64         /* N/1024 csp blocks per b */
#define ECHUNK 128        /* einsum split-K chunks */
#define EK (NNv/ECHUNK)   /* 512 n per chunk */

// ---------------- scratch (device globals: no allocation allowed) ----------
__device__ float g_E[(size_t)Bz*NNv];            // exp(beta*sim) buffer [B,N]
__device__ float g_wpow_w[(size_t)Bz*NNv];       // write-head w_pow
__device__ float g_wpow_r[(size_t)Rv*Bz*NNv];    // read-head w_pow [R,B,N]
__device__ float g_m1[(size_t)NNv*Mv];           // updated memory
__device__ float g_kn[Bz*Mv];
__device__ float g_ev[Bz*Mv];
__device__ float g_av[Bz*Mv];
__device__ float g_beta[Bz];
__device__ float g_gate[Bz];
__device__ float g_gamma[Bz];
__device__ float g_shift[Bz*3];
__device__ float g_psum[(size_t)Bz*SIMBLK];      // per-block exp partial sums
__device__ float g_sumexp[Bz];
__device__ float g_tpart[Rv*Bz*CSPBLK];          // per-block pow partial sums
__device__ float g_totals[1+Rv];                 // [0]=write total, [1..4]=read totals
__device__ float g_epart[(size_t)Rv*ECHUNK*Bz*Mv]; // einsum split-K partials

__device__ __forceinline__ float clip01(float x){ return fminf(fmaxf(x, 0.f), 1.f); }
// fast x^g for x > 0 (w_tilde strictly positive: gated softmax mix, s_j > 0)
__device__ __forceinline__ float fpow(float x, float g){ return __expf(g * __logf(x)); }

// ---------------- kernel 1: head projections (once per step) ---------------
__global__ void heads_kernel(const float* __restrict__ h,
    const float* __restrict__ key_w,   const float* __restrict__ key_b,
    const float* __restrict__ beta_w,  const float* __restrict__ beta_b,
    const float* __restrict__ gate_w,  const float* __restrict__ gate_b,
    const float* __restrict__ shift_w, const float* __restrict__ shift_b,
    const float* __restrict__ gamma_w, const float* __restrict__ gamma_b,
    const float* __restrict__ erase_w, const float* __restrict__ erase_b,
    const float* __restrict__ add_w,   const float* __restrict__ add_b)
{
    __shared__ float hs[Hh];
    __shared__ float ksh[Mv];
    __shared__ float sdot[6];
    __shared__ float sinv;
    const int b = blockIdx.x, t = threadIdx.x;
    for (int i = t; i < Hh; i += 256) hs[i] = h[(size_t)b*Hh + i];
    __syncthreads();

    if (t < 64) {
        float a0=0,a1=0,a2=0,a3=0;
        for (int j = 0; j < Hh; j += 4) {
            a0 = fmaf(hs[j  ], key_w[(j  )*Mv + t], a0);
            a1 = fmaf(hs[j+1], key_w[(j+1)*Mv + t], a1);
            a2 = fmaf(hs[j+2], key_w[(j+2)*Mv + t], a2);
            a3 = fmaf(hs[j+3], key_w[(j+3)*Mv + t], a3);
        }
        ksh[t] = clip01(a0+a1+a2+a3 + key_b[t]);
    } else if (t < 128) {
        const int m = t - 64;
        float a0=0,a1=0,a2=0,a3=0;
        for (int j = 0; j < Hh; j += 4) {
            a0 = fmaf(hs[j  ], erase_w[(j  )*Mv + m], a0);
            a1 = fmaf(hs[j+1], erase_w[(j+1)*Mv + m], a1);
            a2 = fmaf(hs[j+2], erase_w[(j+2)*Mv + m], a2);
            a3 = fmaf(hs[j+3], erase_w[(j+3)*Mv + m], a3);
        }
        g_ev[b*Mv + m] = clip01(a0+a1+a2+a3 + erase_b[m]);
    } else if (t < 192) {
        const int m = t - 128;
        float a0=0,a1=0,a2=0,a3=0;
        for (int j = 0; j < Hh; j += 4) {
            a0 = fmaf(hs[j  ], add_w[(j  )*Mv + m], a0);
            a1 = fmaf(hs[j+1], add_w[(j+1)*Mv + m], a1);
            a2 = fmaf(hs[j+2], add_w[(j+2)*Mv + m], a2);
            a3 = fmaf(hs[j+3], add_w[(j+3)*Mv + m], a3);
        }
        // relu then clip01 == clip01
        g_av[b*Mv + m] = clip01(a0+a1+a2+a3 + add_b[m]);
    } else if (t < 198) {
        const int d = t - 192;
        const float* w; int str, col;
        if      (d == 0) { w = beta_w;  str = 1; col = 0; }
        else if (d == 1) { w = gate_w;  str = 1; col = 0; }
        else if (d == 2) { w = gamma_w; str = 1; col = 0; }
        else             { w = shift_w; str = 3; col = d - 3; }
        float a0=0,a1=0;
        for (int j = 0; j < Hh; j += 2) {
            a0 = fmaf(hs[j  ], w[(j  )*str + col], a0);
            a1 = fmaf(hs[j+1], w[(j+1)*str + col], a1);
        }
        sdot[d] = a0 + a1;
    }
    __syncthreads();

    if (t < 32) {
        float v = ksh[t]*ksh[t] + ksh[t+32]*ksh[t+32];
        #pragma unroll
        for (int off = 16; off; off >>= 1) v += __shfl_xor_sync(0xffffffffu, v, off);
        if (t == 0) sinv = 1.f / (sqrtf(v) + 1e-8f);
    }
    __syncthreads();
    if (t < 64) g_kn[b*Mv + t] = ksh[t] * sinv;
    if (t == 0) {
        g_beta[b]  = fmaxf(sdot[0] + beta_b[0], 0.f);
        g_gate[b]  = clip01(sdot[1] + gate_b[0]);
        g_gamma[b] = 1.f + fmaxf(sdot[2] + gamma_b[0], 0.f);
        float x0 = sdot[3] + shift_b[0];
        float x1 = sdot[4] + shift_b[1];
        float x2 = sdot[5] + shift_b[2];
        float mx = fmaxf(x0, fmaxf(x1, x2));
        float e0 = expf(x0-mx), e1 = expf(x1-mx), e2 = expf(x2-mx);
        float is = 1.f / (e0+e1+e2);
        g_shift[b*3+0] = e0*is; g_shift[b*3+1] = e1*is; g_shift[b*3+2] = e2*is;
    }
}

// ------- kernel 2: E[b,n] = exp(beta[b] * (kn[b]·m[n]) / (||m[n]||+eps)) ---
// tf32 WMMA version. A = g_kn [b][k] straight from global (ld=64),
// B = staged m-tile transposed [k][n] (ld=68). Acc -> smem -> exp epilogue.
__global__ void sim_kernel(const float* __restrict__ mem,
                           const int* __restrict__ bank, int use_m1)
{
    const float* __restrict__ src = use_m1 ? g_m1
                                           : (mem + (size_t)bank[0]*NNv*Mv);
    __shared__ __align__(16) float mt[64*68];   // [k][n], padded
    __shared__ __align__(16) float cs[64*68];   // [b][n] raw sim (k-dot)
    __shared__ float invn[64];
    __shared__ float sbeta[64];
    const int t = threadIdx.x;
    const int n0 = blockIdx.x * 64;

    for (int i = t; i < 64*64; i += 256) {
        int rr = i >> 6, cc = i & 63;
        mt[cc*68 + rr] = src[(size_t)(n0 + rr)*Mv + cc];
    }
    if (t < 64) sbeta[t] = g_beta[t];
    __syncthreads();
    if (t < 64) {
        float s = 0.f;
        #pragma unroll 16
        for (int k = 0; k < 64; k++) { float v = mt[k*68 + t]; s = fmaf(v, v, s); }
        invn[t] = 1.f / (sqrtf(s) + 1e-8f);
    }

    // WMMA: C[64b][64n] = kn[64b][64k] @ mt[64k][64n]
    const int warp  = t >> 5;
    const int brow  = warp >> 1;        // b-tile 0..3
    const int ncol0 = (warp & 1) * 2;   // n-tiles {0,1} or {2,3}
    wmma::fragment<wmma::accumulator, 16, 16, 8, float> acc0, acc1;
    wmma::fill_fragment(acc0, 0.f);
    wmma::fill_fragment(acc1, 0.f);
    #pragma unroll
    for (int kt = 0; kt < 8; kt++) {
        wmma::fragment<wmma::matrix_a, 16, 16, 8, wmma::precision::tf32,
                       wmma::row_major> fa;
        wmma::load_matrix_sync(fa, &g_kn[(brow*16)*Mv + kt*8], Mv);
        #pragma unroll
        for (int i = 0; i < fa.num_elements; i++)
            fa.x[i] = wmma::__float_to_tf32(fa.x[i]);
        wmma::fragment<wmma::matrix_b, 16, 16, 8, wmma::precision::tf32,
                       wmma::row_major> fb0, fb1;
        wmma::load_matrix_sync(fb0, &mt[(kt*8)*68 + (ncol0    )*16], 68);
        wmma::load_matrix_sync(fb1, &mt[(kt*8)*68 + (ncol0 + 1)*16], 68);
        #pragma unroll
        for (int i = 0; i < fb0.num_elements; i++) {
            fb0.x[i] = wmma::__float_to_tf32(fb0.x[i]);
            fb1.x[i] = wmma::__float_to_tf32(fb1.x[i]);
        }
        wmma::mma_sync(acc0, fa, fb0, acc0);
        wmma::mma_sync(acc1, fa, fb1, acc1);
    }
    wmma::store_matrix_sync(&cs[(brow*16)*68 + (ncol0    )*16], acc0, 68,
                            wmma::mem_row_major);
    wmma::store_matrix_sync(&cs[(brow*16)*68 + (ncol0 + 1)*16], acc1, 68,
                            wmma::mem_row_major);
    __syncthreads();

    // epilogue: scale by invn, exp, write, per-b partial sums
    const int by = t >> 5, nx = t & 31;   // 8 b's per thread, 2 n's per thread
    const float2 iv = *(const float2*)&invn[2*nx];
    float psum[8];
    #pragma unroll
    for (int bi = 0; bi < 8; bi++) {
        const int bb = 8*by + bi;
        const float bt = sbeta[bb];
        const float2 cv = *(const float2*)&cs[bb*68 + 2*nx];
        float e0 = __expf(bt * cv.x * iv.x);
        float e1 = __expf(bt * cv.y * iv.y);
        *(float2*)&g_E[(size_t)bb*NNv + n0 + 2*nx] = make_float2(e0, e1);
        psum[bi] = e0 + e1;
    }
    #pragma unroll
    for (int bi = 0; bi < 8; bi++)
        #pragma unroll
        for (int off = 16; off; off >>= 1)
            psum[bi] += __shfl_xor_sync(0xffffffffu, psum[bi], off);
    if (nx == 0) {
        #pragma unroll
        for (int bi = 0; bi < 8; bi++)
            g_psum[(size_t)(8*by + bi)*SIMBLK + blockIdx.x] = psum[bi];
    }
}

// ---------------- deterministic reductions ---------------------------------
__global__ void reduce_sumexp_kernel()
{
    const int b = blockIdx.x, t = threadIdx.x;
    float s = 0.f;
    for (int i = t; i < SIMBLK; i += 256) s += g_psum[(size_t)b*SIMBLK + i];
    __shared__ float red[256];
    red[t] = s; __syncthreads();
    for (int off = 128; off; off >>= 1) { if (t < off) red[t] += red[t+off]; __syncthreads(); }
    if (t == 0) g_sumexp[b] = red[0];
}

__global__ void reduce_total_kernel(int out_off)
{
    const int seg = blockIdx.x, t = threadIdx.x;
    float s = 0.f;
    for (int i = t; i < Bz*CSPBLK; i += 256) s += g_tpart[seg*(Bz*CSPBLK) + i];
    __shared__ float red[256];
    red[t] = s; __syncthreads();
    for (int off = 128; off; off >>= 1) { if (t < off) red[t] += red[t+off]; __syncthreads(); }
    if (t == 0) g_totals[out_off + seg] = red[0];
}

// ----- kernel 3a: WRITE head csp (vectorized) -------------------------------
__global__ void csp_write_kernel(const float* __restrict__ ww)
{
    const int b  = blockIdx.y;
    const int c0 = blockIdx.x * 1024;
    const float* __restrict__ wp = ww + (size_t)b*NNv;
    float* __restrict__ wo = g_wpow_w + (size_t)b*NNv;
    const float* __restrict__ Eb = g_E + (size_t)b*NNv;

    __shared__ __align__(16) float wg2[1032];
    __shared__ __align__(16) float red[256];
    const float gg   = g_gate[b];
    const float invS = gg / g_sumexp[b];   // gate folded into content scale
    const float omg  = 1.f - gg;
    const float s0 = g_shift[b*3+0], s1 = g_shift[b*3+1], s2 = g_shift[b*3+2];
    const float gm = g_gamma[b];
    const int t = threadIdx.x;

    {
        const int n = c0 + 4*t;
        const float4 e = *(const float4*)&Eb[n];
        const float4 w = *(const float4*)&wp[n];
        float4 v;
        v.x = fmaf(omg, w.x, e.x*invS);
        v.y = fmaf(omg, w.y, e.y*invS);
        v.z = fmaf(omg, w.z, e.z*invS);
        v.w = fmaf(omg, w.w, e.w*invS);
        *(float4*)&wg2[4*t] = v;
    }
    if (t == 0) {
        const int nl = c0 - 1;
        wg2[1025] = (nl >= 0)  ? fmaf(omg, wp[nl], Eb[nl]*invS) : 0.f;
        const int nr = c0 + 1024;
        wg2[1024] = (nr < NNv) ? fmaf(omg, wp[nr], Eb[nr]*invS) : 0.f;
    }
    __syncthreads();

    const float4 f   = *(const float4*)&wg2[4*t];
    const float left  = wg2[(t == 0) ? 1025 : 4*t - 1];
    const float right = wg2[4*t + 4];   // t==255 lands on wg2[1024] = halo
    float4 o;
    o.x = fpow(fmaf(s0, left, fmaf(s1, f.x, s2*f.y)),  gm);
    o.y = fpow(fmaf(s0, f.x,  fmaf(s1, f.y, s2*f.z)),  gm);
    o.z = fpow(fmaf(s0, f.y,  fmaf(s1, f.z, s2*f.w)),  gm);
    o.w = fpow(fmaf(s0, f.z,  fmaf(s1, f.w, s2*right)), gm);
    *(float4*)&wo[c0 + 4*t] = o;

    red[t] = (o.x + o.y) + (o.z + o.w);
    __syncthreads();
    for (int off = 128; off; off >>= 1) { if (t < off) red[t] += red[t+off]; __syncthreads(); }
    if (t == 0) g_tpart[b*CSPBLK + blockIdx.x] = red[0];
}

// ----- kernel 3b: READ heads csp (vectorized, all R heads per block) --------
__global__ void csp_read_kernel(const float* __restrict__ wr)
{
    const int b  = blockIdx.y;
    const int c0 = blockIdx.x * 1024;
    const float* __restrict__ Eb = g_E + (size_t)b*NNv;

    __shared__ __align__(16) float ec [1032];   // same halo layout as wg2
    __shared__ __align__(16) float wg2[1032];
    __shared__ __align__(16) float red[256];
    const float gg   = g_gate[b];
    const float omg  = 1.f - gg;
    const float invS = gg / g_sumexp[b];
    const float s0 = g_shift[b*3+0], s1 = g_shift[b*3+1], s2 = g_shift[b*3+2];
    const float gm = g_gamma[b];
    const int t = threadIdx.x;

    {
        const int n = c0 + 4*t;
        const float4 e = *(const float4*)&Eb[n];
        float4 v;
        v.x = e.x*invS; v.y = e.y*invS; v.z = e.z*invS; v.w = e.w*invS;
        *(float4*)&ec[4*t] = v;
    }
    if (t == 0) {
        const int nl = c0 - 1;
        ec[1025] = (nl >= 0)  ? Eb[nl]*invS : 0.f;
        const int nr = c0 + 1024;
        ec[1024] = (nr < NNv) ? Eb[nr]*invS : 0.f;
    }

    #pragma unroll
    for (int r = 0; r < Rv; r++) {
        const size_t head_off = ((size_t)r*Bz + b) * NNv;
        const float* __restrict__ wp = wr + head_off;
        float* __restrict__ wo = g_wpow_r + head_off;

        __syncthreads();   // ec ready (r==0) / prior-r wg2 consumers done
        {
            const int n = c0 + 4*t;
            const float4 w = *(const float4*)&wp[n];
            const float4 e = *(const float4*)&ec[4*t];
            float4 v;
            v.x = fmaf(omg, w.x, e.x);
            v.y = fmaf(omg, w.y, e.y);
            v.z = fmaf(omg, w.z, e.z);
            v.w = fmaf(omg, w.w, e.w);
            *(float4*)&wg2[4*t] = v;
        }
        if (t == 0) {
            const int nl = c0 - 1;
            wg2[1025] = (nl >= 0)  ? fmaf(omg, wp[nl], ec[1025]) : 0.f;
            const int nr = c0 + 1024;
            wg2[1024] = (nr < NNv) ? fmaf(omg, wp[nr], ec[1024]) : 0.f;
        }
        __syncthreads();

        const float4 f   = *(const float4*)&wg2[4*t];
        const float left  = wg2[(t == 0) ? 1025 : 4*t - 1];
        const float right = wg2[4*t + 4];
        float4 o;
        o.x = fpow(fmaf(s0, left, fmaf(s1, f.x, s2*f.y)),  gm);
        o.y = fpow(fmaf(s0, f.x,  fmaf(s1, f.y, s2*f.z)),  gm);
        o.z = fpow(fmaf(s0, f.y,  fmaf(s1, f.z, s2*f.w)),  gm);
        o.w = fpow(fmaf(s0, f.z,  fmaf(s1, f.w, s2*right)), gm);
        *(float4*)&wo[c0 + 4*t] = o;

        red[t] = (o.x + o.y) + (o.z + o.w);
        __syncthreads();
        for (int off = 128; off; off >>= 1) { if (t < off) red[t] += red[t+off]; __syncthreads(); }
        if (t == 0)
            g_tpart[r*(Bz*CSPBLK) + b*CSPBLK + blockIdx.x] = red[0];
    }
}

// --- kernel 4: m1 = m0*(1 - W^T e) + W^T a  (tf32 WMMA) ---------------------
// A col_major: (row=n, col=b) at wsh[b*64+n] — the existing staging layout.
// B row_major: es/as_ [b][m], ld=64. Accumulators alias wsh/es after sync.
__global__ void memupdate_kernel(const float* __restrict__ mem,
                                 const int* __restrict__ bank)
{
    const float* __restrict__ m0 = mem + (size_t)bank[0]*NNv*Mv;
    __shared__ __align__(16) float wsh[64*64];   // [b][n] -> A col_major
    __shared__ __align__(16) float es [64*64];   // [b][m] pre-scaled
    __shared__ __align__(16) float as_[64*64];
    const int t = threadIdx.x;
    const int n0 = blockIdx.x * 64;
    const float inv = 1.f / (g_totals[0] + 1e-5f);

    for (int i = t; i < 64*64; i += 256) {
        int bb = i >> 6, nl = i & 63;
        wsh[i] = g_wpow_w[(size_t)bb*NNv + n0 + nl];
    }
    for (int i = t; i < 64*64; i += 256) { es[i] = g_ev[i]*inv; as_[i] = g_av[i]*inv; }
    __syncthreads();

    const int warp  = t >> 5;
    const int nrow  = warp >> 1;        // n-tile 0..3
    const int mcol0 = (warp & 1) * 2;   // m-tiles {0,1} or {2,3}
    wmma::fragment<wmma::accumulator, 16, 16, 8, float> ce0, ce1, ca0, ca1;
    wmma::fill_fragment(ce0, 0.f); wmma::fill_fragment(ce1, 0.f);
    wmma::fill_fragment(ca0, 0.f); wmma::fill_fragment(ca1, 0.f);

    #pragma unroll
    for (int kt = 0; kt < 8; kt++) {
        wmma::fragment<wmma::matrix_a, 16, 16, 8, wmma::precision::tf32,
                       wmma::col_major> fa;
        wmma::load_matrix_sync(fa, &wsh[(kt*8)*64 + nrow*16], 64);
        #pragma unroll
        for (int i = 0; i < fa.num_elements; i++)
            fa.x[i] = wmma::__float_to_tf32(fa.x[i]);
        wmma::fragment<wmma::matrix_b, 16, 16, 8, wmma::precision::tf32,
                       wmma::row_major> fe0, fe1, fd0, fd1;
        wmma::load_matrix_sync(fe0, &es [(kt*8)*64 + (mcol0    )*16], 64);
        wmma::load_matrix_sync(fe1, &es [(kt*8)*64 + (mcol0 + 1)*16], 64);
        wmma::load_matrix_sync(fd0, &as_[(kt*8)*64 + (mcol0    )*16], 64);
        wmma::load_matrix_sync(fd1, &as_[(kt*8)*64 + (mcol0 + 1)*16], 64);
        #pragma unroll
        for (int i = 0; i < fe0.num_elements; i++) {
            fe0.x[i] = wmma::__float_to_tf32(fe0.x[i]);
            fe1.x[i] = wmma::__float_to_tf32(fe1.x[i]);
            fd0.x[i] = wmma::__float_to_tf32(fd0.x[i]);
            fd1.x[i] = wmma::__float_to_tf32(fd1.x[i]);
        }
        wmma::mma_sync(ce0, fa, fe0, ce0);
        wmma::mma_sync(ce1, fa, fe1, ce1);
        wmma::mma_sync(ca0, fa, fd0, ca0);
        wmma::mma_sync(ca1, fa, fd1, ca1);
    }
    __syncthreads();   // all warps done reading wsh/es before acc overwrite

    float* ce_s = wsh;   // alias: [n][m] ld=64
    float* ca_s = es;
    wmma::store_matrix_sync(&ce_s[(nrow*16)*64 + (mcol0    )*16], ce0, 64,
                            wmma::mem_row_major);
    wmma::store_matrix_sync(&ce_s[(nrow*16)*64 + (mcol0 + 1)*16], ce1, 64,
                            wmma::mem_row_major);
    wmma::store_matrix_sync(&ca_s[(nrow*16)*64 + (mcol0    )*16], ca0, 64,
                            wmma::mem_row_major);
    wmma::store_matrix_sync(&ca_s[(nrow*16)*64 + (mcol0 + 1)*16], ca1, 64,
                            wmma::mem_row_major);
    __syncthreads();

    #pragma unroll
    for (int j = 0; j < 4; j++) {
        const int idx = j*1024 + 4*t;          // element index in 64x64 tile
        const int nl = idx >> 6, mm = idx & 63;
        const size_t n = (size_t)(n0 + nl);
        const float4 o  = *(const float4*)&m0  [n*Mv + mm];
        const float4 ce = *(const float4*)&ce_s[nl*64 + mm];
        const float4 ca = *(const float4*)&ca_s[nl*64 + mm];
        float4 v;
        v.x = o.x*(1.f - ce.x) + ca.x;
        v.y = o.y*(1.f - ce.y) + ca.y;
        v.z = o.z*(1.f - ce.z) + ca.z;
        v.w = o.w*(1.f - ce.w) + ca.w;
        *(float4*)&g_m1[n*Mv + mm] = v;
    }
}

// ----- kernel 5: split-K read einsum partials (bf16 WMMA tensor cores) -----
__global__ void einsum_kernel()
{
    __shared__ __align__(16) __nv_bfloat16 ash[64*72];  // [b][k], ld=72
    __shared__ __align__(16) __nv_bfloat16 bsh[64*72];  // [k][m], ld=72
    const int chunk = blockIdx.x, r = blockIdx.y;
    const int n0 = chunk * EK;
    const int t = threadIdx.x;
    const int warp  = t >> 5;
    const int trow  = warp >> 1;          // b-tile: 0..3
    const int tcol0 = (warp & 1) * 2;     // m-tiles: {0,1} or {2,3}

    wmma::fragment<wmma::accumulator, 16, 16, 16, float> acc0, acc1;
    wmma::fill_fragment(acc0, 0.f);
    wmma::fill_fragment(acc1, 0.f);

    for (int sub = 0; sub < EK/64; sub++) {
        const int nb = n0 + sub*64;
        for (int i = t; i < 64*64; i += 256) {
            const int bb = i >> 6, kk = i & 63;
            ash[bb*72 + kk] =
                __float2bfloat16(g_wpow_r[((size_t)r*Bz + bb)*NNv + nb + kk]);
        }
        for (int i = t; i < 64*64; i += 256) {
            const int kk = i >> 6, mm = i & 63;
            bsh[kk*72 + mm] = __float2bfloat16(g_m1[(size_t)(nb + kk)*Mv + mm]);
        }
        __syncthreads();

        #pragma unroll
        for (int kt = 0; kt < 4; kt++) {
            wmma::fragment<wmma::matrix_a, 16, 16, 16, __nv_bfloat16,
                           wmma::row_major> fa;
            wmma::load_matrix_sync(fa, &ash[(trow*16)*72 + kt*16], 72);
            wmma::fragment<wmma::matrix_b, 16, 16, 16, __nv_bfloat16,
                           wmma::row_major> fb0, fb1;
            wmma::load_matrix_sync(fb0, &bsh[(kt*16)*72 + (tcol0    )*16], 72);
            wmma::load_matrix_sync(fb1, &bsh[(kt*16)*72 + (tcol0 + 1)*16], 72);
            wmma::mma_sync(acc0, fa, fb0, acc0);
            wmma::mma_sync(acc1, fa, fb1, acc1);
        }
        __syncthreads();
    }

    const size_t base = ((size_t)r*ECHUNK + chunk) * (Bz*Mv);
    wmma::store_matrix_sync(&g_epart[base + (size_t)(trow*16)*Mv + (tcol0    )*16],
                            acc0, Mv, wmma::mem_row_major);
    wmma::store_matrix_sync(&g_epart[base + (size_t)(trow*16)*Mv + (tcol0 + 1)*16],
                            acc1, Mv, wmma::mem_row_major);
}

// ----- kernel 6: reduce split-K + apply 1/(total_r+eps) + transpose --------
__global__ void reduce_out_kernel(float* __restrict__ out)
{
    const int gid = blockIdx.x*256 + threadIdx.x;   // 0..R*B*M-1
    const int r = gid >> 12;
    const int b = (gid >> 6) & 63;
    const int m = gid & 63;
    const float inv = 1.f / (g_totals[1 + r] + 1e-5f);
    float s = 0.f;
    for (int c = 0; c < ECHUNK; c++)
        s += g_epart[(((size_t)r*ECHUNK + c)*Bz + b)*Mv + m];
    out[(size_t)b*(Rv*Mv) + r*Mv + m] = s * inv;
}

// ---------------------------------------------------------------------------
extern "C" void kernel_launch(void* const* d_in, const int* in_sizes, int n_in,
                              void* d_out, int out_size)
{
    const float* h_t     = (const float*)d_in[0];
    const float* ww      = (const float*)d_in[1];
    const float* wr      = (const float*)d_in[2];
    const float* memory  = (const float*)d_in[3];
    const float* key_w   = (const float*)d_in[4];
    const float* key_b   = (const float*)d_in[5];
    const float* beta_w  = (const float*)d_in[6];
    const float* beta_b  = (const float*)d_in[7];
    const float* gate_w  = (const float*)d_in[8];
    const float* gate_b  = (const float*)d_in[9];
    const float* shift_w = (const float*)d_in[10];
    const float* shift_b = (const float*)d_in[11];
    const float* gamma_w = (const float*)d_in[12];
    const float* gamma_b = (const float*)d_in[13];
    const float* erase_w = (const float*)d_in[14];
    const float* erase_b = (const float*)d_in[15];
    const float* add_w   = (const float*)d_in[16];
    const float* add_b   = (const float*)d_in[17];
    const int*   bank    = (const int*)d_in[18];
    float* out = (float*)d_out;

    // head params (shared by all 5 weight updates)
    heads_kernel<<<Bz, 256>>>(h_t, key_w, key_b, beta_w, beta_b, gate_w, gate_b,
                              shift_w, shift_b, gamma_w, gamma_b,
                              erase_w, erase_b, add_w, add_b);

    // --- write head: content addressing on m0 ---
    sim_kernel<<<SIMBLK, 256>>>(memory, bank, 0);
    reduce_sumexp_kernel<<<Bz, 256>>>();
    csp_write_kernel<<<dim3(CSPBLK, Bz), 256>>>(ww);
    reduce_total_kernel<<<1, 256>>>(0);

    // --- memory erase/add ---
    memupdate_kernel<<<NNv/64, 256>>>(memory, bank);

    // --- read heads: shared content addressing on m1, all R heads/block ---
    sim_kernel<<<SIMBLK, 256>>>(memory, bank, 1);
    reduce_sumexp_kernel<<<Bz, 256>>>();
    csp_read_kernel<<<dim3(CSPBLK, Bz), 256>>>(wr);
    reduce_total_kernel<<<Rv, 256>>>(1);

    // --- read: r[r,b,:] = (wpow_r[r,b,:]/total_r) @ m1 ---
    einsum_kernel<<<dim3(ECHUNK, Rv), 256>>>();
    reduce_out_kernel<<<(Rv*Bz*Mv)/256, 256>>>(out);
}

// round 13
// speedup vs baseline: 1.7998x; 1.0331x over previous
#include <cuda_runtime.h>
#include <cuda_bf16.h>
#include <mma.h>
#include <math.h>

using namespace nvcuda;

#define Bz 64
#define Hh 1024
#define NNv 65536
#define Mv 64
#define Rv 4
#define SIMBLK (NNv/64)   /* 1024 sim blocks */
#define CSPBLK 64         /* N/1024 csp blocks per b */
#define ECHUNK 128        /* einsum split-K chunks */
#define EK (NNv/ECHUNK)   /* 512 n per chunk */

// ---------------- scratch (device globals: no allocation allowed) ----------
__device__ __nv_bfloat16 g_E[(size_t)Bz*NNv];       // exp(beta*sim) [B,N] bf16
__device__ float g_wpow_w[(size_t)Bz*NNv];          // write-head w_pow (fp32)
__device__ __nv_bfloat16 g_wpow_r[(size_t)Rv*Bz*NNv]; // read-head w_pow bf16
__device__ float g_m1[(size_t)NNv*Mv];              // updated memory
__device__ float g_kn[Bz*Mv];
__device__ float g_ev[Bz*Mv];
__device__ float g_av[Bz*Mv];
__device__ float g_beta[Bz];
__device__ float g_gate[Bz];
__device__ float g_gamma[Bz];
__device__ float g_shift[Bz*3];
__device__ float g_psum[(size_t)Bz*SIMBLK];         // per-block exp partial sums
__device__ float g_sumexp[Bz];
__device__ float g_tpart[Rv*Bz*CSPBLK];             // per-block pow partial sums
__device__ float g_totals[1+Rv];                    // [0]=write, [1..4]=read totals
__device__ float g_epart[(size_t)Rv*ECHUNK*Bz*Mv];  // einsum split-K partials

__device__ __forceinline__ float clip01(float x){ return fminf(fmaxf(x, 0.f), 1.f); }
// fast x^g for x > 0 (w_tilde strictly positive: gated softmax mix, s_j > 0)
__device__ __forceinline__ float fpow(float x, float g){ return __expf(g * __logf(x)); }

// ---------------- kernel 1: head projections (once per step) ---------------
__global__ void heads_kernel(const float* __restrict__ h,
    const float* __restrict__ key_w,   const float* __restrict__ key_b,
    const float* __restrict__ beta_w,  const float* __restrict__ beta_b,
    const float* __restrict__ gate_w,  const float* __restrict__ gate_b,
    const float* __restrict__ shift_w, const float* __restrict__ shift_b,
    const float* __restrict__ gamma_w, const float* __restrict__ gamma_b,
    const float* __restrict__ erase_w, const float* __restrict__ erase_b,
    const float* __restrict__ add_w,   const float* __restrict__ add_b)
{
    __shared__ float hs[Hh];
    __shared__ float ksh[Mv];
    __shared__ float sdot[6];
    __shared__ float sinv;
    const int b = blockIdx.x, t = threadIdx.x;
    for (int i = t; i < Hh; i += 256) hs[i] = h[(size_t)b*Hh + i];
    __syncthreads();

    if (t < 64) {
        float a0=0,a1=0,a2=0,a3=0;
        for (int j = 0; j < Hh; j += 4) {
            a0 = fmaf(hs[j  ], key_w[(j  )*Mv + t], a0);
            a1 = fmaf(hs[j+1], key_w[(j+1)*Mv + t], a1);
            a2 = fmaf(hs[j+2], key_w[(j+2)*Mv + t], a2);
            a3 = fmaf(hs[j+3], key_w[(j+3)*Mv + t], a3);
        }
        ksh[t] = clip01(a0+a1+a2+a3 + key_b[t]);
    } else if (t < 128) {
        const int m = t - 64;
        float a0=0,a1=0,a2=0,a3=0;
        for (int j = 0; j < Hh; j += 4) {
            a0 = fmaf(hs[j  ], erase_w[(j  )*Mv + m], a0);
            a1 = fmaf(hs[j+1], erase_w[(j+1)*Mv + m], a1);
            a2 = fmaf(hs[j+2], erase_w[(j+2)*Mv + m], a2);
            a3 = fmaf(hs[j+3], erase_w[(j+3)*Mv + m], a3);
        }
        g_ev[b*Mv + m] = clip01(a0+a1+a2+a3 + erase_b[m]);
    } else if (t < 192) {
        const int m = t - 128;
        float a0=0,a1=0,a2=0,a3=0;
        for (int j = 0; j < Hh; j += 4) {
            a0 = fmaf(hs[j  ], add_w[(j  )*Mv + m], a0);
            a1 = fmaf(hs[j+1], add_w[(j+1)*Mv + m], a1);
            a2 = fmaf(hs[j+2], add_w[(j+2)*Mv + m], a2);
            a3 = fmaf(hs[j+3], add_w[(j+3)*Mv + m], a3);
        }
        // relu then clip01 == clip01
        g_av[b*Mv + m] = clip01(a0+a1+a2+a3 + add_b[m]);
    } else if (t < 198) {
        const int d = t - 192;
        const float* w; int str, col;
        if      (d == 0) { w = beta_w;  str = 1; col = 0; }
        else if (d == 1) { w = gate_w;  str = 1; col = 0; }
        else if (d == 2) { w = gamma_w; str = 1; col = 0; }
        else             { w = shift_w; str = 3; col = d - 3; }
        float a0=0,a1=0;
        for (int j = 0; j < Hh; j += 2) {
            a0 = fmaf(hs[j  ], w[(j  )*str + col], a0);
            a1 = fmaf(hs[j+1], w[(j+1)*str + col], a1);
        }
        sdot[d] = a0 + a1;
    }
    __syncthreads();

    if (t < 32) {
        float v = ksh[t]*ksh[t] + ksh[t+32]*ksh[t+32];
        #pragma unroll
        for (int off = 16; off; off >>= 1) v += __shfl_xor_sync(0xffffffffu, v, off);
        if (t == 0) sinv = 1.f / (sqrtf(v) + 1e-8f);
    }
    __syncthreads();
    if (t < 64) g_kn[b*Mv + t] = ksh[t] * sinv;
    if (t == 0) {
        g_beta[b]  = fmaxf(sdot[0] + beta_b[0], 0.f);
        g_gate[b]  = clip01(sdot[1] + gate_b[0]);
        g_gamma[b] = 1.f + fmaxf(sdot[2] + gamma_b[0], 0.f);
        float x0 = sdot[3] + shift_b[0];
        float x1 = sdot[4] + shift_b[1];
        float x2 = sdot[5] + shift_b[2];
        float mx = fmaxf(x0, fmaxf(x1, x2));
        float e0 = expf(x0-mx), e1 = expf(x1-mx), e2 = expf(x2-mx);
        float is = 1.f / (e0+e1+e2);
        g_shift[b*3+0] = e0*is; g_shift[b*3+1] = e1*is; g_shift[b*3+2] = e2*is;
    }
}

// ------- kernel 2: E[b,n] = exp(beta[b] * (kn[b]·m[n]) / (||m[n]||+eps)) ---
// tf32 WMMA; E stored bf16. psum is computed from the bf16-ROUNDED values so
// the normalizer matches the stored numerators exactly.
__global__ void sim_kernel(const float* __restrict__ mem,
                           const int* __restrict__ bank, int use_m1)
{
    const float* __restrict__ src = use_m1 ? g_m1
                                           : (mem + (size_t)bank[0]*NNv*Mv);
    __shared__ __align__(16) float mt[64*68];   // [k][n], padded
    __shared__ __align__(16) float cs[64*68];   // [b][n] raw sim (k-dot)
    __shared__ float invn[64];
    __shared__ float sbeta[64];
    const int t = threadIdx.x;
    const int n0 = blockIdx.x * 64;

    for (int i = t; i < 64*64; i += 256) {
        int rr = i >> 6, cc = i & 63;
        mt[cc*68 + rr] = src[(size_t)(n0 + rr)*Mv + cc];
    }
    if (t < 64) sbeta[t] = g_beta[t];
    __syncthreads();
    if (t < 64) {
        float s = 0.f;
        #pragma unroll 16
        for (int k = 0; k < 64; k++) { float v = mt[k*68 + t]; s = fmaf(v, v, s); }
        invn[t] = 1.f / (sqrtf(s) + 1e-8f);
    }

    // WMMA: C[64b][64n] = kn[64b][64k] @ mt[64k][64n]
    const int warp  = t >> 5;
    const int brow  = warp >> 1;        // b-tile 0..3
    const int ncol0 = (warp & 1) * 2;   // n-tiles {0,1} or {2,3}
    wmma::fragment<wmma::accumulator, 16, 16, 8, float> acc0, acc1;
    wmma::fill_fragment(acc0, 0.f);
    wmma::fill_fragment(acc1, 0.f);
    #pragma unroll
    for (int kt = 0; kt < 8; kt++) {
        wmma::fragment<wmma::matrix_a, 16, 16, 8, wmma::precision::tf32,
                       wmma::row_major> fa;
        wmma::load_matrix_sync(fa, &g_kn[(brow*16)*Mv + kt*8], Mv);
        #pragma unroll
        for (int i = 0; i < fa.num_elements; i++)
            fa.x[i] = wmma::__float_to_tf32(fa.x[i]);
        wmma::fragment<wmma::matrix_b, 16, 16, 8, wmma::precision::tf32,
                       wmma::row_major> fb0, fb1;
        wmma::load_matrix_sync(fb0, &mt[(kt*8)*68 + (ncol0    )*16], 68);
        wmma::load_matrix_sync(fb1, &mt[(kt*8)*68 + (ncol0 + 1)*16], 68);
        #pragma unroll
        for (int i = 0; i < fb0.num_elements; i++) {
            fb0.x[i] = wmma::__float_to_tf32(fb0.x[i]);
            fb1.x[i] = wmma::__float_to_tf32(fb1.x[i]);
        }
        wmma::mma_sync(acc0, fa, fb0, acc0);
        wmma::mma_sync(acc1, fa, fb1, acc1);
    }
    wmma::store_matrix_sync(&cs[(brow*16)*68 + (ncol0    )*16], acc0, 68,
                            wmma::mem_row_major);
    wmma::store_matrix_sync(&cs[(brow*16)*68 + (ncol0 + 1)*16], acc1, 68,
                            wmma::mem_row_major);
    __syncthreads();

    // epilogue: scale by invn, exp, bf16 store, per-b partial sums
    const int by = t >> 5, nx = t & 31;   // 8 b's per thread, 2 n's per thread
    const float2 iv = *(const float2*)&invn[2*nx];
    float psum[8];
    #pragma unroll
    for (int bi = 0; bi < 8; bi++) {
        const int bb = 8*by + bi;
        const float bt = sbeta[bb];
        const float2 cv = *(const float2*)&cs[bb*68 + 2*nx];
        float e0 = __expf(bt * cv.x * iv.x);
        float e1 = __expf(bt * cv.y * iv.y);
        __nv_bfloat162 hv = __floats2bfloat162_rn(e0, e1);
        *(__nv_bfloat162*)&g_E[(size_t)bb*NNv + n0 + 2*nx] = hv;
        psum[bi] = __bfloat162float(hv.x) + __bfloat162float(hv.y);
    }
    #pragma unroll
    for (int bi = 0; bi < 8; bi++)
        #pragma unroll
        for (int off = 16; off; off >>= 1)
            psum[bi] += __shfl_xor_sync(0xffffffffu, psum[bi], off);
    if (nx == 0) {
        #pragma unroll
        for (int bi = 0; bi < 8; bi++)
            g_psum[(size_t)(8*by + bi)*SIMBLK + blockIdx.x] = psum[bi];
    }
}

// ---------------- deterministic reductions ---------------------------------
__global__ void reduce_sumexp_kernel()
{
    const int b = blockIdx.x, t = threadIdx.x;
    float s = 0.f;
    for (int i = t; i < SIMBLK; i += 256) s += g_psum[(size_t)b*SIMBLK + i];
    __shared__ float red[256];
    red[t] = s; __syncthreads();
    for (int off = 128; off; off >>= 1) { if (t < off) red[t] += red[t+off]; __syncthreads(); }
    if (t == 0) g_sumexp[b] = red[0];
}

__global__ void reduce_total_kernel(int out_off)
{
    const int seg = blockIdx.x, t = threadIdx.x;
    float s = 0.f;
    for (int i = t; i < Bz*CSPBLK; i += 256) s += g_tpart[seg*(Bz*CSPBLK) + i];
    __shared__ float red[256];
    red[t] = s; __syncthreads();
    for (int off = 128; off; off >>= 1) { if (t < off) red[t] += red[t+off]; __syncthreads(); }
    if (t == 0) g_totals[out_off + seg] = red[0];
}

// helper: load 4 consecutive bf16 E values as floats
__device__ __forceinline__ float4 ld_e4(const __nv_bfloat16* p)
{
    const __nv_bfloat162 a = *(const __nv_bfloat162*)p;
    const __nv_bfloat162 b = *(const __nv_bfloat162*)(p + 2);
    float4 v;
    v.x = __bfloat162float(a.x); v.y = __bfloat162float(a.y);
    v.z = __bfloat162float(b.x); v.w = __bfloat162float(b.y);
    return v;
}

// ----- kernel 3a: WRITE head csp (vectorized, bf16 E in) --------------------
__global__ void csp_write_kernel(const float* __restrict__ ww)
{
    const int b  = blockIdx.y;
    const int c0 = blockIdx.x * 1024;
    const float* __restrict__ wp = ww + (size_t)b*NNv;
    float* __restrict__ wo = g_wpow_w + (size_t)b*NNv;
    const __nv_bfloat16* __restrict__ Eb = g_E + (size_t)b*NNv;

    __shared__ __align__(16) float wg2[1032];
    __shared__ __align__(16) float red[256];
    const float gg   = g_gate[b];
    const float invS = gg / g_sumexp[b];   // gate folded into content scale
    const float omg  = 1.f - gg;
    const float s0 = g_shift[b*3+0], s1 = g_shift[b*3+1], s2 = g_shift[b*3+2];
    const float gm = g_gamma[b];
    const int t = threadIdx.x;

    {
        const int n = c0 + 4*t;
        const float4 e = ld_e4(&Eb[n]);
        const float4 w = *(const float4*)&wp[n];
        float4 v;
        v.x = fmaf(omg, w.x, e.x*invS);
        v.y = fmaf(omg, w.y, e.y*invS);
        v.z = fmaf(omg, w.z, e.z*invS);
        v.w = fmaf(omg, w.w, e.w*invS);
        *(float4*)&wg2[4*t] = v;
    }
    if (t == 0) {
        const int nl = c0 - 1;
        wg2[1025] = (nl >= 0)
            ? fmaf(omg, wp[nl], __bfloat162float(Eb[nl])*invS) : 0.f;
        const int nr = c0 + 1024;
        wg2[1024] = (nr < NNv)
            ? fmaf(omg, wp[nr], __bfloat162float(Eb[nr])*invS) : 0.f;
    }
    __syncthreads();

    const float4 f   = *(const float4*)&wg2[4*t];
    const float left  = wg2[(t == 0) ? 1025 : 4*t - 1];
    const float right = wg2[4*t + 4];   // t==255 lands on wg2[1024] = halo
    float4 o;
    o.x = fpow(fmaf(s0, left, fmaf(s1, f.x, s2*f.y)),  gm);
    o.y = fpow(fmaf(s0, f.x,  fmaf(s1, f.y, s2*f.z)),  gm);
    o.z = fpow(fmaf(s0, f.y,  fmaf(s1, f.z, s2*f.w)),  gm);
    o.w = fpow(fmaf(s0, f.z,  fmaf(s1, f.w, s2*right)), gm);
    *(float4*)&wo[c0 + 4*t] = o;

    red[t] = (o.x + o.y) + (o.z + o.w);
    __syncthreads();
    for (int off = 128; off; off >>= 1) { if (t < off) red[t] += red[t+off]; __syncthreads(); }
    if (t == 0) g_tpart[b*CSPBLK + blockIdx.x] = red[0];
}

// ----- kernel 3b: READ heads csp (vectorized, bf16 E in / bf16 w_pow out) ---
// Gated content term g*E/sumexp is r-independent: staged once into ec.
// Pow partial sums use the bf16-ROUNDED outputs so totals match einsum input.
__global__ void csp_read_kernel(const float* __restrict__ wr)
{
    const int b  = blockIdx.y;
    const int c0 = blockIdx.x * 1024;
    const __nv_bfloat16* __restrict__ Eb = g_E + (size_t)b*NNv;

    __shared__ __align__(16) float ec [1032];   // same halo layout as wg2
    __shared__ __align__(16) float wg2[1032];
    __shared__ __align__(16) float red[256];
    const float gg   = g_gate[b];
    const float omg  = 1.f - gg;
    const float invS = gg / g_sumexp[b];
    const float s0 = g_shift[b*3+0], s1 = g_shift[b*3+1], s2 = g_shift[b*3+2];
    const float gm = g_gamma[b];
    const int t = threadIdx.x;

    {
        const int n = c0 + 4*t;
        const float4 e = ld_e4(&Eb[n]);
        float4 v;
        v.x = e.x*invS; v.y = e.y*invS; v.z = e.z*invS; v.w = e.w*invS;
        *(float4*)&ec[4*t] = v;
    }
    if (t == 0) {
        const int nl = c0 - 1;
        ec[1025] = (nl >= 0)  ? __bfloat162float(Eb[nl])*invS : 0.f;
        const int nr = c0 + 1024;
        ec[1024] = (nr < NNv) ? __bfloat162float(Eb[nr])*invS : 0.f;
    }

    #pragma unroll
    for (int r = 0; r < Rv; r++) {
        const size_t head_off = ((size_t)r*Bz + b) * NNv;
        const float* __restrict__ wp = wr + head_off;
        __nv_bfloat16* __restrict__ wo = g_wpow_r + head_off;

        __syncthreads();   // ec ready (r==0) / prior-r wg2 consumers done
        {
            const int n = c0 + 4*t;
            const float4 w = *(const float4*)&wp[n];
            const float4 e = *(const float4*)&ec[4*t];
            float4 v;
            v.x = fmaf(omg, w.x, e.x);
            v.y = fmaf(omg, w.y, e.y);
            v.z = fmaf(omg, w.z, e.z);
            v.w = fmaf(omg, w.w, e.w);
            *(float4*)&wg2[4*t] = v;
        }
        if (t == 0) {
            const int nl = c0 - 1;
            wg2[1025] = (nl >= 0)  ? fmaf(omg, wp[nl], ec[1025]) : 0.f;
            const int nr = c0 + 1024;
            wg2[1024] = (nr < NNv) ? fmaf(omg, wp[nr], ec[1024]) : 0.f;
        }
        __syncthreads();

        const float4 f   = *(const float4*)&wg2[4*t];
        const float left  = wg2[(t == 0) ? 1025 : 4*t - 1];
        const float right = wg2[4*t + 4];
        float4 o;
        o.x = fpow(fmaf(s0, left, fmaf(s1, f.x, s2*f.y)),  gm);
        o.y = fpow(fmaf(s0, f.x,  fmaf(s1, f.y, s2*f.z)),  gm);
        o.z = fpow(fmaf(s0, f.y,  fmaf(s1, f.z, s2*f.w)),  gm);
        o.w = fpow(fmaf(s0, f.z,  fmaf(s1, f.w, s2*right)), gm);
        __nv_bfloat162 o01 = __floats2bfloat162_rn(o.x, o.y);
        __nv_bfloat162 o23 = __floats2bfloat162_rn(o.z, o.w);
        *(__nv_bfloat162*)&wo[c0 + 4*t]     = o01;
        *(__nv_bfloat162*)&wo[c0 + 4*t + 2] = o23;

        red[t] = (__bfloat162float(o01.x) + __bfloat162float(o01.y))
               + (__bfloat162float(o23.x) + __bfloat162float(o23.y));
        __syncthreads();
        for (int off = 128; off; off >>= 1) { if (t < off) red[t] += red[t+off]; __syncthreads(); }
        if (t == 0)
            g_tpart[r*(Bz*CSPBLK) + b*CSPBLK + blockIdx.x] = red[0];
    }
}

// --- kernel 4: m1 = m0*(1 - W^T e) + W^T a  (tf32 WMMA) ---------------------
__global__ void memupdate_kernel(const float* __restrict__ mem,
                                 const int* __restrict__ bank)
{
    const float* __restrict__ m0 = mem + (size_t)bank[0]*NNv*Mv;
    __shared__ __align__(16) float wsh[64*64];   // [b][n] -> A col_major
    __shared__ __align__(16) float es [64*64];   // [b][m] pre-scaled
    __shared__ __align__(16) float as_[64*64];
    const int t = threadIdx.x;
    const int n0 = blockIdx.x * 64;
    const float inv = 1.f / (g_totals[0] + 1e-5f);

    for (int i = t; i < 64*64; i += 256) {
        int bb = i >> 6, nl = i & 63;
        wsh[i] = g_wpow_w[(size_t)bb*NNv + n0 + nl];
    }
    for (int i = t; i < 64*64; i += 256) { es[i] = g_ev[i]*inv; as_[i] = g_av[i]*inv; }
    __syncthreads();

    const int warp  = t >> 5;
    const int nrow  = warp >> 1;        // n-tile 0..3
    const int mcol0 = (warp & 1) * 2;   // m-tiles {0,1} or {2,3}
    wmma::fragment<wmma::accumulator, 16, 16, 8, float> ce0, ce1, ca0, ca1;
    wmma::fill_fragment(ce0, 0.f); wmma::fill_fragment(ce1, 0.f);
    wmma::fill_fragment(ca0, 0.f); wmma::fill_fragment(ca1, 0.f);

    #pragma unroll
    for (int kt = 0; kt < 8; kt++) {
        wmma::fragment<wmma::matrix_a, 16, 16, 8, wmma::precision::tf32,
                       wmma::col_major> fa;
        wmma::load_matrix_sync(fa, &wsh[(kt*8)*64 + nrow*16], 64);
        #pragma unroll
        for (int i = 0; i < fa.num_elements; i++)
            fa.x[i] = wmma::__float_to_tf32(fa.x[i]);
        wmma::fragment<wmma::matrix_b, 16, 16, 8, wmma::precision::tf32,
                       wmma::row_major> fe0, fe1, fd0, fd1;
        wmma::load_matrix_sync(fe0, &es [(kt*8)*64 + (mcol0    )*16], 64);
        wmma::load_matrix_sync(fe1, &es [(kt*8)*64 + (mcol0 + 1)*16], 64);
        wmma::load_matrix_sync(fd0, &as_[(kt*8)*64 + (mcol0    )*16], 64);
        wmma::load_matrix_sync(fd1, &as_[(kt*8)*64 + (mcol0 + 1)*16], 64);
        #pragma unroll
        for (int i = 0; i < fe0.num_elements; i++) {
            fe0.x[i] = wmma::__float_to_tf32(fe0.x[i]);
            fe1.x[i] = wmma::__float_to_tf32(fe1.x[i]);
            fd0.x[i] = wmma::__float_to_tf32(fd0.x[i]);
            fd1.x[i] = wmma::__float_to_tf32(fd1.x[i]);
        }
        wmma::mma_sync(ce0, fa, fe0, ce0);
        wmma::mma_sync(ce1, fa, fe1, ce1);
        wmma::mma_sync(ca0, fa, fd0, ca0);
        wmma::mma_sync(ca1, fa, fd1, ca1);
    }
    __syncthreads();   // all warps done reading wsh/es before acc overwrite

    float* ce_s = wsh;   // alias: [n][m] ld=64
    float* ca_s = es;
    wmma::store_matrix_sync(&ce_s[(nrow*16)*64 + (mcol0    )*16], ce0, 64,
                            wmma::mem_row_major);
    wmma::store_matrix_sync(&ce_s[(nrow*16)*64 + (mcol0 + 1)*16], ce1, 64,
                            wmma::mem_row_major);
    wmma::store_matrix_sync(&ca_s[(nrow*16)*64 + (mcol0    )*16], ca0, 64,
                            wmma::mem_row_major);
    wmma::store_matrix_sync(&ca_s[(nrow*16)*64 + (mcol0 + 1)*16], ca1, 64,
                            wmma::mem_row_major);
    __syncthreads();

    #pragma unroll
    for (int j = 0; j < 4; j++) {
        const int idx = j*1024 + 4*t;          // element index in 64x64 tile
        const int nl = idx >> 6, mm = idx & 63;
        const size_t n = (size_t)(n0 + nl);
        const float4 o  = *(const float4*)&m0  [n*Mv + mm];
        const float4 ce = *(const float4*)&ce_s[nl*64 + mm];
        const float4 ca = *(const float4*)&ca_s[nl*64 + mm];
        float4 v;
        v.x = o.x*(1.f - ce.x) + ca.x;
        v.y = o.y*(1.f - ce.y) + ca.y;
        v.z = o.z*(1.f - ce.z) + ca.z;
        v.w = o.w*(1.f - ce.w) + ca.w;
        *(float4*)&g_m1[n*Mv + mm] = v;
    }
}

// ----- kernel 5: split-K read einsum partials (bf16 WMMA tensor cores) -----
// wpow_r is already bf16 in global: staging is a straight vector copy.
__global__ void einsum_kernel()
{
    __shared__ __align__(16) __nv_bfloat16 ash[64*72];  // [b][k], ld=72
    __shared__ __align__(16) __nv_bfloat16 bsh[64*72];  // [k][m], ld=72
    const int chunk = blockIdx.x, r = blockIdx.y;
    const int n0 = chunk * EK;
    const int t = threadIdx.x;
    const int warp  = t >> 5;
    const int trow  = warp >> 1;          // b-tile: 0..3
    const int tcol0 = (warp & 1) * 2;     // m-tiles: {0,1} or {2,3}

    wmma::fragment<wmma::accumulator, 16, 16, 16, float> acc0, acc1;
    wmma::fill_fragment(acc0, 0.f);
    wmma::fill_fragment(acc1, 0.f);

    for (int sub = 0; sub < EK/64; sub++) {
        const int nb = n0 + sub*64;
        // 64 rows x 32 bf162 per row, straight copy
        for (int i = t; i < 64*32; i += 256) {
            const int bb = i >> 5, kp = i & 31;
            *(__nv_bfloat162*)&ash[bb*72 + 2*kp] =
                *(const __nv_bfloat162*)&g_wpow_r[((size_t)r*Bz + bb)*NNv + nb + 2*kp];
        }
        for (int i = t; i < 64*64; i += 256) {
            const int kk = i >> 6, mm = i & 63;
            bsh[kk*72 + mm] = __float2bfloat16(g_m1[(size_t)(nb + kk)*Mv + mm]);
        }
        __syncthreads();

        #pragma unroll
        for (int kt = 0; kt < 4; kt++) {
            wmma::fragment<wmma::matrix_a, 16, 16, 16, __nv_bfloat16,
                           wmma::row_major> fa;
            wmma::load_matrix_sync(fa, &ash[(trow*16)*72 + kt*16], 72);
            wmma::fragment<wmma::matrix_b, 16, 16, 16, __nv_bfloat16,
                           wmma::row_major> fb0, fb1;
            wmma::load_matrix_sync(fb0, &bsh[(kt*16)*72 + (tcol0    )*16], 72);
            wmma::load_matrix_sync(fb1, &bsh[(kt*16)*72 + (tcol0 + 1)*16], 72);
            wmma::mma_sync(acc0, fa, fb0, acc0);
            wmma::mma_sync(acc1, fa, fb1, acc1);
        }
        __syncthreads();
    }

    const size_t base = ((size_t)r*ECHUNK + chunk) * (Bz*Mv);
    wmma::store_matrix_sync(&g_epart[base + (size_t)(trow*16)*Mv + (tcol0    )*16],
                            acc0, Mv, wmma::mem_row_major);
    wmma::store_matrix_sync(&g_epart[base + (size_t)(trow*16)*Mv + (tcol0 + 1)*16],
                            acc1, Mv, wmma::mem_row_major);
}

// ----- kernel 6: reduce split-K + apply 1/(total_r+eps) + transpose --------
__global__ void reduce_out_kernel(float* __restrict__ out)
{
    const int gid = blockIdx.x*256 + threadIdx.x;   // 0..R*B*M-1
    const int r = gid >> 12;
    const int b = (gid >> 6) & 63;
    const int m = gid & 63;
    const float inv = 1.f / (g_totals[1 + r] + 1e-5f);
    float s = 0.f;
    for (int c = 0; c < ECHUNK; c++)
        s += g_epart[(((size_t)r*ECHUNK + c)*Bz + b)*Mv + m];
    out[(size_t)b*(Rv*Mv) + r*Mv + m] = s * inv;
}

// ---------------------------------------------------------------------------
extern "C" void kernel_launch(void* const* d_in, const int* in_sizes, int n_in,
                              void* d_out, int out_size)
{
    const float* h_t     = (const float*)d_in[0];
    const float* ww      = (const float*)d_in[1];
    const float* wr      = (const float*)d_in[2];
    const float* memory  = (const float*)d_in[3];
    const float* key_w   = (const float*)d_in[4];
    const float* key_b   = (const float*)d_in[5];
    const float* beta_w  = (const float*)d_in[6];
    const float* beta_b  = (const float*)d_in[7];
    const float* gate_w  = (const float*)d_in[8];
    const float* gate_b  = (const float*)d_in[9];
    const float* shift_w = (const float*)d_in[10];
    const float* shift_b = (const float*)d_in[11];
    const float* gamma_w = (const float*)d_in[12];
    const float* gamma_b = (const float*)d_in[13];
    const float* erase_w = (const float*)d_in[14];
    const float* erase_b = (const float*)d_in[15];
    const float* add_w   = (const float*)d_in[16];
    const float* add_b   = (const float*)d_in[17];
    const int*   bank    = (const int*)d_in[18];
    float* out = (float*)d_out;

    // head params (shared by all 5 weight updates)
    heads_kernel<<<Bz, 256>>>(h_t, key_w, key_b, beta_w, beta_b, gate_w, gate_b,
                              shift_w, shift_b, gamma_w, gamma_b,
                              erase_w, erase_b, add_w, add_b);

    // --- write head: content addressing on m0 ---
    sim_kernel<<<SIMBLK, 256>>>(memory, bank, 0);
    reduce_sumexp_kernel<<<Bz, 256>>>();
    csp_write_kernel<<<dim3(CSPBLK, Bz), 256>>>(ww);
    reduce_total_kernel<<<1, 256>>>(0);

    // --- memory erase/add ---
    memupdate_kernel<<<NNv/64, 256>>>(memory, bank);

    // --- read heads: shared content addressing on m1, all R heads/block ---
    sim_kernel<<<SIMBLK, 256>>>(memory, bank, 1);
    reduce_sumexp_kernel<<<Bz, 256>>>();
    csp_read_kernel<<<dim3(CSPBLK, Bz), 256>>>(wr);
    reduce_total_kernel<<<Rv, 256>>>(1);

    // --- read: r[r,b,:] = (wpow_r[r,b,:]/total_r) @ m1 ---
    einsum_kernel<<<dim3(ECHUNK, Rv), 256>>>();
    reduce_out_kernel<<<(Rv*Bz*Mv)/256, 256>>>(out);
}

// round 14
// speedup vs baseline: 1.8858x; 1.0478x over previous
#include <cuda_runtime.h>
#include <cuda_bf16.h>
#include <mma.h>
#include <math.h>

using namespace nvcuda;

#define Bz 64
#define Hh 1024
#define NNv 65536
#define Mv 64
#define Rv 4
#define SIMBLK (NNv/64)   /* 1024 sim blocks */
#define CSPBLK 64         /* N/1024 csp blocks per b */
#define ECHUNK 128        /* einsum split-K chunks */
#define EK (NNv/ECHUNK)   /* 512 n per chunk */

// ---------------- scratch (device globals: no allocation allowed) ----------
__device__ __nv_bfloat16 g_E[(size_t)Bz*NNv];       // exp(beta*sim) [B,N] bf16
__device__ __nv_bfloat16 g_wpow_w[(size_t)Bz*NNv];  // write-head w_pow bf16
__device__ __nv_bfloat16 g_wpow_r[(size_t)Rv*Bz*NNv]; // read-head w_pow bf16
__device__ float g_m1[(size_t)NNv*Mv];              // updated memory
__device__ float g_kn[Bz*Mv];
__device__ float g_ev[Bz*Mv];
__device__ float g_av[Bz*Mv];
__device__ float g_beta[Bz];
__device__ float g_gate[Bz];
__device__ float g_gamma[Bz];
__device__ float g_shift[Bz*3];
__device__ float g_psum[(size_t)Bz*SIMBLK];         // per-block exp partial sums
__device__ float g_tpart[Rv*Bz*CSPBLK];             // per-block pow partial sums
__device__ float g_epart[(size_t)Rv*ECHUNK*Bz*Mv];  // einsum split-K partials

__device__ __forceinline__ float clip01(float x){ return fminf(fmaxf(x, 0.f), 1.f); }
// fast x^g for x > 0 (w_tilde strictly positive: gated softmax mix, s_j > 0)
__device__ __forceinline__ float fpow(float x, float g){ return __expf(g * __logf(x)); }

// ---------------- kernel 1: head projections (once per step) ---------------
__global__ void heads_kernel(const float* __restrict__ h,
    const float* __restrict__ key_w,   const float* __restrict__ key_b,
    const float* __restrict__ beta_w,  const float* __restrict__ beta_b,
    const float* __restrict__ gate_w,  const float* __restrict__ gate_b,
    const float* __restrict__ shift_w, const float* __restrict__ shift_b,
    const float* __restrict__ gamma_w, const float* __restrict__ gamma_b,
    const float* __restrict__ erase_w, const float* __restrict__ erase_b,
    const float* __restrict__ add_w,   const float* __restrict__ add_b)
{
    __shared__ float hs[Hh];
    __shared__ float ksh[Mv];
    __shared__ float sdot[6];
    __shared__ float sinv;
    const int b = blockIdx.x, t = threadIdx.x;
    for (int i = t; i < Hh; i += 256) hs[i] = h[(size_t)b*Hh + i];
    __syncthreads();

    if (t < 64) {
        float a0=0,a1=0,a2=0,a3=0;
        for (int j = 0; j < Hh; j += 4) {
            a0 = fmaf(hs[j  ], key_w[(j  )*Mv + t], a0);
            a1 = fmaf(hs[j+1], key_w[(j+1)*Mv + t], a1);
            a2 = fmaf(hs[j+2], key_w[(j+2)*Mv + t], a2);
            a3 = fmaf(hs[j+3], key_w[(j+3)*Mv + t], a3);
        }
        ksh[t] = clip01(a0+a1+a2+a3 + key_b[t]);
    } else if (t < 128) {
        const int m = t - 64;
        float a0=0,a1=0,a2=0,a3=0;
        for (int j = 0; j < Hh; j += 4) {
            a0 = fmaf(hs[j  ], erase_w[(j  )*Mv + m], a0);
            a1 = fmaf(hs[j+1], erase_w[(j+1)*Mv + m], a1);
            a2 = fmaf(hs[j+2], erase_w[(j+2)*Mv + m], a2);
            a3 = fmaf(hs[j+3], erase_w[(j+3)*Mv + m], a3);
        }
        g_ev[b*Mv + m] = clip01(a0+a1+a2+a3 + erase_b[m]);
    } else if (t < 192) {
        const int m = t - 128;
        float a0=0,a1=0,a2=0,a3=0;
        for (int j = 0; j < Hh; j += 4) {
            a0 = fmaf(hs[j  ], add_w[(j  )*Mv + m], a0);
            a1 = fmaf(hs[j+1], add_w[(j+1)*Mv + m], a1);
            a2 = fmaf(hs[j+2], add_w[(j+2)*Mv + m], a2);
            a3 = fmaf(hs[j+3], add_w[(j+3)*Mv + m], a3);
        }
        // relu then clip01 == clip01
        g_av[b*Mv + m] = clip01(a0+a1+a2+a3 + add_b[m]);
    } else if (t < 198) {
        const int d = t - 192;
        const float* w; int str, col;
        if      (d == 0) { w = beta_w;  str = 1; col = 0; }
        else if (d == 1) { w = gate_w;  str = 1; col = 0; }
        else if (d == 2) { w = gamma_w; str = 1; col = 0; }
        else             { w = shift_w; str = 3; col = d - 3; }
        float a0=0,a1=0;
        for (int j = 0; j < Hh; j += 2) {
            a0 = fmaf(hs[j  ], w[(j  )*str + col], a0);
            a1 = fmaf(hs[j+1], w[(j+1)*str + col], a1);
        }
        sdot[d] = a0 + a1;
    }
    __syncthreads();

    if (t < 32) {
        float v = ksh[t]*ksh[t] + ksh[t+32]*ksh[t+32];
        #pragma unroll
        for (int off = 16; off; off >>= 1) v += __shfl_xor_sync(0xffffffffu, v, off);
        if (t == 0) sinv = 1.f / (sqrtf(v) + 1e-8f);
    }
    __syncthreads();
    if (t < 64) g_kn[b*Mv + t] = ksh[t] * sinv;
    if (t == 0) {
        g_beta[b]  = fmaxf(sdot[0] + beta_b[0], 0.f);
        g_gate[b]  = clip01(sdot[1] + gate_b[0]);
        g_gamma[b] = 1.f + fmaxf(sdot[2] + gamma_b[0], 0.f);
        float x0 = sdot[3] + shift_b[0];
        float x1 = sdot[4] + shift_b[1];
        float x2 = sdot[5] + shift_b[2];
        float mx = fmaxf(x0, fmaxf(x1, x2));
        float e0 = expf(x0-mx), e1 = expf(x1-mx), e2 = expf(x2-mx);
        float is = 1.f / (e0+e1+e2);
        g_shift[b*3+0] = e0*is; g_shift[b*3+1] = e1*is; g_shift[b*3+2] = e2*is;
    }
}

// ------- kernel 2: E[b,n] = exp(beta[b] * (kn[b]·m[n]) / (||m[n]||+eps)) ---
__global__ void sim_kernel(const float* __restrict__ mem,
                           const int* __restrict__ bank, int use_m1)
{
    const float* __restrict__ src = use_m1 ? g_m1
                                           : (mem + (size_t)bank[0]*NNv*Mv);
    __shared__ __align__(16) float mt[64*68];   // [k][n], padded
    __shared__ __align__(16) float cs[64*68];   // [b][n] raw sim (k-dot)
    __shared__ float invn[64];
    __shared__ float sbeta[64];
    const int t = threadIdx.x;
    const int n0 = blockIdx.x * 64;

    for (int i = t; i < 64*64; i += 256) {
        int rr = i >> 6, cc = i & 63;
        mt[cc*68 + rr] = src[(size_t)(n0 + rr)*Mv + cc];
    }
    if (t < 64) sbeta[t] = g_beta[t];
    __syncthreads();
    if (t < 64) {
        float s = 0.f;
        #pragma unroll 16
        for (int k = 0; k < 64; k++) { float v = mt[k*68 + t]; s = fmaf(v, v, s); }
        invn[t] = 1.f / (sqrtf(s) + 1e-8f);
    }

    // WMMA: C[64b][64n] = kn[64b][64k] @ mt[64k][64n]
    const int warp  = t >> 5;
    const int brow  = warp >> 1;        // b-tile 0..3
    const int ncol0 = (warp & 1) * 2;   // n-tiles {0,1} or {2,3}
    wmma::fragment<wmma::accumulator, 16, 16, 8, float> acc0, acc1;
    wmma::fill_fragment(acc0, 0.f);
    wmma::fill_fragment(acc1, 0.f);
    #pragma unroll
    for (int kt = 0; kt < 8; kt++) {
        wmma::fragment<wmma::matrix_a, 16, 16, 8, wmma::precision::tf32,
                       wmma::row_major> fa;
        wmma::load_matrix_sync(fa, &g_kn[(brow*16)*Mv + kt*8], Mv);
        #pragma unroll
        for (int i = 0; i < fa.num_elements; i++)
            fa.x[i] = wmma::__float_to_tf32(fa.x[i]);
        wmma::fragment<wmma::matrix_b, 16, 16, 8, wmma::precision::tf32,
                       wmma::row_major> fb0, fb1;
        wmma::load_matrix_sync(fb0, &mt[(kt*8)*68 + (ncol0    )*16], 68);
        wmma::load_matrix_sync(fb1, &mt[(kt*8)*68 + (ncol0 + 1)*16], 68);
        #pragma unroll
        for (int i = 0; i < fb0.num_elements; i++) {
            fb0.x[i] = wmma::__float_to_tf32(fb0.x[i]);
            fb1.x[i] = wmma::__float_to_tf32(fb1.x[i]);
        }
        wmma::mma_sync(acc0, fa, fb0, acc0);
        wmma::mma_sync(acc1, fa, fb1, acc1);
    }
    wmma::store_matrix_sync(&cs[(brow*16)*68 + (ncol0    )*16], acc0, 68,
                            wmma::mem_row_major);
    wmma::store_matrix_sync(&cs[(brow*16)*68 + (ncol0 + 1)*16], acc1, 68,
                            wmma::mem_row_major);
    __syncthreads();

    // epilogue: scale by invn, exp, bf16 store, per-b partial sums
    const int by = t >> 5, nx = t & 31;   // 8 b's per thread, 2 n's per thread
    const float2 iv = *(const float2*)&invn[2*nx];
    float psum[8];
    #pragma unroll
    for (int bi = 0; bi < 8; bi++) {
        const int bb = 8*by + bi;
        const float bt = sbeta[bb];
        const float2 cv = *(const float2*)&cs[bb*68 + 2*nx];
        float e0 = __expf(bt * cv.x * iv.x);
        float e1 = __expf(bt * cv.y * iv.y);
        __nv_bfloat162 hv = __floats2bfloat162_rn(e0, e1);
        *(__nv_bfloat162*)&g_E[(size_t)bb*NNv + n0 + 2*nx] = hv;
        psum[bi] = __bfloat162float(hv.x) + __bfloat162float(hv.y);
    }
    #pragma unroll
    for (int bi = 0; bi < 8; bi++)
        #pragma unroll
        for (int off = 16; off; off >>= 1)
            psum[bi] += __shfl_xor_sync(0xffffffffu, psum[bi], off);
    if (nx == 0) {
        #pragma unroll
        for (int bi = 0; bi < 8; bi++)
            g_psum[(size_t)(8*by + bi)*SIMBLK + blockIdx.x] = psum[bi];
    }
}

// helper: load 4 consecutive bf16 values as floats
__device__ __forceinline__ float4 ld_e4(const __nv_bfloat16* p)
{
    const __nv_bfloat162 a = *(const __nv_bfloat162*)p;
    const __nv_bfloat162 b = *(const __nv_bfloat162*)(p + 2);
    float4 v;
    v.x = __bfloat162float(a.x); v.y = __bfloat162float(a.y);
    v.z = __bfloat162float(b.x); v.w = __bfloat162float(b.y);
    return v;
}

// ----- kernel 3a: WRITE head csp (fused sumexp, bf16 in/out) ----------------
__global__ void csp_write_kernel(const float* __restrict__ ww)
{
    const int b  = blockIdx.y;
    const int c0 = blockIdx.x * 1024;
    const float* __restrict__ wp = ww + (size_t)b*NNv;
    __nv_bfloat16* __restrict__ wo = g_wpow_w + (size_t)b*NNv;
    const __nv_bfloat16* __restrict__ Eb = g_E + (size_t)b*NNv;

    __shared__ __align__(16) float wg2[1032];
    __shared__ __align__(16) float red[256];
    const int t = threadIdx.x;

    // fused sumexp: deterministic block-local sum of g_psum[b][*]
    {
        float s = 0.f;
        #pragma unroll
        for (int i = t; i < SIMBLK; i += 256) s += g_psum[(size_t)b*SIMBLK + i];
        red[t] = s; __syncthreads();
        for (int off = 128; off; off >>= 1) {
            if (t < off) red[t] += red[t+off];
            __syncthreads();
        }
    }
    const float gg   = g_gate[b];
    const float invS = gg / red[0];        // gate folded into content scale
    const float omg  = 1.f - gg;
    const float s0 = g_shift[b*3+0], s1 = g_shift[b*3+1], s2 = g_shift[b*3+2];
    const float gm = g_gamma[b];

    {
        const int n = c0 + 4*t;
        const float4 e = ld_e4(&Eb[n]);
        const float4 w = *(const float4*)&wp[n];
        float4 v;
        v.x = fmaf(omg, w.x, e.x*invS);
        v.y = fmaf(omg, w.y, e.y*invS);
        v.z = fmaf(omg, w.z, e.z*invS);
        v.w = fmaf(omg, w.w, e.w*invS);
        *(float4*)&wg2[4*t] = v;
    }
    if (t == 0) {
        const int nl = c0 - 1;
        wg2[1025] = (nl >= 0)
            ? fmaf(omg, wp[nl], __bfloat162float(Eb[nl])*invS) : 0.f;
        const int nr = c0 + 1024;
        wg2[1024] = (nr < NNv)
            ? fmaf(omg, wp[nr], __bfloat162float(Eb[nr])*invS) : 0.f;
    }
    __syncthreads();

    const float4 f   = *(const float4*)&wg2[4*t];
    const float left  = wg2[(t == 0) ? 1025 : 4*t - 1];
    const float right = wg2[4*t + 4];   // t==255 lands on wg2[1024] = halo
    float4 o;
    o.x = fpow(fmaf(s0, left, fmaf(s1, f.x, s2*f.y)),  gm);
    o.y = fpow(fmaf(s0, f.x,  fmaf(s1, f.y, s2*f.z)),  gm);
    o.z = fpow(fmaf(s0, f.y,  fmaf(s1, f.z, s2*f.w)),  gm);
    o.w = fpow(fmaf(s0, f.z,  fmaf(s1, f.w, s2*right)), gm);
    __nv_bfloat162 o01 = __floats2bfloat162_rn(o.x, o.y);
    __nv_bfloat162 o23 = __floats2bfloat162_rn(o.z, o.w);
    *(__nv_bfloat162*)&wo[c0 + 4*t]     = o01;
    *(__nv_bfloat162*)&wo[c0 + 4*t + 2] = o23;

    red[t] = (__bfloat162float(o01.x) + __bfloat162float(o01.y))
           + (__bfloat162float(o23.x) + __bfloat162float(o23.y));
    __syncthreads();
    for (int off = 128; off; off >>= 1) { if (t < off) red[t] += red[t+off]; __syncthreads(); }
    if (t == 0) g_tpart[b*CSPBLK + blockIdx.x] = red[0];
}

// ----- kernel 3b: READ heads csp (fused sumexp, all R heads staged at once) -
__global__ void csp_read_kernel(const float* __restrict__ wr)
{
    const int b  = blockIdx.y;
    const int c0 = blockIdx.x * 1024;
    const __nv_bfloat16* __restrict__ Eb = g_E + (size_t)b*NNv;

    __shared__ __align__(16) float ec [1032];     // halo layout as before
    __shared__ __align__(16) float wg4[4*1032];   // all 4 heads staged
    __shared__ __align__(16) float sred[256];
    __shared__ __align__(16) float red32[32];
    const int t = threadIdx.x;
    const int warp = t >> 5, lane = t & 31;

    // fused sumexp
    {
        float s = 0.f;
        #pragma unroll
        for (int i = t; i < SIMBLK; i += 256) s += g_psum[(size_t)b*SIMBLK + i];
        sred[t] = s; __syncthreads();
        for (int off = 128; off; off >>= 1) {
            if (t < off) sred[t] += sred[t+off];
            __syncthreads();
        }
    }
    const float gg   = g_gate[b];
    const float omg  = 1.f - gg;
    const float invS = gg / sred[0];
    const float s0 = g_shift[b*3+0], s1 = g_shift[b*3+1], s2 = g_shift[b*3+2];
    const float gm = g_gamma[b];
    __syncthreads();   // all threads read sred[0] before any reuse

    // stage gated content + all 4 heads (independent streams -> MLP)
    {
        const int n = c0 + 4*t;
        const float4 e = ld_e4(&Eb[n]);
        float4 ev;
        ev.x = e.x*invS; ev.y = e.y*invS; ev.z = e.z*invS; ev.w = e.w*invS;
        *(float4*)&ec[4*t] = ev;
        #pragma unroll
        for (int r = 0; r < Rv; r++) {
            const float4 w = *(const float4*)&wr[((size_t)r*Bz + b)*NNv + n];
            float4 v;
            v.x = fmaf(omg, w.x, ev.x);
            v.y = fmaf(omg, w.y, ev.y);
            v.z = fmaf(omg, w.z, ev.z);
            v.w = fmaf(omg, w.w, ev.w);
            *(float4*)&wg4[r*1032 + 4*t] = v;
        }
    }
    if (t < 8) {   // halos: t>>1 = r, t&1 = side (0=right,1=left)
        const int r = t >> 1;
        const float* __restrict__ wp = wr + ((size_t)r*Bz + b)*NNv;
        if (t & 1) {
            const int nl = c0 - 1;
            wg4[r*1032 + 1025] = (nl >= 0)
                ? fmaf(omg, wp[nl], __bfloat162float(Eb[nl])*invS) : 0.f;
        } else {
            const int nr = c0 + 1024;
            wg4[r*1032 + 1024] = (nr < NNv)
                ? fmaf(omg, wp[nr], __bfloat162float(Eb[nr])*invS) : 0.f;
        }
    }
    __syncthreads();

    float ls[4];
    #pragma unroll
    for (int r = 0; r < Rv; r++) {
        const float* w = &wg4[r*1032];
        __nv_bfloat16* __restrict__ wo = g_wpow_r + ((size_t)r*Bz + b)*NNv;
        const float4 f   = *(const float4*)&w[4*t];
        const float left  = w[(t == 0) ? 1025 : 4*t - 1];
        const float right = w[4*t + 4];
        float4 o;
        o.x = fpow(fmaf(s0, left, fmaf(s1, f.x, s2*f.y)),  gm);
        o.y = fpow(fmaf(s0, f.x,  fmaf(s1, f.y, s2*f.z)),  gm);
        o.z = fpow(fmaf(s0, f.y,  fmaf(s1, f.z, s2*f.w)),  gm);
        o.w = fpow(fmaf(s0, f.z,  fmaf(s1, f.w, s2*right)), gm);
        __nv_bfloat162 o01 = __floats2bfloat162_rn(o.x, o.y);
        __nv_bfloat162 o23 = __floats2bfloat162_rn(o.z, o.w);
        *(__nv_bfloat162*)&wo[c0 + 4*t]     = o01;
        *(__nv_bfloat162*)&wo[c0 + 4*t + 2] = o23;
        ls[r] = (__bfloat162float(o01.x) + __bfloat162float(o01.y))
              + (__bfloat162float(o23.x) + __bfloat162float(o23.y));
    }

    // combined reduction: warp shuffles, then 8 warp-partials per r
    #pragma unroll
    for (int r = 0; r < Rv; r++)
        #pragma unroll
        for (int off = 16; off; off >>= 1)
            ls[r] += __shfl_xor_sync(0xffffffffu, ls[r], off);
    if (lane == 0) {
        #pragma unroll
        for (int r = 0; r < Rv; r++) red32[r*8 + warp] = ls[r];
    }
    __syncthreads();
    if (t < Rv) {
        float s = 0.f;
        #pragma unroll
        for (int w = 0; w < 8; w++) s += red32[t*8 + w];
        g_tpart[t*(Bz*CSPBLK) + b*CSPBLK + blockIdx.x] = s;
    }
}

// --- kernel 4: m1 = m0*(1 - W^T e) + W^T a  (tf32 WMMA, fused write-total) --
__global__ void memupdate_kernel(const float* __restrict__ mem,
                                 const int* __restrict__ bank)
{
    const float* __restrict__ m0 = mem + (size_t)bank[0]*NNv*Mv;
    __shared__ __align__(16) float wsh[64*64];   // [b][n] -> A col_major
    __shared__ __align__(16) float es [64*64];   // [b][m] pre-scaled
    __shared__ __align__(16) float as_[64*64];
    const int t = threadIdx.x;
    const int n0 = blockIdx.x * 64;

    // fused write-head total: deterministic block-local sum (wsh as scratch)
    float inv;
    {
        float s = 0.f;
        #pragma unroll
        for (int i = t; i < Bz*CSPBLK; i += 256) s += g_tpart[i];
        wsh[t] = s; __syncthreads();
        for (int off = 128; off; off >>= 1) {
            if (t < off) wsh[t] += wsh[t+off];
            __syncthreads();
        }
        inv = 1.f / (wsh[0] + 1e-5f);
        __syncthreads();   // all reads of wsh[0] done before staging overwrites
    }

    for (int i = t; i < 64*64; i += 256) {
        int bb = i >> 6, nl = i & 63;
        wsh[i] = __bfloat162float(g_wpow_w[(size_t)bb*NNv + n0 + nl]);
    }
    for (int i = t; i < 64*64; i += 256) { es[i] = g_ev[i]*inv; as_[i] = g_av[i]*inv; }
    __syncthreads();

    const int warp  = t >> 5;
    const int nrow  = warp >> 1;        // n-tile 0..3
    const int mcol0 = (warp & 1) * 2;   // m-tiles {0,1} or {2,3}
    wmma::fragment<wmma::accumulator, 16, 16, 8, float> ce0, ce1, ca0, ca1;
    wmma::fill_fragment(ce0, 0.f); wmma::fill_fragment(ce1, 0.f);
    wmma::fill_fragment(ca0, 0.f); wmma::fill_fragment(ca1, 0.f);

    #pragma unroll
    for (int kt = 0; kt < 8; kt++) {
        wmma::fragment<wmma::matrix_a, 16, 16, 8, wmma::precision::tf32,
                       wmma::col_major> fa;
        wmma::load_matrix_sync(fa, &wsh[(kt*8)*64 + nrow*16], 64);
        #pragma unroll
        for (int i = 0; i < fa.num_elements; i++)
            fa.x[i] = wmma::__float_to_tf32(fa.x[i]);
        wmma::fragment<wmma::matrix_b, 16, 16, 8, wmma::precision::tf32,
                       wmma::row_major> fe0, fe1, fd0, fd1;
        wmma::load_matrix_sync(fe0, &es [(kt*8)*64 + (mcol0    )*16], 64);
        wmma::load_matrix_sync(fe1, &es [(kt*8)*64 + (mcol0 + 1)*16], 64);
        wmma::load_matrix_sync(fd0, &as_[(kt*8)*64 + (mcol0    )*16], 64);
        wmma::load_matrix_sync(fd1, &as_[(kt*8)*64 + (mcol0 + 1)*16], 64);
        #pragma unroll
        for (int i = 0; i < fe0.num_elements; i++) {
            fe0.x[i] = wmma::__float_to_tf32(fe0.x[i]);
            fe1.x[i] = wmma::__float_to_tf32(fe1.x[i]);
            fd0.x[i] = wmma::__float_to_tf32(fd0.x[i]);
            fd1.x[i] = wmma::__float_to_tf32(fd1.x[i]);
        }
        wmma::mma_sync(ce0, fa, fe0, ce0);
        wmma::mma_sync(ce1, fa, fe1, ce1);
        wmma::mma_sync(ca0, fa, fd0, ca0);
        wmma::mma_sync(ca1, fa, fd1, ca1);
    }
    __syncthreads();   // all warps done reading wsh/es before acc overwrite

    float* ce_s = wsh;   // alias: [n][m] ld=64
    float* ca_s = es;
    wmma::store_matrix_sync(&ce_s[(nrow*16)*64 + (mcol0    )*16], ce0, 64,
                            wmma::mem_row_major);
    wmma::store_matrix_sync(&ce_s[(nrow*16)*64 + (mcol0 + 1)*16], ce1, 64,
                            wmma::mem_row_major);
    wmma::store_matrix_sync(&ca_s[(nrow*16)*64 + (mcol0    )*16], ca0, 64,
                            wmma::mem_row_major);
    wmma::store_matrix_sync(&ca_s[(nrow*16)*64 + (mcol0 + 1)*16], ca1, 64,
                            wmma::mem_row_major);
    __syncthreads();

    #pragma unroll
    for (int j = 0; j < 4; j++) {
        const int idx = j*1024 + 4*t;          // element index in 64x64 tile
        const int nl = idx >> 6, mm = idx & 63;
        const size_t n = (size_t)(n0 + nl);
        const float4 o  = *(const float4*)&m0  [n*Mv + mm];
        const float4 ce = *(const float4*)&ce_s[nl*64 + mm];
        const float4 ca = *(const float4*)&ca_s[nl*64 + mm];
        float4 v;
        v.x = o.x*(1.f - ce.x) + ca.x;
        v.y = o.y*(1.f - ce.y) + ca.y;
        v.z = o.z*(1.f - ce.z) + ca.z;
        v.w = o.w*(1.f - ce.w) + ca.w;
        *(float4*)&g_m1[n*Mv + mm] = v;
    }
}

// ----- kernel 5: split-K read einsum partials (bf16 WMMA tensor cores) -----
__global__ void einsum_kernel()
{
    __shared__ __align__(16) __nv_bfloat16 ash[64*72];  // [b][k], ld=72
    __shared__ __align__(16) __nv_bfloat16 bsh[64*72];  // [k][m], ld=72
    const int chunk = blockIdx.x, r = blockIdx.y;
    const int n0 = chunk * EK;
    const int t = threadIdx.x;
    const int warp  = t >> 5;
    const int trow  = warp >> 1;          // b-tile: 0..3
    const int tcol0 = (warp & 1) * 2;     // m-tiles: {0,1} or {2,3}

    wmma::fragment<wmma::accumulator, 16, 16, 16, float> acc0, acc1;
    wmma::fill_fragment(acc0, 0.f);
    wmma::fill_fragment(acc1, 0.f);

    for (int sub = 0; sub < EK/64; sub++) {
        const int nb = n0 + sub*64;
        // 64 rows x 32 bf162 per row, straight copy
        for (int i = t; i < 64*32; i += 256) {
            const int bb = i >> 5, kp = i & 31;
            *(__nv_bfloat162*)&ash[bb*72 + 2*kp] =
                *(const __nv_bfloat162*)&g_wpow_r[((size_t)r*Bz + bb)*NNv + nb + 2*kp];
        }
        for (int i = t; i < 64*64; i += 256) {
            const int kk = i >> 6, mm = i & 63;
            bsh[kk*72 + mm] = __float2bfloat16(g_m1[(size_t)(nb + kk)*Mv + mm]);
        }
        __syncthreads();

        #pragma unroll
        for (int kt = 0; kt < 4; kt++) {
            wmma::fragment<wmma::matrix_a, 16, 16, 16, __nv_bfloat16,
                           wmma::row_major> fa;
            wmma::load_matrix_sync(fa, &ash[(trow*16)*72 + kt*16], 72);
            wmma::fragment<wmma::matrix_b, 16, 16, 16, __nv_bfloat16,
                           wmma::row_major> fb0, fb1;
            wmma::load_matrix_sync(fb0, &bsh[(kt*16)*72 + (tcol0    )*16], 72);
            wmma::load_matrix_sync(fb1, &bsh[(kt*16)*72 + (tcol0 + 1)*16], 72);
            wmma::mma_sync(acc0, fa, fb0, acc0);
            wmma::mma_sync(acc1, fa, fb1, acc1);
        }
        __syncthreads();
    }

    const size_t base = ((size_t)r*ECHUNK + chunk) * (Bz*Mv);
    wmma::store_matrix_sync(&g_epart[base + (size_t)(trow*16)*Mv + (tcol0    )*16],
                            acc0, Mv, wmma::mem_row_major);
    wmma::store_matrix_sync(&g_epart[base + (size_t)(trow*16)*Mv + (tcol0 + 1)*16],
                            acc1, Mv, wmma::mem_row_major);
}

// ----- kernel 6: reduce split-K + fused read-total + transpose --------------
// Each block covers 256 consecutive outputs -> a single r. It computes its
// r's total from g_tpart deterministically, then reduces the split-K parts.
__global__ void reduce_out_kernel(float* __restrict__ out)
{
    __shared__ float red[256];
    const int t = threadIdx.x;
    const int gid = blockIdx.x*256 + t;   // 0..R*B*M-1
    const int r = gid >> 12;              // constant within the block
    const int b = (gid >> 6) & 63;
    const int m = gid & 63;

    {
        float s = 0.f;
        #pragma unroll
        for (int i = t; i < Bz*CSPBLK; i += 256)
            s += g_tpart[r*(Bz*CSPBLK) + i];
        red[t] = s; __syncthreads();
        for (int off = 128; off; off >>= 1) {
            if (t < off) red[t] += red[t+off];
            __syncthreads();
        }
    }
    const float inv = 1.f / (red[0] + 1e-5f);

    float s = 0.f;
    for (int c = 0; c < ECHUNK; c++)
        s += g_epart[(((size_t)r*ECHUNK + c)*Bz + b)*Mv + m];
    out[(size_t)b*(Rv*Mv) + r*Mv + m] = s * inv;
}

// ---------------------------------------------------------------------------
extern "C" void kernel_launch(void* const* d_in, const int* in_sizes, int n_in,
                              void* d_out, int out_size)
{
    const float* h_t     = (const float*)d_in[0];
    const float* ww      = (const float*)d_in[1];
    const float* wr      = (const float*)d_in[2];
    const float* memory  = (const float*)d_in[3];
    const float* key_w   = (const float*)d_in[4];
    const float* key_b   = (const float*)d_in[5];
    const float* beta_w  = (const float*)d_in[6];
    const float* beta_b  = (const float*)d_in[7];
    const float* gate_w  = (const float*)d_in[8];
    const float* gate_b  = (const float*)d_in[9];
    const float* shift_w = (const float*)d_in[10];
    const float* shift_b = (const float*)d_in[11];
    const float* gamma_w = (const float*)d_in[12];
    const float* gamma_b = (const float*)d_in[13];
    const float* erase_w = (const float*)d_in[14];
    const float* erase_b = (const float*)d_in[15];
    const float* add_w   = (const float*)d_in[16];
    const float* add_b   = (const float*)d_in[17];
    const int*   bank    = (const int*)d_in[18];
    float* out = (float*)d_out;

    // head params (shared by all 5 weight updates)
    heads_kernel<<<Bz, 256>>>(h_t, key_w, key_b, beta_w, beta_b, gate_w, gate_b,
                              shift_w, shift_b, gamma_w, gamma_b,
                              erase_w, erase_b, add_w, add_b);

    // --- write head: content addressing on m0, fused sumexp in csp ---
    sim_kernel<<<SIMBLK, 256>>>(memory, bank, 0);
    csp_write_kernel<<<dim3(CSPBLK, Bz), 256>>>(ww);

    // --- memory erase/add (fused write-total) ---
    memupdate_kernel<<<NNv/64, 256>>>(memory, bank);

    // --- read heads: shared content addressing on m1, all R heads/block ---
    sim_kernel<<<SIMBLK, 256>>>(memory, bank, 1);
    csp_read_kernel<<<dim3(CSPBLK, Bz), 256>>>(wr);

    // --- read: r[r,b,:] = (wpow_r[r,b,:]/total_r) @ m1 (fused read-totals) ---
    einsum_kernel<<<dim3(ECHUNK, Rv), 256>>>();
    reduce_out_kernel<<<(Rv*Bz*Mv)/256, 256>>>(out);
}

// round 15
// speedup vs baseline: 2.0909x; 1.1087x over previous
#include <cuda_runtime.h>
#include <cuda_bf16.h>
#include <mma.h>
#include <math.h>

using namespace nvcuda;

#define Bz 64
#define Hh 1024
#define NNv 65536
#define Mv 64
#define Rv 4
#define SIMBLK (NNv/64)   /* 1024 sim blocks */
#define CSPBLK 64         /* N/1024 csp blocks per b */
#define ECHUNK 128        /* einsum split-K chunks */
#define EK (NNv/ECHUNK)   /* 512 n per chunk */

// ---------------- scratch (device globals: no allocation allowed) ----------
__device__ __nv_bfloat16 g_E[(size_t)Bz*NNv];       // exp(beta*sim) [B,N] bf16
__device__ __nv_bfloat16 g_wpow_w[(size_t)Bz*NNv];  // write-head w_pow bf16
__device__ __nv_bfloat16 g_wpow_r[(size_t)Rv*Bz*NNv]; // read-head w_pow bf16
__device__ float g_m1[(size_t)NNv*Mv];              // updated memory
__device__ float g_kn[Bz*Mv];
__device__ float g_ev[Bz*Mv];
__device__ float g_av[Bz*Mv];
__device__ float g_beta[Bz];
__device__ float g_gate[Bz];
__device__ float g_gamma[Bz];
__device__ float g_shift[Bz*3];
__device__ float g_psum[(size_t)Bz*SIMBLK];         // per-block exp partial sums
__device__ float g_tpart[Rv*Bz*CSPBLK];             // per-block pow partial sums
__device__ float g_epart[(size_t)Rv*ECHUNK*Bz*Mv];  // einsum split-K partials

__device__ __forceinline__ float clip01(float x){ return fminf(fmaxf(x, 0.f), 1.f); }
// fast x^g for x > 0 (w_tilde strictly positive: gated softmax mix, s_j > 0)
__device__ __forceinline__ float fpow(float x, float g){ return __expf(g * __logf(x)); }

// ---------------- kernel 1: head projections (once per step) ---------------
__global__ void heads_kernel(const float* __restrict__ h,
    const float* __restrict__ key_w,   const float* __restrict__ key_b,
    const float* __restrict__ beta_w,  const float* __restrict__ beta_b,
    const float* __restrict__ gate_w,  const float* __restrict__ gate_b,
    const float* __restrict__ shift_w, const float* __restrict__ shift_b,
    const float* __restrict__ gamma_w, const float* __restrict__ gamma_b,
    const float* __restrict__ erase_w, const float* __restrict__ erase_b,
    const float* __restrict__ add_w,   const float* __restrict__ add_b)
{
    __shared__ float hs[Hh];
    __shared__ float ksh[Mv];
    __shared__ float sdot[6];
    __shared__ float sinv;
    const int b = blockIdx.x, t = threadIdx.x;
    for (int i = t; i < Hh; i += 256) hs[i] = h[(size_t)b*Hh + i];
    __syncthreads();

    if (t < 64) {
        float a0=0,a1=0,a2=0,a3=0;
        for (int j = 0; j < Hh; j += 4) {
            a0 = fmaf(hs[j  ], key_w[(j  )*Mv + t], a0);
            a1 = fmaf(hs[j+1], key_w[(j+1)*Mv + t], a1);
            a2 = fmaf(hs[j+2], key_w[(j+2)*Mv + t], a2);
            a3 = fmaf(hs[j+3], key_w[(j+3)*Mv + t], a3);
        }
        ksh[t] = clip01(a0+a1+a2+a3 + key_b[t]);
    } else if (t < 128) {
        const int m = t - 64;
        float a0=0,a1=0,a2=0,a3=0;
        for (int j = 0; j < Hh; j += 4) {
            a0 = fmaf(hs[j  ], erase_w[(j  )*Mv + m], a0);
            a1 = fmaf(hs[j+1], erase_w[(j+1)*Mv + m], a1);
            a2 = fmaf(hs[j+2], erase_w[(j+2)*Mv + m], a2);
            a3 = fmaf(hs[j+3], erase_w[(j+3)*Mv + m], a3);
        }
        g_ev[b*Mv + m] = clip01(a0+a1+a2+a3 + erase_b[m]);
    } else if (t < 192) {
        const int m = t - 128;
        float a0=0,a1=0,a2=0,a3=0;
        for (int j = 0; j < Hh; j += 4) {
            a0 = fmaf(hs[j  ], add_w[(j  )*Mv + m], a0);
            a1 = fmaf(hs[j+1], add_w[(j+1)*Mv + m], a1);
            a2 = fmaf(hs[j+2], add_w[(j+2)*Mv + m], a2);
            a3 = fmaf(hs[j+3], add_w[(j+3)*Mv + m], a3);
        }
        // relu then clip01 == clip01
        g_av[b*Mv + m] = clip01(a0+a1+a2+a3 + add_b[m]);
    } else if (t < 198) {
        const int d = t - 192;
        const float* w; int str, col;
        if      (d == 0) { w = beta_w;  str = 1; col = 0; }
        else if (d == 1) { w = gate_w;  str = 1; col = 0; }
        else if (d == 2) { w = gamma_w; str = 1; col = 0; }
        else             { w = shift_w; str = 3; col = d - 3; }
        float a0=0,a1=0;
        for (int j = 0; j < Hh; j += 2) {
            a0 = fmaf(hs[j  ], w[(j  )*str + col], a0);
            a1 = fmaf(hs[j+1], w[(j+1)*str + col], a1);
        }
        sdot[d] = a0 + a1;
    }
    __syncthreads();

    if (t < 32) {
        float v = ksh[t]*ksh[t] + ksh[t+32]*ksh[t+32];
        #pragma unroll
        for (int off = 16; off; off >>= 1) v += __shfl_xor_sync(0xffffffffu, v, off);
        if (t == 0) sinv = 1.f / (sqrtf(v) + 1e-8f);
    }
    __syncthreads();
    if (t < 64) g_kn[b*Mv + t] = ksh[t] * sinv;
    if (t == 0) {
        g_beta[b]  = fmaxf(sdot[0] + beta_b[0], 0.f);
        g_gate[b]  = clip01(sdot[1] + gate_b[0]);
        g_gamma[b] = 1.f + fmaxf(sdot[2] + gamma_b[0], 0.f);
        float x0 = sdot[3] + shift_b[0];
        float x1 = sdot[4] + shift_b[1];
        float x2 = sdot[5] + shift_b[2];
        float mx = fmaxf(x0, fmaxf(x1, x2));
        float e0 = expf(x0-mx), e1 = expf(x1-mx), e2 = expf(x2-mx);
        float is = 1.f / (e0+e1+e2);
        g_shift[b*3+0] = e0*is; g_shift[b*3+1] = e1*is; g_shift[b*3+2] = e2*is;
    }
}

// ------- kernel 2: E[b,n] = exp(beta[b] * (kn[b]·m[n]) / (||m[n]||+eps)) ---
__global__ void sim_kernel(const float* __restrict__ mem,
                           const int* __restrict__ bank, int use_m1)
{
    const float* __restrict__ src = use_m1 ? g_m1
                                           : (mem + (size_t)bank[0]*NNv*Mv);
    __shared__ __align__(16) float mt[64*68];   // [k][n], padded
    __shared__ __align__(16) float cs[64*68];   // [b][n] raw sim (k-dot)
    __shared__ float invn[64];
    __shared__ float sbeta[64];
    const int t = threadIdx.x;
    const int n0 = blockIdx.x * 64;

    for (int i = t; i < 64*64; i += 256) {
        int rr = i >> 6, cc = i & 63;
        mt[cc*68 + rr] = src[(size_t)(n0 + rr)*Mv + cc];
    }
    if (t < 64) sbeta[t] = g_beta[t];
    __syncthreads();
    if (t < 64) {
        float s = 0.f;
        #pragma unroll 16
        for (int k = 0; k < 64; k++) { float v = mt[k*68 + t]; s = fmaf(v, v, s); }
        invn[t] = 1.f / (sqrtf(s) + 1e-8f);
    }

    // WMMA: C[64b][64n] = kn[64b][64k] @ mt[64k][64n]
    const int warp  = t >> 5;
    const int brow  = warp >> 1;        // b-tile 0..3
    const int ncol0 = (warp & 1) * 2;   // n-tiles {0,1} or {2,3}
    wmma::fragment<wmma::accumulator, 16, 16, 8, float> acc0, acc1;
    wmma::fill_fragment(acc0, 0.f);
    wmma::fill_fragment(acc1, 0.f);
    #pragma unroll
    for (int kt = 0; kt < 8; kt++) {
        wmma::fragment<wmma::matrix_a, 16, 16, 8, wmma::precision::tf32,
                       wmma::row_major> fa;
        wmma::load_matrix_sync(fa, &g_kn[(brow*16)*Mv + kt*8], Mv);
        #pragma unroll
        for (int i = 0; i < fa.num_elements; i++)
            fa.x[i] = wmma::__float_to_tf32(fa.x[i]);
        wmma::fragment<wmma::matrix_b, 16, 16, 8, wmma::precision::tf32,
                       wmma::row_major> fb0, fb1;
        wmma::load_matrix_sync(fb0, &mt[(kt*8)*68 + (ncol0    )*16], 68);
        wmma::load_matrix_sync(fb1, &mt[(kt*8)*68 + (ncol0 + 1)*16], 68);
        #pragma unroll
        for (int i = 0; i < fb0.num_elements; i++) {
            fb0.x[i] = wmma::__float_to_tf32(fb0.x[i]);
            fb1.x[i] = wmma::__float_to_tf32(fb1.x[i]);
        }
        wmma::mma_sync(acc0, fa, fb0, acc0);
        wmma::mma_sync(acc1, fa, fb1, acc1);
    }
    wmma::store_matrix_sync(&cs[(brow*16)*68 + (ncol0    )*16], acc0, 68,
                            wmma::mem_row_major);
    wmma::store_matrix_sync(&cs[(brow*16)*68 + (ncol0 + 1)*16], acc1, 68,
                            wmma::mem_row_major);
    __syncthreads();

    // epilogue: scale by invn, exp, bf16 store, per-b partial sums
    const int by = t >> 5, nx = t & 31;   // 8 b's per thread, 2 n's per thread
    const float2 iv = *(const float2*)&invn[2*nx];
    float psum[8];
    #pragma unroll
    for (int bi = 0; bi < 8; bi++) {
        const int bb = 8*by + bi;
        const float bt = sbeta[bb];
        const float2 cv = *(const float2*)&cs[bb*68 + 2*nx];
        float e0 = __expf(bt * cv.x * iv.x);
        float e1 = __expf(bt * cv.y * iv.y);
        __nv_bfloat162 hv = __floats2bfloat162_rn(e0, e1);
        *(__nv_bfloat162*)&g_E[(size_t)bb*NNv + n0 + 2*nx] = hv;
        psum[bi] = __bfloat162float(hv.x) + __bfloat162float(hv.y);
    }
    #pragma unroll
    for (int bi = 0; bi < 8; bi++)
        #pragma unroll
        for (int off = 16; off; off >>= 1)
            psum[bi] += __shfl_xor_sync(0xffffffffu, psum[bi], off);
    if (nx == 0) {
        #pragma unroll
        for (int bi = 0; bi < 8; bi++)
            g_psum[(size_t)(8*by + bi)*SIMBLK + blockIdx.x] = psum[bi];
    }
}

// helper: load 4 consecutive bf16 values as floats
__device__ __forceinline__ float4 ld_e4(const __nv_bfloat16* p)
{
    const __nv_bfloat162 a = *(const __nv_bfloat162*)p;
    const __nv_bfloat162 b = *(const __nv_bfloat162*)(p + 2);
    float4 v;
    v.x = __bfloat162float(a.x); v.y = __bfloat162float(a.y);
    v.z = __bfloat162float(b.x); v.w = __bfloat162float(b.y);
    return v;
}

// ----- kernel 3a: WRITE head csp (fused sumexp, bf16 in/out) ----------------
__global__ void csp_write_kernel(const float* __restrict__ ww)
{
    const int b  = blockIdx.y;
    const int c0 = blockIdx.x * 1024;
    const float* __restrict__ wp = ww + (size_t)b*NNv;
    __nv_bfloat16* __restrict__ wo = g_wpow_w + (size_t)b*NNv;
    const __nv_bfloat16* __restrict__ Eb = g_E + (size_t)b*NNv;

    __shared__ __align__(16) float wg2[1032];
    __shared__ __align__(16) float red[256];
    const int t = threadIdx.x;

    // fused sumexp: deterministic block-local sum of g_psum[b][*]
    {
        float s = 0.f;
        #pragma unroll
        for (int i = t; i < SIMBLK; i += 256) s += g_psum[(size_t)b*SIMBLK + i];
        red[t] = s; __syncthreads();
        for (int off = 128; off; off >>= 1) {
            if (t < off) red[t] += red[t+off];
            __syncthreads();
        }
    }
    const float gg   = g_gate[b];
    const float invS = gg / red[0];        // gate folded into content scale
    const float omg  = 1.f - gg;
    const float s0 = g_shift[b*3+0], s1 = g_shift[b*3+1], s2 = g_shift[b*3+2];
    const float gm = g_gamma[b];

    {
        const int n = c0 + 4*t;
        const float4 e = ld_e4(&Eb[n]);
        const float4 w = *(const float4*)&wp[n];
        float4 v;
        v.x = fmaf(omg, w.x, e.x*invS);
        v.y = fmaf(omg, w.y, e.y*invS);
        v.z = fmaf(omg, w.z, e.z*invS);
        v.w = fmaf(omg, w.w, e.w*invS);
        *(float4*)&wg2[4*t] = v;
    }
    if (t == 0) {
        const int nl = c0 - 1;
        wg2[1025] = (nl >= 0)
            ? fmaf(omg, wp[nl], __bfloat162float(Eb[nl])*invS) : 0.f;
        const int nr = c0 + 1024;
        wg2[1024] = (nr < NNv)
            ? fmaf(omg, wp[nr], __bfloat162float(Eb[nr])*invS) : 0.f;
    }
    __syncthreads();

    const float4 f   = *(const float4*)&wg2[4*t];
    const float left  = wg2[(t == 0) ? 1025 : 4*t - 1];
    const float right = wg2[4*t + 4];   // t==255 lands on wg2[1024] = halo
    float4 o;
    o.x = fpow(fmaf(s0, left, fmaf(s1, f.x, s2*f.y)),  gm);
    o.y = fpow(fmaf(s0, f.x,  fmaf(s1, f.y, s2*f.z)),  gm);
    o.z = fpow(fmaf(s0, f.y,  fmaf(s1, f.z, s2*f.w)),  gm);
    o.w = fpow(fmaf(s0, f.z,  fmaf(s1, f.w, s2*right)), gm);
    __nv_bfloat162 o01 = __floats2bfloat162_rn(o.x, o.y);
    __nv_bfloat162 o23 = __floats2bfloat162_rn(o.z, o.w);
    *(__nv_bfloat162*)&wo[c0 + 4*t]     = o01;
    *(__nv_bfloat162*)&wo[c0 + 4*t + 2] = o23;

    red[t] = (__bfloat162float(o01.x) + __bfloat162float(o01.y))
           + (__bfloat162float(o23.x) + __bfloat162float(o23.y));
    __syncthreads();
    for (int off = 128; off; off >>= 1) { if (t < off) red[t] += red[t+off]; __syncthreads(); }
    if (t == 0) g_tpart[b*CSPBLK + blockIdx.x] = red[0];
}

// ----- kernel 3b: READ heads csp (fused sumexp, all R heads staged at once) -
__global__ void csp_read_kernel(const float* __restrict__ wr)
{
    const int b  = blockIdx.y;
    const int c0 = blockIdx.x * 1024;
    const __nv_bfloat16* __restrict__ Eb = g_E + (size_t)b*NNv;

    __shared__ __align__(16) float ec [1032];     // halo layout as before
    __shared__ __align__(16) float wg4[4*1032];   // all 4 heads staged
    __shared__ __align__(16) float sred[256];
    __shared__ __align__(16) float red32[32];
    const int t = threadIdx.x;
    const int warp = t >> 5, lane = t & 31;

    // fused sumexp
    {
        float s = 0.f;
        #pragma unroll
        for (int i = t; i < SIMBLK; i += 256) s += g_psum[(size_t)b*SIMBLK + i];
        sred[t] = s; __syncthreads();
        for (int off = 128; off; off >>= 1) {
            if (t < off) sred[t] += sred[t+off];
            __syncthreads();
        }
    }
    const float gg   = g_gate[b];
    const float omg  = 1.f - gg;
    const float invS = gg / sred[0];
    const float s0 = g_shift[b*3+0], s1 = g_shift[b*3+1], s2 = g_shift[b*3+2];
    const float gm = g_gamma[b];
    __syncthreads();   // all threads read sred[0] before any reuse

    // stage gated content + all 4 heads (independent streams -> MLP)
    {
        const int n = c0 + 4*t;
        const float4 e = ld_e4(&Eb[n]);
        float4 ev;
        ev.x = e.x*invS; ev.y = e.y*invS; ev.z = e.z*invS; ev.w = e.w*invS;
        *(float4*)&ec[4*t] = ev;
        #pragma unroll
        for (int r = 0; r < Rv; r++) {
            const float4 w = *(const float4*)&wr[((size_t)r*Bz + b)*NNv + n];
            float4 v;
            v.x = fmaf(omg, w.x, ev.x);
            v.y = fmaf(omg, w.y, ev.y);
            v.z = fmaf(omg, w.z, ev.z);
            v.w = fmaf(omg, w.w, ev.w);
            *(float4*)&wg4[r*1032 + 4*t] = v;
        }
    }
    if (t < 8) {   // halos: t>>1 = r, t&1 = side (0=right,1=left)
        const int r = t >> 1;
        const float* __restrict__ wp = wr + ((size_t)r*Bz + b)*NNv;
        if (t & 1) {
            const int nl = c0 - 1;
            wg4[r*1032 + 1025] = (nl >= 0)
                ? fmaf(omg, wp[nl], __bfloat162float(Eb[nl])*invS) : 0.f;
        } else {
            const int nr = c0 + 1024;
            wg4[r*1032 + 1024] = (nr < NNv)
                ? fmaf(omg, wp[nr], __bfloat162float(Eb[nr])*invS) : 0.f;
        }
    }
    __syncthreads();

    float ls[4];
    #pragma unroll
    for (int r = 0; r < Rv; r++) {
        const float* w = &wg4[r*1032];
        __nv_bfloat16* __restrict__ wo = g_wpow_r + ((size_t)r*Bz + b)*NNv;
        const float4 f   = *(const float4*)&w[4*t];
        const float left  = w[(t == 0) ? 1025 : 4*t - 1];
        const float right = w[4*t + 4];
        float4 o;
        o.x = fpow(fmaf(s0, left, fmaf(s1, f.x, s2*f.y)),  gm);
        o.y = fpow(fmaf(s0, f.x,  fmaf(s1, f.y, s2*f.z)),  gm);
        o.z = fpow(fmaf(s0, f.y,  fmaf(s1, f.z, s2*f.w)),  gm);
        o.w = fpow(fmaf(s0, f.z,  fmaf(s1, f.w, s2*right)), gm);
        __nv_bfloat162 o01 = __floats2bfloat162_rn(o.x, o.y);
        __nv_bfloat162 o23 = __floats2bfloat162_rn(o.z, o.w);
        *(__nv_bfloat162*)&wo[c0 + 4*t]     = o01;
        *(__nv_bfloat162*)&wo[c0 + 4*t + 2] = o23;
        ls[r] = (__bfloat162float(o01.x) + __bfloat162float(o01.y))
              + (__bfloat162float(o23.x) + __bfloat162float(o23.y));
    }

    // combined reduction: warp shuffles, then 8 warp-partials per r
    #pragma unroll
    for (int r = 0; r < Rv; r++)
        #pragma unroll
        for (int off = 16; off; off >>= 1)
            ls[r] += __shfl_xor_sync(0xffffffffu, ls[r], off);
    if (lane == 0) {
        #pragma unroll
        for (int r = 0; r < Rv; r++) red32[r*8 + warp] = ls[r];
    }
    __syncthreads();
    if (t < Rv) {
        float s = 0.f;
        #pragma unroll
        for (int w = 0; w < 8; w++) s += red32[t*8 + w];
        g_tpart[t*(Bz*CSPBLK) + b*CSPBLK + blockIdx.x] = s;
    }
}

// --- kernel 4: m1 = m0*(1 - inv*W^T e) + inv*W^T a  (bf16 WMMA) -------------
// A col_major: (row=n, col=b) at wsh[b*72 + n] (natural [b][n] bf16 staging).
// Write-head total reduction DEFERRED to after the MMAs; inv applied in the
// epilogue algebraically (removes the serialized prelude).
__global__ void memupdate_kernel(const float* __restrict__ mem,
                                 const int* __restrict__ bank)
{
    const float* __restrict__ m0 = mem + (size_t)bank[0]*NNv*Mv;
    __shared__ __align__(16) char smbuf[33024];
    __nv_bfloat16* wsh = (__nv_bfloat16*)smbuf;            // [b][n], ld=72
    __nv_bfloat16* esh = (__nv_bfloat16*)(smbuf + 9216);   // [b][m], ld=72
    __nv_bfloat16* ash = (__nv_bfloat16*)(smbuf + 18432);  // [b][m], ld=72
    __shared__ float red8[8];
    const int t = threadIdx.x;
    const int warp = t >> 5, lane = t & 31;
    const int n0 = blockIdx.x * 64;

    // stage W (bf16 straight copy), e, a (fp32->bf16), all unscaled
    for (int i = t; i < 64*32; i += 256) {
        const int bb = i >> 5, kp = i & 31;
        *(__nv_bfloat162*)&wsh[bb*72 + 2*kp] =
            *(const __nv_bfloat162*)&g_wpow_w[(size_t)bb*NNv + n0 + 2*kp];
    }
    for (int i = t; i < 64*64; i += 256) {
        const int bb = i >> 6, mm = i & 63;
        esh[bb*72 + mm] = __float2bfloat16(g_ev[i]);
        ash[bb*72 + mm] = __float2bfloat16(g_av[i]);
    }
    __syncthreads();

    const int nrow  = warp >> 1;        // n-tile 0..3
    const int mcol0 = (warp & 1) * 2;   // m-tiles {0,1} or {2,3}
    wmma::fragment<wmma::accumulator, 16, 16, 16, float> ce0, ce1, ca0, ca1;
    wmma::fill_fragment(ce0, 0.f); wmma::fill_fragment(ce1, 0.f);
    wmma::fill_fragment(ca0, 0.f); wmma::fill_fragment(ca1, 0.f);

    #pragma unroll
    for (int kt = 0; kt < 4; kt++) {
        wmma::fragment<wmma::matrix_a, 16, 16, 16, __nv_bfloat16,
                       wmma::col_major> fa;
        wmma::load_matrix_sync(fa, &wsh[(kt*16)*72 + nrow*16], 72);
        wmma::fragment<wmma::matrix_b, 16, 16, 16, __nv_bfloat16,
                       wmma::row_major> fe0, fe1, fd0, fd1;
        wmma::load_matrix_sync(fe0, &esh[(kt*16)*72 + (mcol0    )*16], 72);
        wmma::load_matrix_sync(fe1, &esh[(kt*16)*72 + (mcol0 + 1)*16], 72);
        wmma::load_matrix_sync(fd0, &ash[(kt*16)*72 + (mcol0    )*16], 72);
        wmma::load_matrix_sync(fd1, &ash[(kt*16)*72 + (mcol0 + 1)*16], 72);
        wmma::mma_sync(ce0, fa, fe0, ce0);
        wmma::mma_sync(ce1, fa, fe1, ce1);
        wmma::mma_sync(ca0, fa, fd0, ca0);
        wmma::mma_sync(ca1, fa, fd1, ca1);
    }

    // deferred write-head total (deterministic; overlaps MMA tail)
    float s = 0.f;
    #pragma unroll
    for (int i = t; i < Bz*CSPBLK; i += 256) s += g_tpart[i];
    #pragma unroll
    for (int off = 16; off; off >>= 1) s += __shfl_xor_sync(0xffffffffu, s, off);
    if (lane == 0) red8[warp] = s;
    __syncthreads();   // guards red8 AND all MMA smem reads before overwrite
    float tot = 0.f;
    #pragma unroll
    for (int w = 0; w < 8; w++) tot += red8[w];
    const float inv = 1.f / (tot + 1e-5f);

    float* ce_s = (float*)smbuf;             // [n][m], ld=64 (aliases staging)
    float* ca_s = (float*)(smbuf + 16384);
    wmma::store_matrix_sync(&ce_s[(nrow*16)*64 + (mcol0    )*16], ce0, 64,
                            wmma::mem_row_major);
    wmma::store_matrix_sync(&ce_s[(nrow*16)*64 + (mcol0 + 1)*16], ce1, 64,
                            wmma::mem_row_major);
    wmma::store_matrix_sync(&ca_s[(nrow*16)*64 + (mcol0    )*16], ca0, 64,
                            wmma::mem_row_major);
    wmma::store_matrix_sync(&ca_s[(nrow*16)*64 + (mcol0 + 1)*16], ca1, 64,
                            wmma::mem_row_major);
    __syncthreads();

    #pragma unroll
    for (int j = 0; j < 4; j++) {
        const int idx = j*1024 + 4*t;          // element index in 64x64 tile
        const int nl = idx >> 6, mm = idx & 63;
        const size_t n = (size_t)(n0 + nl);
        const float4 o  = *(const float4*)&m0  [n*Mv + mm];
        const float4 ce = *(const float4*)&ce_s[nl*64 + mm];
        const float4 ca = *(const float4*)&ca_s[nl*64 + mm];
        float4 v;
        v.x = fmaf(o.x, 1.f - inv*ce.x, inv*ca.x);
        v.y = fmaf(o.y, 1.f - inv*ce.y, inv*ca.y);
        v.z = fmaf(o.z, 1.f - inv*ce.z, inv*ca.z);
        v.w = fmaf(o.w, 1.f - inv*ce.w, inv*ca.w);
        *(float4*)&g_m1[n*Mv + mm] = v;
    }
}

// ----- kernel 5: split-K read einsum partials (bf16 WMMA tensor cores) -----
__global__ void einsum_kernel()
{
    __shared__ __align__(16) __nv_bfloat16 ash[64*72];  // [b][k], ld=72
    __shared__ __align__(16) __nv_bfloat16 bsh[64*72];  // [k][m], ld=72
    const int chunk = blockIdx.x, r = blockIdx.y;
    const int n0 = chunk * EK;
    const int t = threadIdx.x;
    const int warp  = t >> 5;
    const int trow  = warp >> 1;          // b-tile: 0..3
    const int tcol0 = (warp & 1) * 2;     // m-tiles: {0,1} or {2,3}

    wmma::fragment<wmma::accumulator, 16, 16, 16, float> acc0, acc1;
    wmma::fill_fragment(acc0, 0.f);
    wmma::fill_fragment(acc1, 0.f);

    for (int sub = 0; sub < EK/64; sub++) {
        const int nb = n0 + sub*64;
        // 64 rows x 32 bf162 per row, straight copy
        for (int i = t; i < 64*32; i += 256) {
            const int bb = i >> 5, kp = i & 31;
            *(__nv_bfloat162*)&ash[bb*72 + 2*kp] =
                *(const __nv_bfloat162*)&g_wpow_r[((size_t)r*Bz + bb)*NNv + nb + 2*kp];
        }
        for (int i = t; i < 64*64; i += 256) {
            const int kk = i >> 6, mm = i & 63;
            bsh[kk*72 + mm] = __float2bfloat16(g_m1[(size_t)(nb + kk)*Mv + mm]);
        }
        __syncthreads();

        #pragma unroll
        for (int kt = 0; kt < 4; kt++) {
            wmma::fragment<wmma::matrix_a, 16, 16, 16, __nv_bfloat16,
                           wmma::row_major> fa;
            wmma::load_matrix_sync(fa, &ash[(trow*16)*72 + kt*16], 72);
            wmma::fragment<wmma::matrix_b, 16, 16, 16, __nv_bfloat16,
                           wmma::row_major> fb0, fb1;
            wmma::load_matrix_sync(fb0, &bsh[(kt*16)*72 + (tcol0    )*16], 72);
            wmma::load_matrix_sync(fb1, &bsh[(kt*16)*72 + (tcol0 + 1)*16], 72);
            wmma::mma_sync(acc0, fa, fb0, acc0);
            wmma::mma_sync(acc1, fa, fb1, acc1);
        }
        __syncthreads();
    }

    const size_t base = ((size_t)r*ECHUNK + chunk) * (Bz*Mv);
    wmma::store_matrix_sync(&g_epart[base + (size_t)(trow*16)*Mv + (tcol0    )*16],
                            acc0, Mv, wmma::mem_row_major);
    wmma::store_matrix_sync(&g_epart[base + (size_t)(trow*16)*Mv + (tcol0 + 1)*16],
                            acc1, Mv, wmma::mem_row_major);
}

// ----- kernel 6: reduce split-K + fused read-total + transpose --------------
__global__ void reduce_out_kernel(float* __restrict__ out)
{
    __shared__ float red[256];
    const int t = threadIdx.x;
    const int gid = blockIdx.x*256 + t;   // 0..R*B*M-1
    const int r = gid >> 12;              // constant within the block
    const int b = (gid >> 6) & 63;
    const int m = gid & 63;

    {
        float s = 0.f;
        #pragma unroll
        for (int i = t; i < Bz*CSPBLK; i += 256)
            s += g_tpart[r*(Bz*CSPBLK) + i];
        red[t] = s; __syncthreads();
        for (int off = 128; off; off >>= 1) {
            if (t < off) red[t] += red[t+off];
            __syncthreads();
        }
    }
    const float inv = 1.f / (red[0] + 1e-5f);

    float s = 0.f;
    for (int c = 0; c < ECHUNK; c++)
        s += g_epart[(((size_t)r*ECHUNK + c)*Bz + b)*Mv + m];
    out[(size_t)b*(Rv*Mv) + r*Mv + m] = s * inv;
}

// ---------------------------------------------------------------------------
extern "C" void kernel_launch(void* const* d_in, const int* in_sizes, int n_in,
                              void* d_out, int out_size)
{
    const float* h_t     = (const float*)d_in[0];
    const float* ww      = (const float*)d_in[1];
    const float* wr      = (const float*)d_in[2];
    const float* memory  = (const float*)d_in[3];
    const float* key_w   = (const float*)d_in[4];
    const float* key_b   = (const float*)d_in[5];
    const float* beta_w  = (const float*)d_in[6];
    const float* beta_b  = (const float*)d_in[7];
    const float* gate_w  = (const float*)d_in[8];
    const float* gate_b  = (const float*)d_in[9];
    const float* shift_w = (const float*)d_in[10];
    const float* shift_b = (const float*)d_in[11];
    const float* gamma_w = (const float*)d_in[12];
    const float* gamma_b = (const float*)d_in[13];
    const float* erase_w = (const float*)d_in[14];
    const float* erase_b = (const float*)d_in[15];
    const float* add_w   = (const float*)d_in[16];
    const float* add_b   = (const float*)d_in[17];
    const int*   bank    = (const int*)d_in[18];
    float* out = (float*)d_out;

    // head params (shared by all 5 weight updates)
    heads_kernel<<<Bz, 256>>>(h_t, key_w, key_b, beta_w, beta_b, gate_w, gate_b,
                              shift_w, shift_b, gamma_w, gamma_b,
                              erase_w, erase_b, add_w, add_b);

    // --- write head: content addressing on m0, fused sumexp in csp ---
    sim_kernel<<<SIMBLK, 256>>>(memory, bank, 0);
    csp_write_kernel<<<dim3(CSPBLK, Bz), 256>>>(ww);

    // --- memory erase/add (bf16 MMA, deferred write-total) ---
    memupdate_kernel<<<NNv/64, 256>>>(memory, bank);

    // --- read heads: shared content addressing on m1, all R heads/block ---
    sim_kernel<<<SIMBLK, 256>>>(memory, bank, 1);
    csp_read_kernel<<<dim3(CSPBLK, Bz), 256>>>(wr);

    // --- read: r[r,b,:] = (wpow_r[r,b,:]/total_r) @ m1 (fused read-totals) ---
    einsum_kernel<<<dim3(ECHUNK, Rv), 256>>>();
    reduce_out_kernel<<<(Rv*Bz*Mv)/256, 256>>>(out);
}

// round 16
// speedup vs baseline: 2.1298x; 1.0186x over previous
#include <cuda_runtime.h>
#include <cuda_bf16.h>
#include <mma.h>
#include <math.h>

using namespace nvcuda;

#define Bz 64
#define Hh 1024
#define NNv 65536
#define Mv 64
#define Rv 4
#define SIMBLK (NNv/64)   /* 1024 sim blocks */
#define CSPBLK 64         /* N/1024 csp blocks per b */
#define ECHUNK 128        /* einsum split-K chunks */
#define EK (NNv/ECHUNK)   /* 512 n per chunk */

// ---------------- scratch (device globals: no allocation allowed) ----------
__device__ __nv_bfloat16 g_E[(size_t)Bz*NNv];       // exp(beta*sim) [B,N] bf16
__device__ __nv_bfloat16 g_wpow_w[(size_t)Bz*NNv];  // write-head w_pow bf16
__device__ __nv_bfloat16 g_wpow_r[(size_t)Rv*Bz*NNv]; // read-head w_pow bf16
__device__ float g_m1[(size_t)NNv*Mv];              // updated memory
__device__ float g_kn[Bz*Mv];
__device__ float g_ev[Bz*Mv];
__device__ float g_av[Bz*Mv];
__device__ float g_beta[Bz];
__device__ float g_gate[Bz];
__device__ float g_gamma[Bz];
__device__ float g_shift[Bz*3];
__device__ float g_psum[(size_t)Bz*SIMBLK];         // per-block exp partial sums
__device__ float g_tpart[Rv*Bz*CSPBLK];             // per-block pow partial sums
__device__ float g_epart[(size_t)Rv*ECHUNK*Bz*Mv];  // einsum split-K partials

__device__ __forceinline__ float clip01(float x){ return fminf(fmaxf(x, 0.f), 1.f); }
// fast x^g for x > 0 (w_tilde strictly positive: gated softmax mix, s_j > 0)
__device__ __forceinline__ float fpow(float x, float g){ return __expf(g * __logf(x)); }

// ---------------- kernel 1: head projections (once per step) ---------------
__global__ void heads_kernel(const float* __restrict__ h,
    const float* __restrict__ key_w,   const float* __restrict__ key_b,
    const float* __restrict__ beta_w,  const float* __restrict__ beta_b,
    const float* __restrict__ gate_w,  const float* __restrict__ gate_b,
    const float* __restrict__ shift_w, const float* __restrict__ shift_b,
    const float* __restrict__ gamma_w, const float* __restrict__ gamma_b,
    const float* __restrict__ erase_w, const float* __restrict__ erase_b,
    const float* __restrict__ add_w,   const float* __restrict__ add_b)
{
    __shared__ float hs[Hh];
    __shared__ float ksh[Mv];
    __shared__ float sdot[6];
    __shared__ float sinv;
    const int b = blockIdx.x, t = threadIdx.x;
    for (int i = t; i < Hh; i += 256) hs[i] = h[(size_t)b*Hh + i];
    __syncthreads();

    if (t < 64) {
        float a0=0,a1=0,a2=0,a3=0;
        for (int j = 0; j < Hh; j += 4) {
            a0 = fmaf(hs[j  ], key_w[(j  )*Mv + t], a0);
            a1 = fmaf(hs[j+1], key_w[(j+1)*Mv + t], a1);
            a2 = fmaf(hs[j+2], key_w[(j+2)*Mv + t], a2);
            a3 = fmaf(hs[j+3], key_w[(j+3)*Mv + t], a3);
        }
        ksh[t] = clip01(a0+a1+a2+a3 + key_b[t]);
    } else if (t < 128) {
        const int m = t - 64;
        float a0=0,a1=0,a2=0,a3=0;
        for (int j = 0; j < Hh; j += 4) {
            a0 = fmaf(hs[j  ], erase_w[(j  )*Mv + m], a0);
            a1 = fmaf(hs[j+1], erase_w[(j+1)*Mv + m], a1);
            a2 = fmaf(hs[j+2], erase_w[(j+2)*Mv + m], a2);
            a3 = fmaf(hs[j+3], erase_w[(j+3)*Mv + m], a3);
        }
        g_ev[b*Mv + m] = clip01(a0+a1+a2+a3 + erase_b[m]);
    } else if (t < 192) {
        const int m = t - 128;
        float a0=0,a1=0,a2=0,a3=0;
        for (int j = 0; j < Hh; j += 4) {
            a0 = fmaf(hs[j  ], add_w[(j  )*Mv + m], a0);
            a1 = fmaf(hs[j+1], add_w[(j+1)*Mv + m], a1);
            a2 = fmaf(hs[j+2], add_w[(j+2)*Mv + m], a2);
            a3 = fmaf(hs[j+3], add_w[(j+3)*Mv + m], a3);
        }
        // relu then clip01 == clip01
        g_av[b*Mv + m] = clip01(a0+a1+a2+a3 + add_b[m]);
    } else if (t < 198) {
        const int d = t - 192;
        const float* w; int str, col;
        if      (d == 0) { w = beta_w;  str = 1; col = 0; }
        else if (d == 1) { w = gate_w;  str = 1; col = 0; }
        else if (d == 2) { w = gamma_w; str = 1; col = 0; }
        else             { w = shift_w; str = 3; col = d - 3; }
        float a0=0,a1=0;
        for (int j = 0; j < Hh; j += 2) {
            a0 = fmaf(hs[j  ], w[(j  )*str + col], a0);
            a1 = fmaf(hs[j+1], w[(j+1)*str + col], a1);
        }
        sdot[d] = a0 + a1;
    }
    __syncthreads();

    if (t < 32) {
        float v = ksh[t]*ksh[t] + ksh[t+32]*ksh[t+32];
        #pragma unroll
        for (int off = 16; off; off >>= 1) v += __shfl_xor_sync(0xffffffffu, v, off);
        if (t == 0) sinv = 1.f / (sqrtf(v) + 1e-8f);
    }
    __syncthreads();
    if (t < 64) g_kn[b*Mv + t] = ksh[t] * sinv;
    if (t == 0) {
        g_beta[b]  = fmaxf(sdot[0] + beta_b[0], 0.f);
        g_gate[b]  = clip01(sdot[1] + gate_b[0]);
        g_gamma[b] = 1.f + fmaxf(sdot[2] + gamma_b[0], 0.f);
        float x0 = sdot[3] + shift_b[0];
        float x1 = sdot[4] + shift_b[1];
        float x2 = sdot[5] + shift_b[2];
        float mx = fmaxf(x0, fmaxf(x1, x2));
        float e0 = expf(x0-mx), e1 = expf(x1-mx), e2 = expf(x2-mx);
        float is = 1.f / (e0+e1+e2);
        g_shift[b*3+0] = e0*is; g_shift[b*3+1] = e1*is; g_shift[b*3+2] = e2*is;
    }
}

// ------- kernel 2: E[b,n] = exp(beta[b] * (kn[b]·m0[n]) / (||m0[n]||+eps)) -
// (write-head pass only; the m1 pass is fused into memupdate_sim_kernel)
__global__ void sim_kernel(const float* __restrict__ mem,
                           const int* __restrict__ bank)
{
    const float* __restrict__ src = mem + (size_t)bank[0]*NNv*Mv;
    __shared__ __align__(16) float mt[64*68];   // [k][n], padded
    __shared__ __align__(16) float cs[64*68];   // [b][n] raw sim (k-dot)
    __shared__ float invn[64];
    __shared__ float sbeta[64];
    const int t = threadIdx.x;
    const int n0 = blockIdx.x * 64;

    for (int i = t; i < 64*64; i += 256) {
        int rr = i >> 6, cc = i & 63;
        mt[cc*68 + rr] = src[(size_t)(n0 + rr)*Mv + cc];
    }
    if (t < 64) sbeta[t] = g_beta[t];
    __syncthreads();
    if (t < 64) {
        float s = 0.f;
        #pragma unroll 16
        for (int k = 0; k < 64; k++) { float v = mt[k*68 + t]; s = fmaf(v, v, s); }
        invn[t] = 1.f / (sqrtf(s) + 1e-8f);
    }

    // WMMA: C[64b][64n] = kn[64b][64k] @ mt[64k][64n]
    const int warp  = t >> 5;
    const int brow  = warp >> 1;        // b-tile 0..3
    const int ncol0 = (warp & 1) * 2;   // n-tiles {0,1} or {2,3}
    wmma::fragment<wmma::accumulator, 16, 16, 8, float> acc0, acc1;
    wmma::fill_fragment(acc0, 0.f);
    wmma::fill_fragment(acc1, 0.f);
    #pragma unroll
    for (int kt = 0; kt < 8; kt++) {
        wmma::fragment<wmma::matrix_a, 16, 16, 8, wmma::precision::tf32,
                       wmma::row_major> fa;
        wmma::load_matrix_sync(fa, &g_kn[(brow*16)*Mv + kt*8], Mv);
        #pragma unroll
        for (int i = 0; i < fa.num_elements; i++)
            fa.x[i] = wmma::__float_to_tf32(fa.x[i]);
        wmma::fragment<wmma::matrix_b, 16, 16, 8, wmma::precision::tf32,
                       wmma::row_major> fb0, fb1;
        wmma::load_matrix_sync(fb0, &mt[(kt*8)*68 + (ncol0    )*16], 68);
        wmma::load_matrix_sync(fb1, &mt[(kt*8)*68 + (ncol0 + 1)*16], 68);
        #pragma unroll
        for (int i = 0; i < fb0.num_elements; i++) {
            fb0.x[i] = wmma::__float_to_tf32(fb0.x[i]);
            fb1.x[i] = wmma::__float_to_tf32(fb1.x[i]);
        }
        wmma::mma_sync(acc0, fa, fb0, acc0);
        wmma::mma_sync(acc1, fa, fb1, acc1);
    }
    wmma::store_matrix_sync(&cs[(brow*16)*68 + (ncol0    )*16], acc0, 68,
                            wmma::mem_row_major);
    wmma::store_matrix_sync(&cs[(brow*16)*68 + (ncol0 + 1)*16], acc1, 68,
                            wmma::mem_row_major);
    __syncthreads();

    // epilogue: scale by invn, exp, bf16 store, per-b partial sums
    const int by = t >> 5, nx = t & 31;   // 8 b's per thread, 2 n's per thread
    const float2 iv = *(const float2*)&invn[2*nx];
    float psum[8];
    #pragma unroll
    for (int bi = 0; bi < 8; bi++) {
        const int bb = 8*by + bi;
        const float bt = sbeta[bb];
        const float2 cv = *(const float2*)&cs[bb*68 + 2*nx];
        float e0 = __expf(bt * cv.x * iv.x);
        float e1 = __expf(bt * cv.y * iv.y);
        __nv_bfloat162 hv = __floats2bfloat162_rn(e0, e1);
        *(__nv_bfloat162*)&g_E[(size_t)bb*NNv + n0 + 2*nx] = hv;
        psum[bi] = __bfloat162float(hv.x) + __bfloat162float(hv.y);
    }
    #pragma unroll
    for (int bi = 0; bi < 8; bi++)
        #pragma unroll
        for (int off = 16; off; off >>= 1)
            psum[bi] += __shfl_xor_sync(0xffffffffu, psum[bi], off);
    if (nx == 0) {
        #pragma unroll
        for (int bi = 0; bi < 8; bi++)
            g_psum[(size_t)(8*by + bi)*SIMBLK + blockIdx.x] = psum[bi];
    }
}

// helper: load 4 consecutive bf16 values as floats
__device__ __forceinline__ float4 ld_e4(const __nv_bfloat16* p)
{
    const __nv_bfloat162 a = *(const __nv_bfloat162*)p;
    const __nv_bfloat162 b = *(const __nv_bfloat162*)(p + 2);
    float4 v;
    v.x = __bfloat162float(a.x); v.y = __bfloat162float(a.y);
    v.z = __bfloat162float(b.x); v.w = __bfloat162float(b.y);
    return v;
}

// ----- kernel 3a: WRITE head csp (fused sumexp, bf16 in/out) ----------------
__global__ void csp_write_kernel(const float* __restrict__ ww)
{
    const int b  = blockIdx.y;
    const int c0 = blockIdx.x * 1024;
    const float* __restrict__ wp = ww + (size_t)b*NNv;
    __nv_bfloat16* __restrict__ wo = g_wpow_w + (size_t)b*NNv;
    const __nv_bfloat16* __restrict__ Eb = g_E + (size_t)b*NNv;

    __shared__ __align__(16) float wg2[1032];
    __shared__ __align__(16) float red[256];
    const int t = threadIdx.x;

    // fused sumexp: deterministic block-local sum of g_psum[b][*]
    {
        float s = 0.f;
        #pragma unroll
        for (int i = t; i < SIMBLK; i += 256) s += g_psum[(size_t)b*SIMBLK + i];
        red[t] = s; __syncthreads();
        for (int off = 128; off; off >>= 1) {
            if (t < off) red[t] += red[t+off];
            __syncthreads();
        }
    }
    const float gg   = g_gate[b];
    const float invS = gg / red[0];        // gate folded into content scale
    const float omg  = 1.f - gg;
    const float s0 = g_shift[b*3+0], s1 = g_shift[b*3+1], s2 = g_shift[b*3+2];
    const float gm = g_gamma[b];

    {
        const int n = c0 + 4*t;
        const float4 e = ld_e4(&Eb[n]);
        const float4 w = *(const float4*)&wp[n];
        float4 v;
        v.x = fmaf(omg, w.x, e.x*invS);
        v.y = fmaf(omg, w.y, e.y*invS);
        v.z = fmaf(omg, w.z, e.z*invS);
        v.w = fmaf(omg, w.w, e.w*invS);
        *(float4*)&wg2[4*t] = v;
    }
    if (t == 0) {
        const int nl = c0 - 1;
        wg2[1025] = (nl >= 0)
            ? fmaf(omg, wp[nl], __bfloat162float(Eb[nl])*invS) : 0.f;
        const int nr = c0 + 1024;
        wg2[1024] = (nr < NNv)
            ? fmaf(omg, wp[nr], __bfloat162float(Eb[nr])*invS) : 0.f;
    }
    __syncthreads();

    const float4 f   = *(const float4*)&wg2[4*t];
    const float left  = wg2[(t == 0) ? 1025 : 4*t - 1];
    const float right = wg2[4*t + 4];   // t==255 lands on wg2[1024] = halo
    float4 o;
    o.x = fpow(fmaf(s0, left, fmaf(s1, f.x, s2*f.y)),  gm);
    o.y = fpow(fmaf(s0, f.x,  fmaf(s1, f.y, s2*f.z)),  gm);
    o.z = fpow(fmaf(s0, f.y,  fmaf(s1, f.z, s2*f.w)),  gm);
    o.w = fpow(fmaf(s0, f.z,  fmaf(s1, f.w, s2*right)), gm);
    __nv_bfloat162 o01 = __floats2bfloat162_rn(o.x, o.y);
    __nv_bfloat162 o23 = __floats2bfloat162_rn(o.z, o.w);
    *(__nv_bfloat162*)&wo[c0 + 4*t]     = o01;
    *(__nv_bfloat162*)&wo[c0 + 4*t + 2] = o23;

    red[t] = (__bfloat162float(o01.x) + __bfloat162float(o01.y))
           + (__bfloat162float(o23.x) + __bfloat162float(o23.y));
    __syncthreads();
    for (int off = 128; off; off >>= 1) { if (t < off) red[t] += red[t+off]; __syncthreads(); }
    if (t == 0) g_tpart[b*CSPBLK + blockIdx.x] = red[0];
}

// ----- kernel 3b: READ heads csp (fused sumexp, all R heads staged at once) -
__global__ void csp_read_kernel(const float* __restrict__ wr)
{
    const int b  = blockIdx.y;
    const int c0 = blockIdx.x * 1024;
    const __nv_bfloat16* __restrict__ Eb = g_E + (size_t)b*NNv;

    __shared__ __align__(16) float ec [1032];     // halo layout as before
    __shared__ __align__(16) float wg4[4*1032];   // all 4 heads staged
    __shared__ __align__(16) float sred[256];
    __shared__ __align__(16) float red32[32];
    const int t = threadIdx.x;
    const int warp = t >> 5, lane = t & 31;

    // fused sumexp
    {
        float s = 0.f;
        #pragma unroll
        for (int i = t; i < SIMBLK; i += 256) s += g_psum[(size_t)b*SIMBLK + i];
        sred[t] = s; __syncthreads();
        for (int off = 128; off; off >>= 1) {
            if (t < off) sred[t] += sred[t+off];
            __syncthreads();
        }
    }
    const float gg   = g_gate[b];
    const float omg  = 1.f - gg;
    const float invS = gg / sred[0];
    const float s0 = g_shift[b*3+0], s1 = g_shift[b*3+1], s2 = g_shift[b*3+2];
    const float gm = g_gamma[b];
    __syncthreads();   // all threads read sred[0] before any reuse

    // stage gated content + all 4 heads (independent streams -> MLP)
    {
        const int n = c0 + 4*t;
        const float4 e = ld_e4(&Eb[n]);
        float4 ev;
        ev.x = e.x*invS; ev.y = e.y*invS; ev.z = e.z*invS; ev.w = e.w*invS;
        *(float4*)&ec[4*t] = ev;
        #pragma unroll
        for (int r = 0; r < Rv; r++) {
            const float4 w = *(const float4*)&wr[((size_t)r*Bz + b)*NNv + n];
            float4 v;
            v.x = fmaf(omg, w.x, ev.x);
            v.y = fmaf(omg, w.y, ev.y);
            v.z = fmaf(omg, w.z, ev.z);
            v.w = fmaf(omg, w.w, ev.w);
            *(float4*)&wg4[r*1032 + 4*t] = v;
        }
    }
    if (t < 8) {   // halos: t>>1 = r, t&1 = side (0=right,1=left)
        const int r = t >> 1;
        const float* __restrict__ wp = wr + ((size_t)r*Bz + b)*NNv;
        if (t & 1) {
            const int nl = c0 - 1;
            wg4[r*1032 + 1025] = (nl >= 0)
                ? fmaf(omg, wp[nl], __bfloat162float(Eb[nl])*invS) : 0.f;
        } else {
            const int nr = c0 + 1024;
            wg4[r*1032 + 1024] = (nr < NNv)
                ? fmaf(omg, wp[nr], __bfloat162float(Eb[nr])*invS) : 0.f;
        }
    }
    __syncthreads();

    float ls[4];
    #pragma unroll
    for (int r = 0; r < Rv; r++) {
        const float* w = &wg4[r*1032];
        __nv_bfloat16* __restrict__ wo = g_wpow_r + ((size_t)r*Bz + b)*NNv;
        const float4 f   = *(const float4*)&w[4*t];
        const float left  = w[(t == 0) ? 1025 : 4*t - 1];
        const float right = w[4*t + 4];
        float4 o;
        o.x = fpow(fmaf(s0, left, fmaf(s1, f.x, s2*f.y)),  gm);
        o.y = fpow(fmaf(s0, f.x,  fmaf(s1, f.y, s2*f.z)),  gm);
        o.z = fpow(fmaf(s0, f.y,  fmaf(s1, f.z, s2*f.w)),  gm);
        o.w = fpow(fmaf(s0, f.z,  fmaf(s1, f.w, s2*right)), gm);
        __nv_bfloat162 o01 = __floats2bfloat162_rn(o.x, o.y);
        __nv_bfloat162 o23 = __floats2bfloat162_rn(o.z, o.w);
        *(__nv_bfloat162*)&wo[c0 + 4*t]     = o01;
        *(__nv_bfloat162*)&wo[c0 + 4*t + 2] = o23;
        ls[r] = (__bfloat162float(o01.x) + __bfloat162float(o01.y))
              + (__bfloat162float(o23.x) + __bfloat162float(o23.y));
    }

    // combined reduction: warp shuffles, then 8 warp-partials per r
    #pragma unroll
    for (int r = 0; r < Rv; r++)
        #pragma unroll
        for (int off = 16; off; off >>= 1)
            ls[r] += __shfl_xor_sync(0xffffffffu, ls[r], off);
    if (lane == 0) {
        #pragma unroll
        for (int r = 0; r < Rv; r++) red32[r*8 + warp] = ls[r];
    }
    __syncthreads();
    if (t < Rv) {
        float s = 0.f;
        #pragma unroll
        for (int w = 0; w < 8; w++) s += red32[t*8 + w];
        g_tpart[t*(Bz*CSPBLK) + b*CSPBLK + blockIdx.x] = s;
    }
}

// --- kernel 4 (FUSED): memupdate + sim(m1) in one pass ----------------------
// Phase A: m1 tile = m0*(1 - inv*W^T e) + inv*W^T a  (bf16 WMMA, deferred inv)
// Phase B: E[b, n-tile] = exp(beta * kn·m1[n] / ||m1[n]||)  (tf32 WMMA)
// The m1 tile flows from Phase A registers into the [m][n]-transposed smem
// tile Phase B needs — no HBM round-trip for sim's input.
// Dynamic smem (50176 B):
//   mt  fp32 [64k][68]                         [0, 17408)
//   region2 (32768 B)                          [17408, 50176)
//     A-staging: wsh/esh/ash bf16 ld=72        (27648 B)
//     A-accs:    ce_s/ca_s fp32 [n][m] ld=64   (32768 B)
//     B-accs:    cs fp32 [b][68]               (17408 B)
__global__ void memupdate_sim_kernel(const float* __restrict__ mem,
                                     const int* __restrict__ bank)
{
    extern __shared__ __align__(16) char smbuf[];
    float* mt = (float*)smbuf;                              // [m][n] ld=68
    char*  reg2 = smbuf + 17408;
    __nv_bfloat16* wsh = (__nv_bfloat16*)reg2;              // [b][n] ld=72
    __nv_bfloat16* esh = (__nv_bfloat16*)(reg2 + 9216);     // [b][m] ld=72
    __nv_bfloat16* ash = (__nv_bfloat16*)(reg2 + 18432);    // [b][m] ld=72
    float* ce_s = (float*)reg2;                             // [n][m] ld=64
    float* ca_s = (float*)(reg2 + 16384);
    float* cs   = (float*)reg2;                             // [b][n] ld=68
    __shared__ float invn[64];
    __shared__ float sbeta[64];
    __shared__ float red8[8];

    const float* __restrict__ m0 = mem + (size_t)bank[0]*NNv*Mv;
    const int t = threadIdx.x;
    const int warp = t >> 5, lane = t & 31;
    const int n0 = blockIdx.x * 64;

    // early-issue the redundant write-total partials (latency overlaps staging)
    float ts = 0.f;
    #pragma unroll
    for (int i = t; i < Bz*CSPBLK; i += 256) ts += g_tpart[i];

    // ---- Phase A staging: W (bf16 copy), e, a (fp32->bf16), unscaled ----
    for (int i = t; i < 64*32; i += 256) {
        const int bb = i >> 5, kp = i & 31;
        *(__nv_bfloat162*)&wsh[bb*72 + 2*kp] =
            *(const __nv_bfloat162*)&g_wpow_w[(size_t)bb*NNv + n0 + 2*kp];
    }
    for (int i = t; i < 64*64; i += 256) {
        const int bb = i >> 6, mm = i & 63;
        esh[bb*72 + mm] = __float2bfloat16(g_ev[i]);
        ash[bb*72 + mm] = __float2bfloat16(g_av[i]);
    }
    if (t < 64) sbeta[t] = g_beta[t];
    __syncthreads();

    // ---- Phase A MMA: ce = W^T e, ca = W^T a ----
    const int nrow  = warp >> 1;        // n-tile 0..3
    const int mcol0 = (warp & 1) * 2;   // m-tiles {0,1} or {2,3}
    {
        wmma::fragment<wmma::accumulator, 16, 16, 16, float> ce0, ce1, ca0, ca1;
        wmma::fill_fragment(ce0, 0.f); wmma::fill_fragment(ce1, 0.f);
        wmma::fill_fragment(ca0, 0.f); wmma::fill_fragment(ca1, 0.f);
        #pragma unroll
        for (int kt = 0; kt < 4; kt++) {
            wmma::fragment<wmma::matrix_a, 16, 16, 16, __nv_bfloat16,
                           wmma::col_major> fa;
            wmma::load_matrix_sync(fa, &wsh[(kt*16)*72 + nrow*16], 72);
            wmma::fragment<wmma::matrix_b, 16, 16, 16, __nv_bfloat16,
                           wmma::row_major> fe0, fe1, fd0, fd1;
            wmma::load_matrix_sync(fe0, &esh[(kt*16)*72 + (mcol0    )*16], 72);
            wmma::load_matrix_sync(fe1, &esh[(kt*16)*72 + (mcol0 + 1)*16], 72);
            wmma::load_matrix_sync(fd0, &ash[(kt*16)*72 + (mcol0    )*16], 72);
            wmma::load_matrix_sync(fd1, &ash[(kt*16)*72 + (mcol0 + 1)*16], 72);
            wmma::mma_sync(ce0, fa, fe0, ce0);
            wmma::mma_sync(ce1, fa, fe1, ce1);
            wmma::mma_sync(ca0, fa, fd0, ca0);
            wmma::mma_sync(ca1, fa, fd1, ca1);
        }

        // finish the deferred write-head total
        #pragma unroll
        for (int off = 16; off; off >>= 1)
            ts += __shfl_xor_sync(0xffffffffu, ts, off);
        if (lane == 0) red8[warp] = ts;
        __syncthreads();   // guards red8 AND all MMA smem reads before overwrite

        wmma::store_matrix_sync(&ce_s[(nrow*16)*64 + (mcol0    )*16], ce0, 64,
                                wmma::mem_row_major);
        wmma::store_matrix_sync(&ce_s[(nrow*16)*64 + (mcol0 + 1)*16], ce1, 64,
                                wmma::mem_row_major);
        wmma::store_matrix_sync(&ca_s[(nrow*16)*64 + (mcol0    )*16], ca0, 64,
                                wmma::mem_row_major);
        wmma::store_matrix_sync(&ca_s[(nrow*16)*64 + (mcol0 + 1)*16], ca1, 64,
                                wmma::mem_row_major);
    }
    __syncthreads();

    float tot = 0.f;
    #pragma unroll
    for (int w = 0; w < 8; w++) tot += red8[w];
    const float inv = 1.f / (tot + 1e-5f);

    // ---- Phase A epilogue: m1 -> gmem AND transposed mt tile in smem ----
    #pragma unroll
    for (int j = 0; j < 4; j++) {
        const int idx = j*1024 + 4*t;          // element index in 64x64 tile
        const int nl = idx >> 6, mm = idx & 63;
        const size_t n = (size_t)(n0 + nl);
        const float4 o  = *(const float4*)&m0  [n*Mv + mm];
        const float4 ce = *(const float4*)&ce_s[nl*64 + mm];
        const float4 ca = *(const float4*)&ca_s[nl*64 + mm];
        float4 v;
        v.x = fmaf(o.x, 1.f - inv*ce.x, inv*ca.x);
        v.y = fmaf(o.y, 1.f - inv*ce.y, inv*ca.y);
        v.z = fmaf(o.z, 1.f - inv*ce.z, inv*ca.z);
        v.w = fmaf(o.w, 1.f - inv*ce.w, inv*ca.w);
        *(float4*)&g_m1[n*Mv + mm] = v;
        mt[(mm    )*68 + nl] = v.x;
        mt[(mm + 1)*68 + nl] = v.y;
        mt[(mm + 2)*68 + nl] = v.z;
        mt[(mm + 3)*68 + nl] = v.w;
    }
    __syncthreads();   // mt complete; ce_s/ca_s now dead (cs may overwrite)

    // ---- Phase B: row norms of m1 tile ----
    if (t < 64) {
        float s = 0.f;
        #pragma unroll 16
        for (int k = 0; k < 64; k++) { float v = mt[k*68 + t]; s = fmaf(v, v, s); }
        invn[t] = 1.f / (sqrtf(s) + 1e-8f);
    }

    // ---- Phase B: C[64b][64n] = kn[64b][64k] @ mt[64k][64n] (tf32) ----
    {
        const int brow  = warp >> 1;
        const int ncol0 = (warp & 1) * 2;
        wmma::fragment<wmma::accumulator, 16, 16, 8, float> acc0, acc1;
        wmma::fill_fragment(acc0, 0.f);
        wmma::fill_fragment(acc1, 0.f);
        #pragma unroll
        for (int kt = 0; kt < 8; kt++) {
            wmma::fragment<wmma::matrix_a, 16, 16, 8, wmma::precision::tf32,
                           wmma::row_major> fa;
            wmma::load_matrix_sync(fa, &g_kn[(brow*16)*Mv + kt*8], Mv);
            #pragma unroll
            for (int i = 0; i < fa.num_elements; i++)
                fa.x[i] = wmma::__float_to_tf32(fa.x[i]);
            wmma::fragment<wmma::matrix_b, 16, 16, 8, wmma::precision::tf32,
                           wmma::row_major> fb0, fb1;
            wmma::load_matrix_sync(fb0, &mt[(kt*8)*68 + (ncol0    )*16], 68);
            wmma::load_matrix_sync(fb1, &mt[(kt*8)*68 + (ncol0 + 1)*16], 68);
            #pragma unroll
            for (int i = 0; i < fb0.num_elements; i++) {
                fb0.x[i] = wmma::__float_to_tf32(fb0.x[i]);
                fb1.x[i] = wmma::__float_to_tf32(fb1.x[i]);
            }
            wmma::mma_sync(acc0, fa, fb0, acc0);
            wmma::mma_sync(acc1, fa, fb1, acc1);
        }
        wmma::store_matrix_sync(&cs[(brow*16)*68 + (ncol0    )*16], acc0, 68,
                                wmma::mem_row_major);
        wmma::store_matrix_sync(&cs[(brow*16)*68 + (ncol0 + 1)*16], acc1, 68,
                                wmma::mem_row_major);
    }
    __syncthreads();

    // ---- Phase B epilogue: exp, bf16 E store, per-b partial sums ----
    const int by = t >> 5, nx = t & 31;
    const float2 iv = *(const float2*)&invn[2*nx];
    float psum[8];
    #pragma unroll
    for (int bi = 0; bi < 8; bi++) {
        const int bb = 8*by + bi;
        const float bt = sbeta[bb];
        const float2 cv = *(const float2*)&cs[bb*68 + 2*nx];
        float e0 = __expf(bt * cv.x * iv.x);
        float e1 = __expf(bt * cv.y * iv.y);
        __nv_bfloat162 hv = __floats2bfloat162_rn(e0, e1);
        *(__nv_bfloat162*)&g_E[(size_t)bb*NNv + n0 + 2*nx] = hv;
        psum[bi] = __bfloat162float(hv.x) + __bfloat162float(hv.y);
    }
    #pragma unroll
    for (int bi = 0; bi < 8; bi++)
        #pragma unroll
        for (int off = 16; off; off >>= 1)
            psum[bi] += __shfl_xor_sync(0xffffffffu, psum[bi], off);
    if (nx == 0) {
        #pragma unroll
        for (int bi = 0; bi < 8; bi++)
            g_psum[(size_t)(8*by + bi)*SIMBLK + blockIdx.x] = psum[bi];
    }
}

// ----- kernel 5: split-K read einsum partials (bf16 WMMA tensor cores) -----
__global__ void einsum_kernel()
{
    __shared__ __align__(16) __nv_bfloat16 ash[64*72];  // [b][k], ld=72
    __shared__ __align__(16) __nv_bfloat16 bsh[64*72];  // [k][m], ld=72
    const int chunk = blockIdx.x, r = blockIdx.y;
    const int n0 = chunk * EK;
    const int t = threadIdx.x;
    const int warp  = t >> 5;
    const int trow  = warp >> 1;          // b-tile: 0..3
    const int tcol0 = (warp & 1) * 2;     // m-tiles: {0,1} or {2,3}

    wmma::fragment<wmma::accumulator, 16, 16, 16, float> acc0, acc1;
    wmma::fill_fragment(acc0, 0.f);
    wmma::fill_fragment(acc1, 0.f);

    for (int sub = 0; sub < EK/64; sub++) {
        const int nb = n0 + sub*64;
        // 64 rows x 32 bf162 per row, straight copy
        for (int i = t; i < 64*32; i += 256) {
            const int bb = i >> 5, kp = i & 31;
            *(__nv_bfloat162*)&ash[bb*72 + 2*kp] =
                *(const __nv_bfloat162*)&g_wpow_r[((size_t)r*Bz + bb)*NNv + nb + 2*kp];
        }
        for (int i = t; i < 64*64; i += 256) {
            const int kk = i >> 6, mm = i & 63;
            bsh[kk*72 + mm] = __float2bfloat16(g_m1[(size_t)(nb + kk)*Mv + mm]);
        }
        __syncthreads();

        #pragma unroll
        for (int kt = 0; kt < 4; kt++) {
            wmma::fragment<wmma::matrix_a, 16, 16, 16, __nv_bfloat16,
                           wmma::row_major> fa;
            wmma::load_matrix_sync(fa, &ash[(trow*16)*72 + kt*16], 72);
            wmma::fragment<wmma::matrix_b, 16, 16, 16, __nv_bfloat16,
                           wmma::row_major> fb0, fb1;
            wmma::load_matrix_sync(fb0, &bsh[(kt*16)*72 + (tcol0    )*16], 72);
            wmma::load_matrix_sync(fb1, &bsh[(kt*16)*72 + (tcol0 + 1)*16], 72);
            wmma::mma_sync(acc0, fa, fb0, acc0);
            wmma::mma_sync(acc1, fa, fb1, acc1);
        }
        __syncthreads();
    }

    const size_t base = ((size_t)r*ECHUNK + chunk) * (Bz*Mv);
    wmma::store_matrix_sync(&g_epart[base + (size_t)(trow*16)*Mv + (tcol0    )*16],
                            acc0, Mv, wmma::mem_row_major);
    wmma::store_matrix_sync(&g_epart[base + (size_t)(trow*16)*Mv + (tcol0 + 1)*16],
                            acc1, Mv, wmma::mem_row_major);
}

// ----- kernel 6: reduce split-K + fused read-total + transpose --------------
__global__ void reduce_out_kernel(float* __restrict__ out)
{
    __shared__ float red[256];
    const int t = threadIdx.x;
    const int gid = blockIdx.x*256 + t;   // 0..R*B*M-1
    const int r = gid >> 12;              // constant within the block
    const int b = (gid >> 6) & 63;
    const int m = gid & 63;

    {
        float s = 0.f;
        #pragma unroll
        for (int i = t; i < Bz*CSPBLK; i += 256)
            s += g_tpart[r*(Bz*CSPBLK) + i];
        red[t] = s; __syncthreads();
        for (int off = 128; off; off >>= 1) {
            if (t < off) red[t] += red[t+off];
            __syncthreads();
        }
    }
    const float inv = 1.f / (red[0] + 1e-5f);

    float s = 0.f;
    for (int c = 0; c < ECHUNK; c++)
        s += g_epart[(((size_t)r*ECHUNK + c)*Bz + b)*Mv + m];
    out[(size_t)b*(Rv*Mv) + r*Mv + m] = s * inv;
}

// ---------------------------------------------------------------------------
extern "C" void kernel_launch(void* const* d_in, const int* in_sizes, int n_in,
                              void* d_out, int out_size)
{
    const float* h_t     = (const float*)d_in[0];
    const float* ww      = (const float*)d_in[1];
    const float* wr      = (const float*)d_in[2];
    const float* memory  = (const float*)d_in[3];
    const float* key_w   = (const float*)d_in[4];
    const float* key_b   = (const float*)d_in[5];
    const float* beta_w  = (const float*)d_in[6];
    const float* beta_b  = (const float*)d_in[7];
    const float* gate_w  = (const float*)d_in[8];
    const float* gate_b  = (const float*)d_in[9];
    const float* shift_w = (const float*)d_in[10];
    const float* shift_b = (const float*)d_in[11];
    const float* gamma_w = (const float*)d_in[12];
    const float* gamma_b = (const float*)d_in[13];
    const float* erase_w = (const float*)d_in[14];
    const float* erase_b = (const float*)d_in[15];
    const float* add_w   = (const float*)d_in[16];
    const float* add_b   = (const float*)d_in[17];
    const int*   bank    = (const int*)d_in[18];
    float* out = (float*)d_out;

    const int FUSED_SMEM = 50176;
    cudaFuncSetAttribute(memupdate_sim_kernel,
        cudaFuncAttributeMaxDynamicSharedMemorySize, FUSED_SMEM);

    // head params (shared by all 5 weight updates)
    heads_kernel<<<Bz, 256>>>(h_t, key_w, key_b, beta_w, beta_b, gate_w, gate_b,
                              shift_w, shift_b, gamma_w, gamma_b,
                              erase_w, erase_b, add_w, add_b);

    // --- write head: content addressing on m0, fused sumexp in csp ---
    sim_kernel<<<SIMBLK, 256>>>(memory, bank);
    csp_write_kernel<<<dim3(CSPBLK, Bz), 256>>>(ww);

    // --- memory erase/add FUSED with read-head content addressing on m1 ---
    memupdate_sim_kernel<<<NNv/64, 256, FUSED_SMEM>>>(memory, bank);

    // --- read heads: gate + shift + pow (all R heads/block) ---
    csp_read_kernel<<<dim3(CSPBLK, Bz), 256>>>(wr);

    // --- read: r[r,b,:] = (wpow_r[r,b,:]/total_r) @ m1 (fused read-totals) ---
    einsum_kernel<<<dim3(ECHUNK, Rv), 256>>>();
    reduce_out_kernel<<<(Rv*Bz*Mv)/256, 256>>>(out);
}

// round 17
// speedup vs baseline: 2.3561x; 1.1063x over previous
#include <cuda_runtime.h>
#include <cuda_bf16.h>
#include <mma.h>
#include <math.h>

using namespace nvcuda;

#define Bz 64
#define Hh 1024
#define NNv 65536
#define Mv 64
#define Rv 4
#define SIMBLK (NNv/64)   /* 1024 sim blocks */
#define CSPBLK 64         /* N/1024 csp blocks per b */
#define ECHUNK 128        /* einsum split-K chunks */
#define EK (NNv/ECHUNK)   /* 512 n per chunk */

// ---------------- scratch (device globals: no allocation allowed) ----------
__device__ __nv_bfloat16 g_E[(size_t)Bz*NNv];       // exp(beta*sim) [B,N] bf16
__device__ __nv_bfloat16 g_wpow_w[(size_t)Bz*NNv];  // write-head w_pow bf16
__device__ __nv_bfloat16 g_wpow_r[(size_t)Rv*Bz*NNv]; // read-head w_pow bf16
__device__ __nv_bfloat16 g_m1b[(size_t)NNv*Mv];     // updated memory (bf16; only
                                                    // einsum consumes it, which
                                                    // rounded to bf16 anyway)
__device__ float g_kn[Bz*Mv];
__device__ float g_ev[Bz*Mv];
__device__ float g_av[Bz*Mv];
__device__ float g_beta[Bz];
__device__ float g_gate[Bz];
__device__ float g_gamma[Bz];
__device__ float g_shift[Bz*3];
__device__ float g_psum[(size_t)Bz*SIMBLK];         // per-block exp partial sums
__device__ float g_tpart[Rv*Bz*CSPBLK];             // per-block pow partial sums
__device__ float g_epart[(size_t)Rv*ECHUNK*Bz*Mv];  // einsum split-K partials

__device__ __forceinline__ float clip01(float x){ return fminf(fmaxf(x, 0.f), 1.f); }
// fast x^g for x > 0 (w_tilde strictly positive: gated softmax mix, s_j > 0)
__device__ __forceinline__ float fpow(float x, float g){ return __expf(g * __logf(x)); }

// ---------------- kernel 1: head projections (once per step) ---------------
__global__ void heads_kernel(const float* __restrict__ h,
    const float* __restrict__ key_w,   const float* __restrict__ key_b,
    const float* __restrict__ beta_w,  const float* __restrict__ beta_b,
    const float* __restrict__ gate_w,  const float* __restrict__ gate_b,
    const float* __restrict__ shift_w, const float* __restrict__ shift_b,
    const float* __restrict__ gamma_w, const float* __restrict__ gamma_b,
    const float* __restrict__ erase_w, const float* __restrict__ erase_b,
    const float* __restrict__ add_w,   const float* __restrict__ add_b)
{
    __shared__ float hs[Hh];
    __shared__ float ksh[Mv];
    __shared__ float sdot[6];
    __shared__ float sinv;
    const int b = blockIdx.x, t = threadIdx.x;
    for (int i = t; i < Hh; i += 256) hs[i] = h[(size_t)b*Hh + i];
    __syncthreads();

    if (t < 64) {
        float a0=0,a1=0,a2=0,a3=0;
        for (int j = 0; j < Hh; j += 4) {
            a0 = fmaf(hs[j  ], key_w[(j  )*Mv + t], a0);
            a1 = fmaf(hs[j+1], key_w[(j+1)*Mv + t], a1);
            a2 = fmaf(hs[j+2], key_w[(j+2)*Mv + t], a2);
            a3 = fmaf(hs[j+3], key_w[(j+3)*Mv + t], a3);
        }
        ksh[t] = clip01(a0+a1+a2+a3 + key_b[t]);
    } else if (t < 128) {
        const int m = t - 64;
        float a0=0,a1=0,a2=0,a3=0;
        for (int j = 0; j < Hh; j += 4) {
            a0 = fmaf(hs[j  ], erase_w[(j  )*Mv + m], a0);
            a1 = fmaf(hs[j+1], erase_w[(j+1)*Mv + m], a1);
            a2 = fmaf(hs[j+2], erase_w[(j+2)*Mv + m], a2);
            a3 = fmaf(hs[j+3], erase_w[(j+3)*Mv + m], a3);
        }
        g_ev[b*Mv + m] = clip01(a0+a1+a2+a3 + erase_b[m]);
    } else if (t < 192) {
        const int m = t - 128;
        float a0=0,a1=0,a2=0,a3=0;
        for (int j = 0; j < Hh; j += 4) {
            a0 = fmaf(hs[j  ], add_w[(j  )*Mv + m], a0);
            a1 = fmaf(hs[j+1], add_w[(j+1)*Mv + m], a1);
            a2 = fmaf(hs[j+2], add_w[(j+2)*Mv + m], a2);
            a3 = fmaf(hs[j+3], add_w[(j+3)*Mv + m], a3);
        }
        // relu then clip01 == clip01
        g_av[b*Mv + m] = clip01(a0+a1+a2+a3 + add_b[m]);
    } else if (t < 198) {
        const int d = t - 192;
        const float* w; int str, col;
        if      (d == 0) { w = beta_w;  str = 1; col = 0; }
        else if (d == 1) { w = gate_w;  str = 1; col = 0; }
        else if (d == 2) { w = gamma_w; str = 1; col = 0; }
        else             { w = shift_w; str = 3; col = d - 3; }
        float a0=0,a1=0;
        for (int j = 0; j < Hh; j += 2) {
            a0 = fmaf(hs[j  ], w[(j  )*str + col], a0);
            a1 = fmaf(hs[j+1], w[(j+1)*str + col], a1);
        }
        sdot[d] = a0 + a1;
    }
    __syncthreads();

    if (t < 32) {
        float v = ksh[t]*ksh[t] + ksh[t+32]*ksh[t+32];
        #pragma unroll
        for (int off = 16; off; off >>= 1) v += __shfl_xor_sync(0xffffffffu, v, off);
        if (t == 0) sinv = 1.f / (sqrtf(v) + 1e-8f);
    }
    __syncthreads();
    if (t < 64) g_kn[b*Mv + t] = ksh[t] * sinv;
    if (t == 0) {
        g_beta[b]  = fmaxf(sdot[0] + beta_b[0], 0.f);
        g_gate[b]  = clip01(sdot[1] + gate_b[0]);
        g_gamma[b] = 1.f + fmaxf(sdot[2] + gamma_b[0], 0.f);
        float x0 = sdot[3] + shift_b[0];
        float x1 = sdot[4] + shift_b[1];
        float x2 = sdot[5] + shift_b[2];
        float mx = fmaxf(x0, fmaxf(x1, x2));
        float e0 = expf(x0-mx), e1 = expf(x1-mx), e2 = expf(x2-mx);
        float is = 1.f / (e0+e1+e2);
        g_shift[b*3+0] = e0*is; g_shift[b*3+1] = e1*is; g_shift[b*3+2] = e2*is;
    }
}

// ------- kernel 2: E[b,n] = exp(beta[b] * (kn[b]·m0[n]) / (||m0[n]||+eps)) -
// m0 tile staged NATURAL [n][m] (float4, conflict-free); B operand consumed
// as col_major. Row norms computed during staging via 16-lane shuffles.
__global__ void sim_kernel(const float* __restrict__ mem,
                           const int* __restrict__ bank)
{
    const float* __restrict__ src = mem + (size_t)bank[0]*NNv*Mv;
    __shared__ __align__(16) float mts[64*68];  // [n][m], ld=68
    __shared__ __align__(16) float cs[64*68];   // [b][n] raw sim
    __shared__ float invn[64];
    __shared__ float sbeta[64];
    const int t = threadIdx.x;
    const int n0 = blockIdx.x * 64;

    // staging + fused row-norm partials (16 threads per row, 4 floats each)
    #pragma unroll
    for (int j = 0; j < 4; j++) {
        const int i  = j*256 + t;          // float4 index in 64x16 grid
        const int rr = i >> 4, c4 = (i & 15) * 4;
        const float4 v = *(const float4*)&src[(size_t)(n0 + rr)*Mv + c4];
        *(float4*)&mts[rr*68 + c4] = v;
        float s = v.x*v.x + v.y*v.y + v.z*v.z + v.w*v.w;
        s += __shfl_xor_sync(0xffffffffu, s, 1);
        s += __shfl_xor_sync(0xffffffffu, s, 2);
        s += __shfl_xor_sync(0xffffffffu, s, 4);
        s += __shfl_xor_sync(0xffffffffu, s, 8);
        if ((t & 15) == 0) invn[rr] = 1.f / (sqrtf(s) + 1e-8f);
    }
    if (t < 64) sbeta[t] = g_beta[t];
    __syncthreads();

    // WMMA: C[64b][64n] = kn[64b][64k] @ m0t (col_major view of [n][m])
    const int warp  = t >> 5;
    const int brow  = warp >> 1;        // b-tile 0..3
    const int ncol0 = (warp & 1) * 2;   // n-tiles {0,1} or {2,3}
    wmma::fragment<wmma::accumulator, 16, 16, 8, float> acc0, acc1;
    wmma::fill_fragment(acc0, 0.f);
    wmma::fill_fragment(acc1, 0.f);
    #pragma unroll
    for (int kt = 0; kt < 8; kt++) {
        wmma::fragment<wmma::matrix_a, 16, 16, 8, wmma::precision::tf32,
                       wmma::row_major> fa;
        wmma::load_matrix_sync(fa, &g_kn[(brow*16)*Mv + kt*8], Mv);
        #pragma unroll
        for (int i = 0; i < fa.num_elements; i++)
            fa.x[i] = wmma::__float_to_tf32(fa.x[i]);
        wmma::fragment<wmma::matrix_b, 16, 16, 8, wmma::precision::tf32,
                       wmma::col_major> fb0, fb1;
        wmma::load_matrix_sync(fb0, &mts[((ncol0    )*16)*68 + kt*8], 68);
        wmma::load_matrix_sync(fb1, &mts[((ncol0 + 1)*16)*68 + kt*8], 68);
        #pragma unroll
        for (int i = 0; i < fb0.num_elements; i++) {
            fb0.x[i] = wmma::__float_to_tf32(fb0.x[i]);
            fb1.x[i] = wmma::__float_to_tf32(fb1.x[i]);
        }
        wmma::mma_sync(acc0, fa, fb0, acc0);
        wmma::mma_sync(acc1, fa, fb1, acc1);
    }
    wmma::store_matrix_sync(&cs[(brow*16)*68 + (ncol0    )*16], acc0, 68,
                            wmma::mem_row_major);
    wmma::store_matrix_sync(&cs[(brow*16)*68 + (ncol0 + 1)*16], acc1, 68,
                            wmma::mem_row_major);
    __syncthreads();

    // epilogue: scale by invn, exp, bf16 store, per-b partial sums
    const int by = t >> 5, nx = t & 31;   // 8 b's per thread, 2 n's per thread
    const float2 iv = *(const float2*)&invn[2*nx];
    float psum[8];
    #pragma unroll
    for (int bi = 0; bi < 8; bi++) {
        const int bb = 8*by + bi;
        const float bt = sbeta[bb];
        const float2 cv = *(const float2*)&cs[bb*68 + 2*nx];
        float e0 = __expf(bt * cv.x * iv.x);
        float e1 = __expf(bt * cv.y * iv.y);
        __nv_bfloat162 hv = __floats2bfloat162_rn(e0, e1);
        *(__nv_bfloat162*)&g_E[(size_t)bb*NNv + n0 + 2*nx] = hv;
        psum[bi] = __bfloat162float(hv.x) + __bfloat162float(hv.y);
    }
    #pragma unroll
    for (int bi = 0; bi < 8; bi++)
        #pragma unroll
        for (int off = 16; off; off >>= 1)
            psum[bi] += __shfl_xor_sync(0xffffffffu, psum[bi], off);
    if (nx == 0) {
        #pragma unroll
        for (int bi = 0; bi < 8; bi++)
            g_psum[(size_t)(8*by + bi)*SIMBLK + blockIdx.x] = psum[bi];
    }
}

// helper: load 4 consecutive bf16 values as floats
__device__ __forceinline__ float4 ld_e4(const __nv_bfloat16* p)
{
    const __nv_bfloat162 a = *(const __nv_bfloat162*)p;
    const __nv_bfloat162 b = *(const __nv_bfloat162*)(p + 2);
    float4 v;
    v.x = __bfloat162float(a.x); v.y = __bfloat162float(a.y);
    v.z = __bfloat162float(b.x); v.w = __bfloat162float(b.y);
    return v;
}

// ----- kernel 3a: WRITE head csp (fused sumexp, bf16 in/out) ----------------
__global__ void csp_write_kernel(const float* __restrict__ ww)
{
    const int b  = blockIdx.y;
    const int c0 = blockIdx.x * 1024;
    const float* __restrict__ wp = ww + (size_t)b*NNv;
    __nv_bfloat16* __restrict__ wo = g_wpow_w + (size_t)b*NNv;
    const __nv_bfloat16* __restrict__ Eb = g_E + (size_t)b*NNv;

    __shared__ __align__(16) float wg2[1032];
    __shared__ __align__(16) float red[256];
    const int t = threadIdx.x;

    // fused sumexp: deterministic block-local sum of g_psum[b][*]
    {
        float s = 0.f;
        #pragma unroll
        for (int i = t; i < SIMBLK; i += 256) s += g_psum[(size_t)b*SIMBLK + i];
        red[t] = s; __syncthreads();
        for (int off = 128; off; off >>= 1) {
            if (t < off) red[t] += red[t+off];
            __syncthreads();
        }
    }
    const float gg   = g_gate[b];
    const float invS = gg / red[0];        // gate folded into content scale
    const float omg  = 1.f - gg;
    const float s0 = g_shift[b*3+0], s1 = g_shift[b*3+1], s2 = g_shift[b*3+2];
    const float gm = g_gamma[b];

    {
        const int n = c0 + 4*t;
        const float4 e = ld_e4(&Eb[n]);
        const float4 w = *(const float4*)&wp[n];
        float4 v;
        v.x = fmaf(omg, w.x, e.x*invS);
        v.y = fmaf(omg, w.y, e.y*invS);
        v.z = fmaf(omg, w.z, e.z*invS);
        v.w = fmaf(omg, w.w, e.w*invS);
        *(float4*)&wg2[4*t] = v;
    }
    if (t == 0) {
        const int nl = c0 - 1;
        wg2[1025] = (nl >= 0)
            ? fmaf(omg, wp[nl], __bfloat162float(Eb[nl])*invS) : 0.f;
        const int nr = c0 + 1024;
        wg2[1024] = (nr < NNv)
            ? fmaf(omg, wp[nr], __bfloat162float(Eb[nr])*invS) : 0.f;
    }
    __syncthreads();

    const float4 f   = *(const float4*)&wg2[4*t];
    const float left  = wg2[(t == 0) ? 1025 : 4*t - 1];
    const float right = wg2[4*t + 4];   // t==255 lands on wg2[1024] = halo
    float4 o;
    o.x = fpow(fmaf(s0, left, fmaf(s1, f.x, s2*f.y)),  gm);
    o.y = fpow(fmaf(s0, f.x,  fmaf(s1, f.y, s2*f.z)),  gm);
    o.z = fpow(fmaf(s0, f.y,  fmaf(s1, f.z, s2*f.w)),  gm);
    o.w = fpow(fmaf(s0, f.z,  fmaf(s1, f.w, s2*right)), gm);
    __nv_bfloat162 o01 = __floats2bfloat162_rn(o.x, o.y);
    __nv_bfloat162 o23 = __floats2bfloat162_rn(o.z, o.w);
    *(__nv_bfloat162*)&wo[c0 + 4*t]     = o01;
    *(__nv_bfloat162*)&wo[c0 + 4*t + 2] = o23;

    red[t] = (__bfloat162float(o01.x) + __bfloat162float(o01.y))
           + (__bfloat162float(o23.x) + __bfloat162float(o23.y));
    __syncthreads();
    for (int off = 128; off; off >>= 1) { if (t < off) red[t] += red[t+off]; __syncthreads(); }
    if (t == 0) g_tpart[b*CSPBLK + blockIdx.x] = red[0];
}

// ----- kernel 3b: READ heads csp (fused sumexp, all R heads staged at once) -
__global__ void csp_read_kernel(const float* __restrict__ wr)
{
    const int b  = blockIdx.y;
    const int c0 = blockIdx.x * 1024;
    const __nv_bfloat16* __restrict__ Eb = g_E + (size_t)b*NNv;

    __shared__ __align__(16) float ec [1032];     // halo layout as before
    __shared__ __align__(16) float wg4[4*1032];   // all 4 heads staged
    __shared__ __align__(16) float sred[256];
    __shared__ __align__(16) float red32[32];
    const int t = threadIdx.x;
    const int warp = t >> 5, lane = t & 31;

    // fused sumexp
    {
        float s = 0.f;
        #pragma unroll
        for (int i = t; i < SIMBLK; i += 256) s += g_psum[(size_t)b*SIMBLK + i];
        sred[t] = s; __syncthreads();
        for (int off = 128; off; off >>= 1) {
            if (t < off) sred[t] += sred[t+off];
            __syncthreads();
        }
    }
    const float gg   = g_gate[b];
    const float omg  = 1.f - gg;
    const float invS = gg / sred[0];
    const float s0 = g_shift[b*3+0], s1 = g_shift[b*3+1], s2 = g_shift[b*3+2];
    const float gm = g_gamma[b];
    __syncthreads();   // all threads read sred[0] before any reuse

    // stage gated content + all 4 heads (independent streams -> MLP)
    {
        const int n = c0 + 4*t;
        const float4 e = ld_e4(&Eb[n]);
        float4 ev;
        ev.x = e.x*invS; ev.y = e.y*invS; ev.z = e.z*invS; ev.w = e.w*invS;
        *(float4*)&ec[4*t] = ev;
        #pragma unroll
        for (int r = 0; r < Rv; r++) {
            const float4 w = *(const float4*)&wr[((size_t)r*Bz + b)*NNv + n];
            float4 v;
            v.x = fmaf(omg, w.x, ev.x);
            v.y = fmaf(omg, w.y, ev.y);
            v.z = fmaf(omg, w.z, ev.z);
            v.w = fmaf(omg, w.w, ev.w);
            *(float4*)&wg4[r*1032 + 4*t] = v;
        }
    }
    if (t < 8) {   // halos: t>>1 = r, t&1 = side (0=right,1=left)
        const int r = t >> 1;
        const float* __restrict__ wp = wr + ((size_t)r*Bz + b)*NNv;
        if (t & 1) {
            const int nl = c0 - 1;
            wg4[r*1032 + 1025] = (nl >= 0)
                ? fmaf(omg, wp[nl], __bfloat162float(Eb[nl])*invS) : 0.f;
        } else {
            const int nr = c0 + 1024;
            wg4[r*1032 + 1024] = (nr < NNv)
                ? fmaf(omg, wp[nr], __bfloat162float(Eb[nr])*invS) : 0.f;
        }
    }
    __syncthreads();

    float ls[4];
    #pragma unroll
    for (int r = 0; r < Rv; r++) {
        const float* w = &wg4[r*1032];
        __nv_bfloat16* __restrict__ wo = g_wpow_r + ((size_t)r*Bz + b)*NNv;
        const float4 f   = *(const float4*)&w[4*t];
        const float left  = w[(t == 0) ? 1025 : 4*t - 1];
        const float right = w[4*t + 4];
        float4 o;
        o.x = fpow(fmaf(s0, left, fmaf(s1, f.x, s2*f.y)),  gm);
        o.y = fpow(fmaf(s0, f.x,  fmaf(s1, f.y, s2*f.z)),  gm);
        o.z = fpow(fmaf(s0, f.y,  fmaf(s1, f.z, s2*f.w)),  gm);
        o.w = fpow(fmaf(s0, f.z,  fmaf(s1, f.w, s2*right)), gm);
        __nv_bfloat162 o01 = __floats2bfloat162_rn(o.x, o.y);
        __nv_bfloat162 o23 = __floats2bfloat162_rn(o.z, o.w);
        *(__nv_bfloat162*)&wo[c0 + 4*t]     = o01;
        *(__nv_bfloat162*)&wo[c0 + 4*t + 2] = o23;
        ls[r] = (__bfloat162float(o01.x) + __bfloat162float(o01.y))
              + (__bfloat162float(o23.x) + __bfloat162float(o23.y));
    }

    // combined reduction: warp shuffles, then 8 warp-partials per r
    #pragma unroll
    for (int r = 0; r < Rv; r++)
        #pragma unroll
        for (int off = 16; off; off >>= 1)
            ls[r] += __shfl_xor_sync(0xffffffffu, ls[r], off);
    if (lane == 0) {
        #pragma unroll
        for (int r = 0; r < Rv; r++) red32[r*8 + warp] = ls[r];
    }
    __syncthreads();
    if (t < Rv) {
        float s = 0.f;
        #pragma unroll
        for (int w = 0; w < 8; w++) s += red32[t*8 + w];
        g_tpart[t*(Bz*CSPBLK) + b*CSPBLK + blockIdx.x] = s;
    }
}

// --- kernel 4 (FUSED): memupdate + sim(m1) in one pass ----------------------
// Phase A: m1 tile = m0*(1 - inv*W^T e) + inv*W^T a  (bf16 WMMA, deferred inv)
// Phase B: E[b, n-tile] = exp(beta * kn·m1[n] / ||m1[n]||)  (tf32 WMMA)
// m1 tile kept NATURAL [n][m] in smem (float4 stores, conflict-free); Phase B
// consumes it as a col_major B operand. Norms fused into the A-epilogue via
// 16-lane shuffles. m1 persisted to gmem in bf16 (einsum rounds anyway).
// Dynamic smem (50176 B): mts fp32 [n][68] | region2 32KB (staging/accs/cs).
__global__ void memupdate_sim_kernel(const float* __restrict__ mem,
                                     const int* __restrict__ bank)
{
    extern __shared__ __align__(16) char smbuf[];
    float* mts = (float*)smbuf;                             // [n][m] ld=68
    char*  reg2 = smbuf + 17408;
    __nv_bfloat16* wsh = (__nv_bfloat16*)reg2;              // [b][n] ld=72
    __nv_bfloat16* esh = (__nv_bfloat16*)(reg2 + 9216);     // [b][m] ld=72
    __nv_bfloat16* ash = (__nv_bfloat16*)(reg2 + 18432);    // [b][m] ld=72
    float* ce_s = (float*)reg2;                             // [n][m] ld=64
    float* ca_s = (float*)(reg2 + 16384);
    float* cs   = (float*)reg2;                             // [b][n] ld=68
    __shared__ float invn[64];
    __shared__ float sbeta[64];
    __shared__ float red8[8];

    const float* __restrict__ m0 = mem + (size_t)bank[0]*NNv*Mv;
    const int t = threadIdx.x;
    const int warp = t >> 5, lane = t & 31;
    const int n0 = blockIdx.x * 64;

    // early-issue the redundant write-total partials (latency overlaps staging)
    float ts = 0.f;
    #pragma unroll
    for (int i = t; i < Bz*CSPBLK; i += 256) ts += g_tpart[i];

    // ---- Phase A staging: W (bf16 copy), e, a (fp32->bf16), unscaled ----
    for (int i = t; i < 64*32; i += 256) {
        const int bb = i >> 5, kp = i & 31;
        *(__nv_bfloat162*)&wsh[bb*72 + 2*kp] =
            *(const __nv_bfloat162*)&g_wpow_w[(size_t)bb*NNv + n0 + 2*kp];
    }
    for (int i = t; i < 64*64; i += 256) {
        const int bb = i >> 6, mm = i & 63;
        esh[bb*72 + mm] = __float2bfloat16(g_ev[i]);
        ash[bb*72 + mm] = __float2bfloat16(g_av[i]);
    }
    if (t < 64) sbeta[t] = g_beta[t];
    __syncthreads();

    // ---- Phase A MMA: ce = W^T e, ca = W^T a ----
    const int nrow  = warp >> 1;        // n-tile 0..3
    const int mcol0 = (warp & 1) * 2;   // m-tiles {0,1} or {2,3}
    {
        wmma::fragment<wmma::accumulator, 16, 16, 16, float> ce0, ce1, ca0, ca1;
        wmma::fill_fragment(ce0, 0.f); wmma::fill_fragment(ce1, 0.f);
        wmma::fill_fragment(ca0, 0.f); wmma::fill_fragment(ca1, 0.f);
        #pragma unroll
        for (int kt = 0; kt < 4; kt++) {
            wmma::fragment<wmma::matrix_a, 16, 16, 16, __nv_bfloat16,
                           wmma::col_major> fa;
            wmma::load_matrix_sync(fa, &wsh[(kt*16)*72 + nrow*16], 72);
            wmma::fragment<wmma::matrix_b, 16, 16, 16, __nv_bfloat16,
                           wmma::row_major> fe0, fe1, fd0, fd1;
            wmma::load_matrix_sync(fe0, &esh[(kt*16)*72 + (mcol0    )*16], 72);
            wmma::load_matrix_sync(fe1, &esh[(kt*16)*72 + (mcol0 + 1)*16], 72);
            wmma::load_matrix_sync(fd0, &ash[(kt*16)*72 + (mcol0    )*16], 72);
            wmma::load_matrix_sync(fd1, &ash[(kt*16)*72 + (mcol0 + 1)*16], 72);
            wmma::mma_sync(ce0, fa, fe0, ce0);
            wmma::mma_sync(ce1, fa, fe1, ce1);
            wmma::mma_sync(ca0, fa, fd0, ca0);
            wmma::mma_sync(ca1, fa, fd1, ca1);
        }

        // finish the deferred write-head total
        #pragma unroll
        for (int off = 16; off; off >>= 1)
            ts += __shfl_xor_sync(0xffffffffu, ts, off);
        if (lane == 0) red8[warp] = ts;
        __syncthreads();   // guards red8 AND all MMA smem reads before overwrite

        wmma::store_matrix_sync(&ce_s[(nrow*16)*64 + (mcol0    )*16], ce0, 64,
                                wmma::mem_row_major);
        wmma::store_matrix_sync(&ce_s[(nrow*16)*64 + (mcol0 + 1)*16], ce1, 64,
                                wmma::mem_row_major);
        wmma::store_matrix_sync(&ca_s[(nrow*16)*64 + (mcol0    )*16], ca0, 64,
                                wmma::mem_row_major);
        wmma::store_matrix_sync(&ca_s[(nrow*16)*64 + (mcol0 + 1)*16], ca1, 64,
                                wmma::mem_row_major);
    }
    __syncthreads();

    float tot = 0.f;
    #pragma unroll
    for (int w = 0; w < 8; w++) tot += red8[w];
    const float inv = 1.f / (tot + 1e-5f);

    // ---- Phase A epilogue: m1 -> gmem(bf16) + natural [n][m] smem tile,
    //      with fused row norms via 16-lane shuffles ----
    #pragma unroll
    for (int j = 0; j < 4; j++) {
        const int idx = j*1024 + 4*t;          // element index in 64x64 tile
        const int nl = idx >> 6, mm = idx & 63;
        const size_t n = (size_t)(n0 + nl);
        const float4 o  = *(const float4*)&m0  [n*Mv + mm];
        const float4 ce = *(const float4*)&ce_s[nl*64 + mm];
        const float4 ca = *(const float4*)&ca_s[nl*64 + mm];
        float4 v;
        v.x = fmaf(o.x, 1.f - inv*ce.x, inv*ca.x);
        v.y = fmaf(o.y, 1.f - inv*ce.y, inv*ca.y);
        v.z = fmaf(o.z, 1.f - inv*ce.z, inv*ca.z);
        v.w = fmaf(o.w, 1.f - inv*ce.w, inv*ca.w);
        __nv_bfloat162 b01 = __floats2bfloat162_rn(v.x, v.y);
        __nv_bfloat162 b23 = __floats2bfloat162_rn(v.z, v.w);
        *(__nv_bfloat162*)&g_m1b[n*Mv + mm]     = b01;
        *(__nv_bfloat162*)&g_m1b[n*Mv + mm + 2] = b23;
        // norm partial BEFORE the smem tile write lands (register values)
        float s = v.x*v.x + v.y*v.y + v.z*v.z + v.w*v.w;
        s += __shfl_xor_sync(0xffffffffu, s, 1);
        s += __shfl_xor_sync(0xffffffffu, s, 2);
        s += __shfl_xor_sync(0xffffffffu, s, 4);
        s += __shfl_xor_sync(0xffffffffu, s, 8);
        if ((t & 15) == 0) invn[nl] = 1.f / (sqrtf(s) + 1e-8f);
        // defer the mts store until after cs-overwrite hazard? No: mts region
        // is distinct from reg2 (ce_s/ca_s/cs) -> safe to write now.
        *(float4*)&mts[nl*68 + mm] = v;
    }
    __syncthreads();   // mts+invn complete; ce_s/ca_s dead (cs may overwrite)

    // ---- Phase B: C[64b][64n] = kn[64b][64k] @ m1t (col_major [n][m]) ----
    {
        const int brow  = warp >> 1;
        const int ncol0 = (warp & 1) * 2;
        wmma::fragment<wmma::accumulator, 16, 16, 8, float> acc0, acc1;
        wmma::fill_fragment(acc0, 0.f);
        wmma::fill_fragment(acc1, 0.f);
        #pragma unroll
        for (int kt = 0; kt < 8; kt++) {
            wmma::fragment<wmma::matrix_a, 16, 16, 8, wmma::precision::tf32,
                           wmma::row_major> fa;
            wmma::load_matrix_sync(fa, &g_kn[(brow*16)*Mv + kt*8], Mv);
            #pragma unroll
            for (int i = 0; i < fa.num_elements; i++)
                fa.x[i] = wmma::__float_to_tf32(fa.x[i]);
            wmma::fragment<wmma::matrix_b, 16, 16, 8, wmma::precision::tf32,
                           wmma::col_major> fb0, fb1;
            wmma::load_matrix_sync(fb0, &mts[((ncol0    )*16)*68 + kt*8], 68);
            wmma::load_matrix_sync(fb1, &mts[((ncol0 + 1)*16)*68 + kt*8], 68);
            #pragma unroll
            for (int i = 0; i < fb0.num_elements; i++) {
                fb0.x[i] = wmma::__float_to_tf32(fb0.x[i]);
                fb1.x[i] = wmma::__float_to_tf32(fb1.x[i]);
            }
            wmma::mma_sync(acc0, fa, fb0, acc0);
            wmma::mma_sync(acc1, fa, fb1, acc1);
        }
        wmma::store_matrix_sync(&cs[(brow*16)*68 + (ncol0    )*16], acc0, 68,
                                wmma::mem_row_major);
        wmma::store_matrix_sync(&cs[(brow*16)*68 + (ncol0 + 1)*16], acc1, 68,
                                wmma::mem_row_major);
    }
    __syncthreads();

    // ---- Phase B epilogue: exp, bf16 E store, per-b partial sums ----
    const int by = t >> 5, nx = t & 31;
    const float2 iv = *(const float2*)&invn[2*nx];
    float psum[8];
    #pragma unroll
    for (int bi = 0; bi < 8; bi++) {
        const int bb = 8*by + bi;
        const float bt = sbeta[bb];
        const float2 cv = *(const float2*)&cs[bb*68 + 2*nx];
        float e0 = __expf(bt * cv.x * iv.x);
        float e1 = __expf(bt * cv.y * iv.y);
        __nv_bfloat162 hv = __floats2bfloat162_rn(e0, e1);
        *(__nv_bfloat162*)&g_E[(size_t)bb*NNv + n0 + 2*nx] = hv;
        psum[bi] = __bfloat162float(hv.x) + __bfloat162float(hv.y);
    }
    #pragma unroll
    for (int bi = 0; bi < 8; bi++)
        #pragma unroll
        for (int off = 16; off; off >>= 1)
            psum[bi] += __shfl_xor_sync(0xffffffffu, psum[bi], off);
    if (nx == 0) {
        #pragma unroll
        for (int bi = 0; bi < 8; bi++)
            g_psum[(size_t)(8*by + bi)*SIMBLK + blockIdx.x] = psum[bi];
    }
}

// ----- kernel 5: split-K read einsum partials (bf16 WMMA tensor cores) -----
// Both operands already bf16 in global: staging is straight vector copies.
__global__ void einsum_kernel()
{
    __shared__ __align__(16) __nv_bfloat16 ash[64*72];  // [b][k], ld=72
    __shared__ __align__(16) __nv_bfloat16 bsh[64*72];  // [k][m], ld=72
    const int chunk = blockIdx.x, r = blockIdx.y;
    const int n0 = chunk * EK;
    const int t = threadIdx.x;
    const int warp  = t >> 5;
    const int trow  = warp >> 1;          // b-tile: 0..3
    const int tcol0 = (warp & 1) * 2;     // m-tiles: {0,1} or {2,3}

    wmma::fragment<wmma::accumulator, 16, 16, 16, float> acc0, acc1;
    wmma::fill_fragment(acc0, 0.f);
    wmma::fill_fragment(acc1, 0.f);

    for (int sub = 0; sub < EK/64; sub++) {
        const int nb = n0 + sub*64;
        for (int i = t; i < 64*32; i += 256) {
            const int bb = i >> 5, kp = i & 31;
            *(__nv_bfloat162*)&ash[bb*72 + 2*kp] =
                *(const __nv_bfloat162*)&g_wpow_r[((size_t)r*Bz + bb)*NNv + nb + 2*kp];
        }
        for (int i = t; i < 64*32; i += 256) {
            const int kk = i >> 5, mp = i & 31;
            *(__nv_bfloat162*)&bsh[kk*72 + 2*mp] =
                *(const __nv_bfloat162*)&g_m1b[(size_t)(nb + kk)*Mv + 2*mp];
        }
        __syncthreads();

        #pragma unroll
        for (int kt = 0; kt < 4; kt++) {
            wmma::fragment<wmma::matrix_a, 16, 16, 16, __nv_bfloat16,
                           wmma::row_major> fa;
            wmma::load_matrix_sync(fa, &ash[(trow*16)*72 + kt*16], 72);
            wmma::fragment<wmma::matrix_b, 16, 16, 16, __nv_bfloat16,
                           wmma::row_major> fb0, fb1;
            wmma::load_matrix_sync(fb0, &bsh[(kt*16)*72 + (tcol0    )*16], 72);
            wmma::load_matrix_sync(fb1, &bsh[(kt*16)*72 + (tcol0 + 1)*16], 72);
            wmma::mma_sync(acc0, fa, fb0, acc0);
            wmma::mma_sync(acc1, fa, fb1, acc1);
        }
        __syncthreads();
    }

    const size_t base = ((size_t)r*ECHUNK + chunk) * (Bz*Mv);
    wmma::store_matrix_sync(&g_epart[base + (size_t)(trow*16)*Mv + (tcol0    )*16],
                            acc0, Mv, wmma::mem_row_major);
    wmma::store_matrix_sync(&g_epart[base + (size_t)(trow*16)*Mv + (tcol0 + 1)*16],
                            acc1, Mv, wmma::mem_row_major);
}

// ----- kernel 6: reduce split-K + fused read-total + transpose --------------
__global__ void reduce_out_kernel(float* __restrict__ out)
{
    __shared__ float red[256];
    const int t = threadIdx.x;
    const int gid = blockIdx.x*256 + t;   // 0..R*B*M-1
    const int r = gid >> 12;              // constant within the block
    const int b = (gid >> 6) & 63;
    const int m = gid & 63;

    {
        float s = 0.f;
        #pragma unroll
        for (int i = t; i < Bz*CSPBLK; i += 256)
            s += g_tpart[r*(Bz*CSPBLK) + i];
        red[t] = s; __syncthreads();
        for (int off = 128; off; off >>= 1) {
            if (t < off) red[t] += red[t+off];
            __syncthreads();
        }
    }
    const float inv = 1.f / (red[0] + 1e-5f);

    float s = 0.f;
    for (int c = 0; c < ECHUNK; c++)
        s += g_epart[(((size_t)r*ECHUNK + c)*Bz + b)*Mv + m];
    out[(size_t)b*(Rv*Mv) + r*Mv + m] = s * inv;
}

// ---------------------------------------------------------------------------
extern "C" void kernel_launch(void* const* d_in, const int* in_sizes, int n_in,
                              void* d_out, int out_size)
{
    const float* h_t     = (const float*)d_in[0];
    const float* ww      = (const float*)d_in[1];
    const float* wr      = (const float*)d_in[2];
    const float* memory  = (const float*)d_in[3];
    const float* key_w   = (const float*)d_in[4];
    const float* key_b   = (const float*)d_in[5];
    const float* beta_w  = (const float*)d_in[6];
    const float* beta_b  = (const float*)d_in[7];
    const float* gate_w  = (const float*)d_in[8];
    const float* gate_b  = (const float*)d_in[9];
    const float* shift_w = (const float*)d_in[10];
    const float* shift_b = (const float*)d_in[11];
    const float* gamma_w = (const float*)d_in[12];
    const float* gamma_b = (const float*)d_in[13];
    const float* erase_w = (const float*)d_in[14];
    const float* erase_b = (const float*)d_in[15];
    const float* add_w   = (const float*)d_in[16];
    const float* add_b   = (const float*)d_in[17];
    const int*   bank    = (const int*)d_in[18];
    float* out = (float*)d_out;

    const int FUSED_SMEM = 50176;
    cudaFuncSetAttribute(memupdate_sim_kernel,
        cudaFuncAttributeMaxDynamicSharedMemorySize, FUSED_SMEM);

    // head params (shared by all 5 weight updates)
    heads_kernel<<<Bz, 256>>>(h_t, key_w, key_b, beta_w, beta_b, gate_w, gate_b,
                              shift_w, shift_b, gamma_w, gamma_b,
                              erase_w, erase_b, add_w, add_b);

    // --- write head: content addressing on m0, fused sumexp in csp ---
    sim_kernel<<<SIMBLK, 256>>>(memory, bank);
    csp_write_kernel<<<dim3(CSPBLK, Bz), 256>>>(ww);

    // --- memory erase/add FUSED with read-head content addressing on m1 ---
    memupdate_sim_kernel<<<NNv/64, 256, FUSED_SMEM>>>(memory, bank);

    // --- read heads: gate + shift + pow (all R heads/block) ---
    csp_read_kernel<<<dim3(CSPBLK, Bz), 256>>>(wr);

    // --- read: r[r,b,:] = (wpow_r[r,b,:]/total_r) @ m1 (fused read-totals) ---
    einsum_kernel<<<dim3(ECHUNK, Rv), 256>>>();
    reduce_out_kernel<<<(Rv*Bz*Mv)/256, 256>>>(out);
}